// round 7
// baseline (speedup 1.0000x reference)
#include <cuda_runtime.h>
#include <cuda_bf16.h>
#include <math.h>
#include <stdint.h>

typedef __nv_bfloat16 bf16;

// ---------------- problem constants ----------------
#define BB 16
#define TT 512
#define DIN 1024
#define HH 256
#define NN 64
#define TOPK 8
#define NCLS 2
#define KBRIDGE (DIN * 9)      // 9216
#define KCONV (HH * 3)         // 768
#define MROWS (BB * TT)        // 8192
#define NROWS (BB * NN)        // 1024

// ---------------- PTX helpers ----------------
__device__ __forceinline__ uint32_t smem_u32(const void* p) {
    uint32_t a;
    asm("{ .reg .u64 t; cvta.to.shared.u64 t, %1; cvt.u32.u64 %0, t; }" : "=r"(a) : "l"(p));
    return a;
}
#define CP_ASYNC16(dst, src) \
    asm volatile("cp.async.cg.shared.global [%0], [%1], 16;" :: "r"(dst), "l"(src) : "memory")
#define CP_COMMIT() asm volatile("cp.async.commit_group;" ::: "memory")
#define CP_WAIT(N)  asm volatile("cp.async.wait_group %0;" :: "n"(N) : "memory")
#define LDSM_X4(r0, r1, r2, r3, a) \
    asm volatile("ldmatrix.sync.aligned.m8n8.x4.shared.b16 {%0,%1,%2,%3}, [%4];" \
        : "=r"(r0), "=r"(r1), "=r"(r2), "=r"(r3) : "r"(a))
#define MMA_BF16(c, a0, a1, a2, a3, b0, b1) \
    asm volatile("mma.sync.aligned.m16n8k16.row.col.f32.bf16.bf16.f32 " \
        "{%0,%1,%2,%3}, {%4,%5,%6,%7}, {%8,%9}, {%0,%1,%2,%3};" \
        : "+f"((c)[0]), "+f"((c)[1]), "+f"((c)[2]), "+f"((c)[3]) \
        : "r"(a0), "r"(a1), "r"(a2), "r"(a3), "r"(b0), "r"(b1))
#define STS128Z(addr) \
    asm volatile("st.shared.v4.b32 [%0], {%1,%1,%1,%1};" :: "r"(addr), "r"(0u) : "memory")

// ---------------- scratch ----------------
__device__ bf16 g_fh[(size_t)MROWS * KBRIDGE];
__device__ bf16 g_fl[(size_t)MROWS * KBRIDGE];
__device__ bf16 g_wh[HH * KBRIDGE];
__device__ bf16 g_wl[HH * KBRIDGE];
__device__ bf16 g_h1h[MROWS * HH];
__device__ bf16 g_h1l[MROWS * HH];
__device__ bf16 g_wc1h[HH * KCONV];
__device__ bf16 g_wc1l[HH * KCONV];
__device__ bf16 g_wc2h[HH * KCONV];
__device__ bf16 g_wc2l[HH * KCONV];
__device__ bf16 g_y1h[MROWS * HH];
__device__ bf16 g_y1l[MROWS * HH];
__device__ float g_y2[MROWS * HH];
__device__ float g_hn[NROWS * HH];
__device__ bf16 g_hnh[NROWS * HH];
__device__ bf16 g_hnl[NROWS * HH];
__device__ bf16 g_wt0h[HH * HH];
__device__ bf16 g_wt0l[HH * HH];
__device__ bf16 g_wt1h[HH * HH];
__device__ bf16 g_wt1l[HH * HH];
__device__ float g_hw[NROWS * HH];
__device__ float g_s[NROWS];
__device__ float g_d[NROWS];
__device__ unsigned long long g_adj[BB * NN];
__device__ float g_ln[NROWS * HH];

// ---------------- math helpers ----------------
__device__ __forceinline__ float silu_f(float x) { return x * (1.f / (1.f + expf(-x))); }
__device__ __forceinline__ float selu_f(float x) {
    const float a = 1.6732632423543772f, s = 1.0507009873554805f;
    return x > 0.f ? s * x : s * a * expm1f(x);
}
__device__ __forceinline__ void split_bf16(float v, bf16& h, bf16& l) {
    h = __float2bfloat16_rn(v);
    l = __float2bfloat16_rn(v - __bfloat162float(h));
}
union Pack2 { bf16 b[2]; uint32_t u; };
union Pack8 { bf16 b[8]; uint4 u; };
__device__ __forceinline__ uint32_t pack2(bf16 a, bf16 b) {
    Pack2 p; p.b[0] = a; p.b[1] = b; return p.u;
}
__device__ __forceinline__ void split_store8(const float* v, bf16* ph, bf16* pl) {
    Pack8 H, L;
#pragma unroll
    for (int j = 0; j < 8; j++) split_bf16(v[j], H.b[j], L.b[j]);
    *reinterpret_cast<uint4*>(ph) = H.u;
    *reinterpret_cast<uint4*>(pl) = L.u;
}
__device__ __forceinline__ void bsplines8(float x, float* out) {
    const float h = 0.4f;
    float b[11];
#pragma unroll
    for (int j = 0; j < 11; j++) {
        float gj = (float)(j - 3) * h - 1.0f;
        float gj1 = (float)(j - 2) * h - 1.0f;
        b[j] = (x >= gj && x < gj1) ? 1.f : 0.f;
    }
#pragma unroll
    for (int k = 1; k <= 3; k++) {
        float inv = 1.f / ((float)k * h);
#pragma unroll
        for (int j = 0; j < 11; j++) {
            if (j < 11 - k) {
                float gj = (float)(j - 3) * h - 1.0f;
                float gjk1 = (float)(j + k - 2) * h - 1.0f;
                b[j] = (x - gj) * inv * b[j] + (gjk1 - x) * inv * b[j + 1];
            }
        }
    }
#pragma unroll
    for (int j = 0; j < 8; j++) out[j] = b[j];
}

// ---------------- prep kernels ----------------
// 8 inputs per thread, 16B packed stores per feature group.
__global__ void bridge_features_bf16(const float* __restrict__ x) {
    int idx = blockIdx.x * blockDim.x + threadIdx.x;
    if (idx >= MROWS * (DIN / 8)) return;
    int r = idx >> 7, i8 = idx & 127;
    const float* xp = x + (size_t)r * DIN + i8 * 8;
    float4 xa = *reinterpret_cast<const float4*>(xp);
    float4 xb = *reinterpret_cast<const float4*>(xp + 4);
    float vv[8] = {xa.x, xa.y, xa.z, xa.w, xb.x, xb.y, xb.z, xb.w};
    float f[9][8];
#pragma unroll
    for (int j = 0; j < 8; j++) {
        f[0][j] = silu_f(vv[j]);
        float bs[8];
        bsplines8(vv[j], bs);
#pragma unroll
        for (int c = 0; c < 8; c++) f[c + 1][j] = bs[c];
    }
    size_t base = (size_t)r * KBRIDGE + i8 * 8;
#pragma unroll
    for (int g = 0; g < 9; g++)
        split_store8(f[g], g_fh + base + (size_t)g * DIN, g_fl + base + (size_t)g * DIN);
}

__global__ void build_wcat_bf16(const float* __restrict__ bw, const float* __restrict__ sw,
                                const float* __restrict__ sc) {
    int idx = blockIdx.x * blockDim.x + threadIdx.x;
    if (idx >= HH * DIN) return;
    int i = idx % DIN, o = idx / DIN;
    size_t base = (size_t)o * KBRIDGE + i;
    bf16 h, l;
    split_bf16(bw[idx], h, l);
    g_wh[base] = h; g_wl[base] = l;
    float scale = sc[idx];
#pragma unroll
    for (int c = 0; c < 8; c++) {
        split_bf16(sw[(size_t)idx * 8 + c] * scale, h, l);
        size_t p = base + (size_t)(c + 1) * DIN;
        g_wh[p] = h; g_wl[p] = l;
    }
}

__global__ void conv_w_bf16(const float* __restrict__ w, bf16* __restrict__ wh, bf16* __restrict__ wl) {
    int idx = blockIdx.x * blockDim.x + threadIdx.x;
    if (idx >= HH * HH) return;
    int i = idx % HH, o = idx / HH;
#pragma unroll
    for (int j = 0; j < 3; j++) {
        bf16 h, l;
        split_bf16(w[((size_t)o * HH + i) * 3 + j], h, l);
        size_t p = (size_t)o * KCONV + j * HH + i;
        wh[p] = h; wl[p] = l;
    }
}

__global__ void gatwt_bf16(const float* __restrict__ w, bf16* __restrict__ wh, bf16* __restrict__ wl) {
    int idx = blockIdx.x * blockDim.x + threadIdx.x;
    if (idx >= HH * HH) return;
    int k = idx % HH, n = idx / HH;
    bf16 h, l;
    split_bf16(w[(size_t)k * HH + n], h, l);
    wh[idx] = h; wl[idx] = l;
}

// ================= split-bf16 GEMM, 256 threads (8 warps, 32x64 warp tile) =========
// C[m,n] = sum_k A[m,k]*B[n,k], hi/lo 3-product. Tile 64(M) x 256(N), BK=64.
// SHIFT=1: implicit im2col (A[row,k] = Y[row + k/256 - 1, k%256], zfill at edges).
// EPI: 0 raw fp32 | 1 selu+bias fp32 | 2 raw split bf16 | 3 selu+bias split bf16.
#define BK 64
#define SROW 144
#define A_STG (64 * SROW)        // 9216
#define B_STG (256 * SROW)       // 36864
#define GEMM_SMEM (4 * A_STG + 4 * B_STG)   // 184320

template <int EPI, int SHIFT>
__global__ __launch_bounds__(256, 1) void gemm_mma(
    const bf16* __restrict__ Ah, const bf16* __restrict__ Al,
    const bf16* __restrict__ Bh, const bf16* __restrict__ Bl,
    float* __restrict__ Cf, bf16* __restrict__ Ch, bf16* __restrict__ Cl,
    int K, const float* __restrict__ bias) {
    extern __shared__ char smem[];
    uint32_t s0 = smem_u32(smem);
    uint32_t sAh = s0, sAl = s0 + 2 * A_STG;
    uint32_t sBh = s0 + 4 * A_STG, sBl = sBh + 2 * B_STG;

    int tid = threadIdx.x, lane = tid & 31, wid = tid >> 5;
    int wm = wid & 1, wn = wid >> 1;       // 2 x 4 warp grid (32 rows x 64 cols each)
    int bm = blockIdx.x * 64;
    const int nc = K / BK;

    int aRow = wm * 32 + (lane & 15);
    int aCol = (lane >> 4) * 8;
    int bRow = wn * 64 + (lane & 7) + ((lane >> 4) << 3);
    int bCol = ((lane >> 3) & 1) * 8;

    float acc[2][8][4];
#pragma unroll
    for (int i = 0; i < 2; i++)
#pragma unroll
        for (int j = 0; j < 8; j++)
#pragma unroll
            for (int q = 0; q < 4; q++) acc[i][j][q] = 0.f;

    auto issue = [&](int stage, int k0) {
#pragma unroll
        for (int i = 0; i < 2; i++) {   // A: 512 chunks per array
            int q = i * 256 + tid;
            int r = q >> 3, c = q & 7;
            uint32_t dh = sAh + (uint32_t)(stage * A_STG + r * SROW + c * 16);
            uint32_t dl = sAl + (uint32_t)(stage * A_STG + r * SROW + c * 16);
            if (SHIFT) {
                int k = k0 + c * 8;
                int j = k >> 8, cc = k & 255;
                int grow = bm + r;
                int tj = (grow & 511) + j - 1;
                if (tj >= 0 && tj < 512) {
                    size_t go = (size_t)(grow + j - 1) * 256 + cc;
                    CP_ASYNC16(dh, Ah + go);
                    CP_ASYNC16(dl, Al + go);
                } else {
                    STS128Z(dh);
                    STS128Z(dl);
                }
            } else {
                size_t go = (size_t)(bm + r) * K + k0 + c * 8;
                CP_ASYNC16(dh, Ah + go);
                CP_ASYNC16(dl, Al + go);
            }
        }
#pragma unroll
        for (int i = 0; i < 8; i++) {   // B: 2048 chunks per array
            int q = i * 256 + tid;
            int r = q >> 3, c = q & 7;
            uint32_t d = (uint32_t)(stage * B_STG + r * SROW + c * 16);
            size_t go = (size_t)r * K + k0 + c * 8;
            CP_ASYNC16(sBh + d, Bh + go);
            CP_ASYNC16(sBl + d, Bl + go);
        }
    };

    issue(0, 0);
    CP_COMMIT();

    for (int kc = 0; kc < nc; kc++) {
        if (kc + 1 < nc) {
            issue((kc + 1) & 1, (kc + 1) * BK);
            CP_COMMIT();
            CP_WAIT(1);
        } else {
            CP_WAIT(0);
        }
        __syncthreads();
        uint32_t stA = (uint32_t)((kc & 1) * A_STG);
        uint32_t stB = (uint32_t)((kc & 1) * B_STG);
#pragma unroll
        for (int kk = 0; kk < 4; kk++) {
            uint32_t ah[2][4], al[2][4];
#pragma unroll
            for (int mt = 0; mt < 2; mt++) {
                uint32_t ao = stA + (uint32_t)((aRow + mt * 16) * SROW + (aCol + kk * 16) * 2);
                LDSM_X4(ah[mt][0], ah[mt][1], ah[mt][2], ah[mt][3], sAh + ao);
                LDSM_X4(al[mt][0], al[mt][1], al[mt][2], al[mt][3], sAl + ao);
            }
#pragma unroll
            for (int nt2 = 0; nt2 < 4; nt2++) {
                uint32_t bo = stB + (uint32_t)((bRow + nt2 * 16) * SROW + (bCol + kk * 16) * 2);
                uint32_t bh[4], bl[4];
                LDSM_X4(bh[0], bh[1], bh[2], bh[3], sBh + bo);
                LDSM_X4(bl[0], bl[1], bl[2], bl[3], sBl + bo);
#pragma unroll
                for (int mt = 0; mt < 2; mt++) {
                    int n0 = nt2 * 2, n1 = n0 + 1;
                    MMA_BF16(acc[mt][n0], ah[mt][0], ah[mt][1], ah[mt][2], ah[mt][3], bh[0], bh[1]);
                    MMA_BF16(acc[mt][n0], ah[mt][0], ah[mt][1], ah[mt][2], ah[mt][3], bl[0], bl[1]);
                    MMA_BF16(acc[mt][n0], al[mt][0], al[mt][1], al[mt][2], al[mt][3], bh[0], bh[1]);
                    MMA_BF16(acc[mt][n1], ah[mt][0], ah[mt][1], ah[mt][2], ah[mt][3], bh[2], bh[3]);
                    MMA_BF16(acc[mt][n1], ah[mt][0], ah[mt][1], ah[mt][2], ah[mt][3], bl[2], bl[3]);
                    MMA_BF16(acc[mt][n1], al[mt][0], al[mt][1], al[mt][2], al[mt][3], bh[2], bh[3]);
                }
            }
        }
        __syncthreads();
    }

    // epilogue
    int rbase = bm + wm * 32 + (lane >> 2);
    int cbase = wn * 64 + (lane & 3) * 2;
#pragma unroll
    for (int mt = 0; mt < 2; mt++) {
#pragma unroll
        for (int nt = 0; nt < 8; nt++) {
            int r = rbase + mt * 16;
            int c = cbase + nt * 8;
            float v0 = acc[mt][nt][0], v1 = acc[mt][nt][1];
            float w0 = acc[mt][nt][2], w1 = acc[mt][nt][3];
            if (EPI == 1 || EPI == 3) {
                float b0 = bias[c], b1 = bias[c + 1];
                v0 = selu_f(v0 + b0); v1 = selu_f(v1 + b1);
                w0 = selu_f(w0 + b0); w1 = selu_f(w1 + b1);
            }
            if (EPI >= 2) {
                bf16 h0, l0, h1, l1;
                split_bf16(v0, h0, l0); split_bf16(v1, h1, l1);
                *reinterpret_cast<uint32_t*>(Ch + (size_t)r * 256 + c) = pack2(h0, h1);
                *reinterpret_cast<uint32_t*>(Cl + (size_t)r * 256 + c) = pack2(l0, l1);
                split_bf16(w0, h0, l0); split_bf16(w1, h1, l1);
                *reinterpret_cast<uint32_t*>(Ch + (size_t)(r + 8) * 256 + c) = pack2(h0, h1);
                *reinterpret_cast<uint32_t*>(Cl + (size_t)(r + 8) * 256 + c) = pack2(l0, l1);
            } else {
                *reinterpret_cast<float2*>(Cf + (size_t)r * 256 + c) = make_float2(v0, v1);
                *reinterpret_cast<float2*>(Cf + (size_t)(r + 8) * 256 + c) = make_float2(w0, w1);
            }
        }
    }
}

// ---------------- pool + pos (+ adj zero, + split) ----------------
__global__ void pool_pos(const float* __restrict__ y2, const float* __restrict__ pos) {
    int idx = blockIdx.x * blockDim.x + threadIdx.x;
    if (idx < BB * NN) g_adj[idx] = 0ull;
    if (idx >= BB * NN * HH) return;
    int c = idx % HH;
    int n = (idx / HH) % NN;
    int b = idx / (HH * NN);
    float s = 0.f;
#pragma unroll
    for (int t = 0; t < 8; t++) s += y2[((size_t)b * TT + n * 8 + t) * HH + c];
    float v = s * 0.125f + pos[(size_t)n * HH + c];
    size_t o = ((size_t)b * NN + n) * HH + c;
    g_hn[o] = v;
    bf16 h, l;
    split_bf16(v, h, l);
    g_hnh[o] = h; g_hnl[o] = l;
}

// ---------------- adjacency ----------------
__global__ void adj_topk() {
    int b = blockIdx.x / NN, n = blockIdx.x % NN;
    __shared__ float sc[NN];
    int m = threadIdx.x;
    const float* hb = g_hn + (size_t)b * NN * HH;
    float s = 0.f;
    for (int k = 0; k < HH; k++) s = fmaf(hb[(size_t)n * HH + k], hb[(size_t)m * HH + k], s);
    sc[m] = s;
    __syncthreads();
    if (m == 0) {
        unsigned long long mask = 1ull << n;
        int sel[TOPK];
#pragma unroll 1
        for (int it = 0; it < TOPK; it++) {
            float best = -INFINITY; int bi = 0;
            for (int j = 0; j < NN; j++)
                if (sc[j] > best) { best = sc[j]; bi = j; }
            sel[it] = bi;
            sc[bi] = -INFINITY;
            mask |= 1ull << bi;
        }
        atomicOr(&g_adj[b * NN + n], mask);
        for (int it = 0; it < TOPK; it++)
            atomicOr(&g_adj[b * NN + sel[it]], 1ull << n);
    }
}

// ---------------- GAT ----------------
__global__ void gat_sd(const float* __restrict__ asrc, const float* __restrict__ adst) {
    int row = blockIdx.x;
    __shared__ float r1[HH], r2[HH];
    int t = threadIdx.x;
    float v = g_hw[(size_t)row * HH + t];
    r1[t] = v * asrc[t];
    r2[t] = v * adst[t];
    __syncthreads();
    for (int st = 128; st > 0; st >>= 1) {
        if (t < st) { r1[t] += r1[t + st]; r2[t] += r2[t + st]; }
        __syncthreads();
    }
    if (t == 0) { g_s[row] = r1[0]; g_d[row] = r2[0]; }
}

__global__ void gat_attn() {
    int b = blockIdx.x / NN, n = blockIdx.x % NN;
    __shared__ float attn[NN];
    __shared__ float inv_s;
    int t = threadIdx.x;
    unsigned long long mask = g_adj[b * NN + n];
    if (t < NN) {
        float e;
        if ((mask >> t) & 1ull) {
            float z = g_s[b * NN + n] + g_d[b * NN + t];
            e = z >= 0.f ? z : 0.2f * z;
        } else {
            e = -1e9f;
        }
        attn[t] = e;
    }
    __syncthreads();
    if (t == 0) {
        float mx = -INFINITY;
        for (int j = 0; j < NN; j++) mx = fmaxf(mx, attn[j]);
        float sum = 0.f;
        for (int j = 0; j < NN; j++) { float ex = expf(attn[j] - mx); attn[j] = ex; sum += ex; }
        inv_s = 1.f / sum;
    }
    __syncthreads();
    float inv = inv_s;
    float acc = 0.f;
    for (int m = 0; m < NN; m++)
        acc = fmaf(attn[m] * inv, g_hw[((size_t)b * NN + m) * HH + t], acc);
    float o = acc > 0.f ? acc : expm1f(acc);
    size_t oo = ((size_t)b * NN + n) * HH + t;
    float nh = g_hn[oo] + o;
    g_hn[oo] = nh;
    bf16 h, l;
    split_bf16(nh, h, l);
    g_hnh[oo] = h; g_hnl[oo] = l;
}

// ---------------- layernorm ----------------
__global__ void layernorm_k(const float* __restrict__ g, const float* __restrict__ bt) {
    int row = blockIdx.x;
    __shared__ float red[HH];
    __shared__ float mu_s, is_s;
    int t = threadIdx.x;
    float v = g_hn[(size_t)row * HH + t];
    red[t] = v;
    __syncthreads();
    for (int st = 128; st > 0; st >>= 1) { if (t < st) red[t] += red[t + st]; __syncthreads(); }
    if (t == 0) mu_s = red[0] * (1.f / HH);
    __syncthreads();
    float mu = mu_s;
    float dv = v - mu;
    red[t] = dv * dv;
    __syncthreads();
    for (int st = 128; st > 0; st >>= 1) { if (t < st) red[t] += red[t + st]; __syncthreads(); }
    if (t == 0) is_s = rsqrtf(red[0] * (1.f / HH) + 1e-5f);
    __syncthreads();
    g_ln[(size_t)row * HH + t] = dv * is_s * g[t] + bt[t];
}

// ---------------- pooling + classifier ----------------
__global__ void pool_emb(float* __restrict__ out) {
    int idx = blockIdx.x * blockDim.x + threadIdx.x;
    if (idx >= BB * HH) return;
    int b = idx / HH, c = idx % HH;
    float sm = 0.f, mx = -INFINITY;
    for (int n = 0; n < NN; n++) {
        float v = g_ln[((size_t)b * NN + n) * HH + c];
        sm += v;
        mx = fmaxf(mx, v);
    }
    out[BB * NCLS + (size_t)b * (2 * HH) + c] = sm * (1.f / NN);
    out[BB * NCLS + (size_t)b * (2 * HH) + HH + c] = mx;
}

__global__ void cls_kan(const float* __restrict__ cbw, const float* __restrict__ csw,
                        const float* __restrict__ csc, float* __restrict__ out) {
    int b = blockIdx.x;
    int t = threadIdx.x;
    __shared__ float r0[256], r1[256];
    float a0 = 0.f, a1 = 0.f;
    const float* emb = out + BB * NCLS + (size_t)b * (2 * HH);
    for (int i = t; i < 2 * HH; i += 256) {
        float x = emb[i];
        float sil = silu_f(x);
        float bs[8];
        bsplines8(x, bs);
        float p0 = sil * cbw[i];
        float p1 = sil * cbw[2 * HH + i];
        float s0 = csc[i], s1 = csc[2 * HH + i];
#pragma unroll
        for (int c = 0; c < 8; c++) {
            p0 = fmaf(bs[c] * csw[(size_t)i * 8 + c], s0, p0);
            p1 = fmaf(bs[c] * csw[(size_t)(2 * HH + i) * 8 + c], s1, p1);
        }
        a0 += p0;
        a1 += p1;
    }
    r0[t] = a0; r1[t] = a1;
    __syncthreads();
    for (int st = 128; st > 0; st >>= 1) {
        if (t < st) { r0[t] += r0[t + st]; r1[t] += r1[t + st]; }
        __syncthreads();
    }
    if (t == 0) { out[b * NCLS + 0] = r0[0]; out[b * NCLS + 1] = r1[0]; }
}

// ---------------- host launch ----------------
extern "C" void kernel_launch(void* const* d_in, const int* in_sizes, int n_in,
                              void* d_out, int out_size) {
    const float* x    = (const float*)d_in[0];
    const float* bbw  = (const float*)d_in[1];
    const float* bsw  = (const float*)d_in[2];
    const float* bsc  = (const float*)d_in[3];
    const float* c1w  = (const float*)d_in[4];
    const float* c1b  = (const float*)d_in[5];
    const float* c2w  = (const float*)d_in[6];
    const float* c2b  = (const float*)d_in[7];
    const float* pos  = (const float*)d_in[8];
    const float* gatW = (const float*)d_in[9];
    const float* asrc = (const float*)d_in[10];
    const float* adst = (const float*)d_in[11];
    const float* lng  = (const float*)d_in[12];
    const float* lnb  = (const float*)d_in[13];
    const float* cbw  = (const float*)d_in[14];
    const float* csw  = (const float*)d_in[15];
    const float* csc  = (const float*)d_in[16];
    float* out = (float*)d_out;

    bf16 *pfh, *pfl, *pwh, *pwl, *ph1h, *ph1l, *pwc1h, *pwc1l, *pwc2h, *pwc2l;
    bf16 *py1h, *py1l, *phnh, *phnl, *pwt0h, *pwt0l, *pwt1h, *pwt1l;
    float *py2, *phw;
    cudaGetSymbolAddress((void**)&pfh, g_fh);
    cudaGetSymbolAddress((void**)&pfl, g_fl);
    cudaGetSymbolAddress((void**)&pwh, g_wh);
    cudaGetSymbolAddress((void**)&pwl, g_wl);
    cudaGetSymbolAddress((void**)&ph1h, g_h1h);
    cudaGetSymbolAddress((void**)&ph1l, g_h1l);
    cudaGetSymbolAddress((void**)&pwc1h, g_wc1h);
    cudaGetSymbolAddress((void**)&pwc1l, g_wc1l);
    cudaGetSymbolAddress((void**)&pwc2h, g_wc2h);
    cudaGetSymbolAddress((void**)&pwc2l, g_wc2l);
    cudaGetSymbolAddress((void**)&py1h, g_y1h);
    cudaGetSymbolAddress((void**)&py1l, g_y1l);
    cudaGetSymbolAddress((void**)&phnh, g_hnh);
    cudaGetSymbolAddress((void**)&phnl, g_hnl);
    cudaGetSymbolAddress((void**)&pwt0h, g_wt0h);
    cudaGetSymbolAddress((void**)&pwt0l, g_wt0l);
    cudaGetSymbolAddress((void**)&pwt1h, g_wt1h);
    cudaGetSymbolAddress((void**)&pwt1l, g_wt1l);
    cudaGetSymbolAddress((void**)&py2, g_y2);
    cudaGetSymbolAddress((void**)&phw, g_hw);

    cudaFuncSetAttribute(gemm_mma<2, 0>, cudaFuncAttributeMaxDynamicSharedMemorySize, GEMM_SMEM);
    cudaFuncSetAttribute(gemm_mma<3, 1>, cudaFuncAttributeMaxDynamicSharedMemorySize, GEMM_SMEM);
    cudaFuncSetAttribute(gemm_mma<1, 1>, cudaFuncAttributeMaxDynamicSharedMemorySize, GEMM_SMEM);
    cudaFuncSetAttribute(gemm_mma<0, 0>, cudaFuncAttributeMaxDynamicSharedMemorySize, GEMM_SMEM);

    const int TPB = 256;

    // all prep first (launches 1-5), bridge GEMM is launch #6 (ncu -s 5 samples it)
    bridge_features_bf16<<<MROWS * (DIN / 8) / TPB, TPB>>>(x);                         // 1
    build_wcat_bf16<<<(HH * DIN + TPB - 1) / TPB, TPB>>>(bbw, bsw, bsc);               // 2
    conv_w_bf16<<<(HH * HH + TPB - 1) / TPB, TPB>>>(c1w, pwc1h, pwc1l);                // 3
    conv_w_bf16<<<(HH * HH + TPB - 1) / TPB, TPB>>>(c2w, pwc2h, pwc2l);                // 4
    gatwt_bf16<<<(HH * HH + TPB - 1) / TPB, TPB>>>(gatW, pwt0h, pwt0l);                // 5

    // bridge GEMM (raw -> split bf16)                                                  // 6
    gemm_mma<2, 0><<<MROWS / 64, 256, GEMM_SMEM>>>(pfh, pfl, pwh, pwl,
                                                   nullptr, ph1h, ph1l, KBRIDGE, nullptr);

    // conv1 (implicit im2col) + selu -> split bf16
    gemm_mma<3, 1><<<MROWS / 64, 256, GEMM_SMEM>>>(ph1h, ph1l, pwc1h, pwc1l,
                                                   nullptr, py1h, py1l, KCONV, c1b);

    // conv2 (implicit im2col) + selu -> fp32
    gemm_mma<1, 1><<<MROWS / 64, 256, GEMM_SMEM>>>(py1h, py1l, pwc2h, pwc2l,
                                                   py2, nullptr, nullptr, KCONV, c2b);

    // pool + pos (+ adj zero + split)
    pool_pos<<<(BB * NN * HH + TPB - 1) / TPB, TPB>>>(py2, pos);

    // adjacency
    adj_topk<<<BB * NN, NN>>>();

    // GAT layer 0
    gemm_mma<0, 0><<<NROWS / 64, 256, GEMM_SMEM>>>(phnh, phnl, pwt0h, pwt0l,
                                                   phw, nullptr, nullptr, HH, nullptr);
    gat_sd<<<NROWS, HH>>>(asrc, adst);
    gat_attn<<<NROWS, HH>>>();

    // GAT layer 1
    gatwt_bf16<<<(HH * HH + TPB - 1) / TPB, TPB>>>(gatW + (size_t)HH * HH, pwt1h, pwt1l);
    gemm_mma<0, 0><<<NROWS / 64, 256, GEMM_SMEM>>>(phnh, phnl, pwt1h, pwt1l,
                                                   phw, nullptr, nullptr, HH, nullptr);
    gat_sd<<<NROWS, HH>>>(asrc + HH, adst + HH);
    gat_attn<<<NROWS, HH>>>();

    // layernorm + pooling + classifier
    layernorm_k<<<NROWS, HH>>>(lng, lnb);
    pool_emb<<<(BB * HH + TPB - 1) / TPB, TPB>>>(out);
    cls_kan<<<BB, 256>>>(cbw, csw, csc, out);
}

// round 8
// speedup vs baseline: 1.0571x; 1.0571x over previous
#include <cuda_runtime.h>
#include <cuda_bf16.h>
#include <math.h>
#include <stdint.h>

typedef __nv_bfloat16 bf16;

// ---------------- problem constants ----------------
#define BB 16
#define TT 512
#define DIN 1024
#define HH 256
#define NN 64
#define TOPK 8
#define NCLS 2
#define KBRIDGE (DIN * 9)      // 9216
#define KCONV (HH * 3)         // 768
#define MROWS (BB * TT)        // 8192
#define NROWS (BB * NN)        // 1024

// ---------------- PTX helpers ----------------
__device__ __forceinline__ uint32_t smem_u32(const void* p) {
    uint32_t a;
    asm("{ .reg .u64 t; cvta.to.shared.u64 t, %1; cvt.u32.u64 %0, t; }" : "=r"(a) : "l"(p));
    return a;
}
#define CP_ASYNC16(dst, src) \
    asm volatile("cp.async.cg.shared.global [%0], [%1], 16;" :: "r"(dst), "l"(src) : "memory")
#define CP_COMMIT() asm volatile("cp.async.commit_group;" ::: "memory")
#define CP_WAIT(N)  asm volatile("cp.async.wait_group %0;" :: "n"(N) : "memory")
#define LDSM_X4(r0, r1, r2, r3, a) \
    asm volatile("ldmatrix.sync.aligned.m8n8.x4.shared.b16 {%0,%1,%2,%3}, [%4];" \
        : "=r"(r0), "=r"(r1), "=r"(r2), "=r"(r3) : "r"(a))
#define MMA_BF16(c, a0, a1, a2, a3, b0, b1) \
    asm volatile("mma.sync.aligned.m16n8k16.row.col.f32.bf16.bf16.f32 " \
        "{%0,%1,%2,%3}, {%4,%5,%6,%7}, {%8,%9}, {%0,%1,%2,%3};" \
        : "+f"((c)[0]), "+f"((c)[1]), "+f"((c)[2]), "+f"((c)[3]) \
        : "r"(a0), "r"(a1), "r"(a2), "r"(a3), "r"(b0), "r"(b1))
#define STS128Z(addr) \
    asm volatile("st.shared.v4.b32 [%0], {%1,%1,%1,%1};" :: "r"(addr), "r"(0u) : "memory")

// ---------------- scratch ----------------
__device__ bf16 g_fh[(size_t)MROWS * KBRIDGE];
__device__ bf16 g_fl[(size_t)MROWS * KBRIDGE];
__device__ bf16 g_wh[HH * KBRIDGE];
__device__ bf16 g_wl[HH * KBRIDGE];
__device__ float g_part[(size_t)4 * MROWS * HH];   // split-K partials (32 MB)
__device__ bf16 g_h1h[MROWS * HH];
__device__ bf16 g_h1l[MROWS * HH];
__device__ bf16 g_wc1h[HH * KCONV];
__device__ bf16 g_wc1l[HH * KCONV];
__device__ bf16 g_wc2h[HH * KCONV];
__device__ bf16 g_wc2l[HH * KCONV];
__device__ bf16 g_y1h[MROWS * HH];
__device__ bf16 g_y1l[MROWS * HH];
__device__ float g_y2[MROWS * HH];
__device__ float g_hn[NROWS * HH];
__device__ bf16 g_hnh[NROWS * HH];
__device__ bf16 g_hnl[NROWS * HH];
__device__ bf16 g_wt0h[HH * HH];
__device__ bf16 g_wt0l[HH * HH];
__device__ bf16 g_wt1h[HH * HH];
__device__ bf16 g_wt1l[HH * HH];
__device__ float g_hw[NROWS * HH];
__device__ float g_s[NROWS];
__device__ float g_d[NROWS];
__device__ unsigned long long g_adj[BB * NN];
__device__ float g_ln[NROWS * HH];

// ---------------- math helpers ----------------
__device__ __forceinline__ float silu_f(float x) { return x * (1.f / (1.f + expf(-x))); }
__device__ __forceinline__ float selu_f(float x) {
    const float a = 1.6732632423543772f, s = 1.0507009873554805f;
    return x > 0.f ? s * x : s * a * expm1f(x);
}
__device__ __forceinline__ void split_bf16(float v, bf16& h, bf16& l) {
    h = __float2bfloat16_rn(v);
    l = __float2bfloat16_rn(v - __bfloat162float(h));
}
union Pack2 { bf16 b[2]; uint32_t u; };
union Pack4 { bf16 b[4]; uint2 u; };
__device__ __forceinline__ void split_store4(const float* v, bf16* ph, bf16* pl) {
    Pack4 H, L;
#pragma unroll
    for (int j = 0; j < 4; j++) split_bf16(v[j], H.b[j], L.b[j]);
    *reinterpret_cast<uint2*>(ph) = H.u;
    *reinterpret_cast<uint2*>(pl) = L.u;
}
__device__ __forceinline__ void bsplines8(float x, float* out) {
    const float h = 0.4f;
    float b[11];
#pragma unroll
    for (int j = 0; j < 11; j++) {
        float gj = (float)(j - 3) * h - 1.0f;
        float gj1 = (float)(j - 2) * h - 1.0f;
        b[j] = (x >= gj && x < gj1) ? 1.f : 0.f;
    }
#pragma unroll
    for (int k = 1; k <= 3; k++) {
        float inv = 1.f / ((float)k * h);
#pragma unroll
        for (int j = 0; j < 11; j++) {
            if (j < 11 - k) {
                float gj = (float)(j - 3) * h - 1.0f;
                float gjk1 = (float)(j + k - 2) * h - 1.0f;
                b[j] = (x - gj) * inv * b[j] + (gjk1 - x) * inv * b[j + 1];
            }
        }
    }
#pragma unroll
    for (int j = 0; j < 8; j++) out[j] = b[j];
}

// ---------------- prep kernels ----------------
__global__ void bridge_features_bf16(const float* __restrict__ x) {
    int idx = blockIdx.x * blockDim.x + threadIdx.x;
    if (idx >= MROWS * (DIN / 4)) return;
    int r = idx >> 8, i4 = idx & 255;
    float4 xv = *reinterpret_cast<const float4*>(x + (size_t)r * DIN + i4 * 4);
    float vv[4] = {xv.x, xv.y, xv.z, xv.w};
    float f[9][4];
#pragma unroll
    for (int j = 0; j < 4; j++) {
        f[0][j] = silu_f(vv[j]);
        float bs[8];
        bsplines8(vv[j], bs);
#pragma unroll
        for (int c = 0; c < 8; c++) f[c + 1][j] = bs[c];
    }
    size_t base = (size_t)r * KBRIDGE + i4 * 4;
#pragma unroll
    for (int g = 0; g < 9; g++)
        split_store4(f[g], g_fh + base + (size_t)g * DIN, g_fl + base + (size_t)g * DIN);
}

__global__ void build_wcat_bf16(const float* __restrict__ bw, const float* __restrict__ sw,
                                const float* __restrict__ sc) {
    int idx = blockIdx.x * blockDim.x + threadIdx.x;
    if (idx >= HH * DIN) return;
    int i = idx % DIN, o = idx / DIN;
    size_t base = (size_t)o * KBRIDGE + i;
    bf16 h, l;
    split_bf16(bw[idx], h, l);
    g_wh[base] = h; g_wl[base] = l;
    float scale = sc[idx];
#pragma unroll
    for (int c = 0; c < 8; c++) {
        split_bf16(sw[(size_t)idx * 8 + c] * scale, h, l);
        size_t p = base + (size_t)(c + 1) * DIN;
        g_wh[p] = h; g_wl[p] = l;
    }
}

__global__ void conv_w_bf16(const float* __restrict__ w, bf16* __restrict__ wh, bf16* __restrict__ wl) {
    int idx = blockIdx.x * blockDim.x + threadIdx.x;
    if (idx >= HH * HH) return;
    int i = idx % HH, o = idx / HH;
#pragma unroll
    for (int j = 0; j < 3; j++) {
        bf16 h, l;
        split_bf16(w[((size_t)o * HH + i) * 3 + j], h, l);
        size_t p = (size_t)o * KCONV + j * HH + i;
        wh[p] = h; wl[p] = l;
    }
}

__global__ void gatwt_bf16(const float* __restrict__ w, bf16* __restrict__ wh, bf16* __restrict__ wl) {
    int idx = blockIdx.x * blockDim.x + threadIdx.x;
    if (idx >= HH * HH) return;
    int k = idx % HH, n = idx / HH;
    bf16 h, l;
    split_bf16(w[(size_t)k * HH + n], h, l);
    wh[idx] = h; wl[idx] = l;
}

// ========== split-bf16 split-K GEMM: 512 threads, 16 warps, warp tile 32x64 ==========
// Tile 128(M) x 256(N), BK=32, 2-stage cp.async. Grid (M/128, SPLITK).
// Each z-slice computes K range [z*kLen, (z+1)*kLen) into fp32 partial buffer.
// SHIFT=1: implicit im2col on A (conv k=3 pad=1 over 512-step batches).
#define BKS 32
#define SROWS 80
#define AS_STG (128 * SROWS)      // 10240
#define BS_STG (256 * SROWS)      // 20480
#define GEMM_SMEM (4 * AS_STG + 4 * BS_STG)   // 122880

template <int SHIFT>
__global__ __launch_bounds__(512, 1) void gemm_mma(
    const bf16* __restrict__ Ah, const bf16* __restrict__ Al,
    const bf16* __restrict__ Bh, const bf16* __restrict__ Bl,
    float* __restrict__ Cpart, int K, int kLen) {
    extern __shared__ char smem[];
    uint32_t s0 = smem_u32(smem);
    uint32_t sAh = s0, sAl = s0 + 2 * AS_STG;
    uint32_t sBh = s0 + 4 * AS_STG, sBl = sBh + 2 * BS_STG;

    int tid = threadIdx.x, lane = tid & 31, wid = tid >> 5;
    int wm = wid & 3, wn = wid >> 2;      // 4 x 4 warp grid, warp tile 32x64
    int bm = blockIdx.x * 128;
    int kOff = blockIdx.y * kLen;
    float* Cf = Cpart + (size_t)blockIdx.y * gridDim.x * 128 * 256;
    const int nc = kLen / BKS;

    int aRow = wm * 32 + (lane & 15);
    int aCol = (lane >> 4) * 8;
    int bRow = wn * 64 + (lane & 7) + ((lane >> 4) << 3);
    int bCol = ((lane >> 3) & 1) * 8;

    float acc[2][8][4];
#pragma unroll
    for (int i = 0; i < 2; i++)
#pragma unroll
        for (int j = 0; j < 8; j++)
#pragma unroll
            for (int q = 0; q < 4; q++) acc[i][j][q] = 0.f;

    auto issue = [&](int stage, int k0) {
        {   // A: 128 rows x 4 chunks = 512 = 1/thread per array
            int r = tid >> 2, c = tid & 3;
            uint32_t dh = sAh + (uint32_t)(stage * AS_STG + r * SROWS + c * 16);
            uint32_t dl = sAl + (uint32_t)(stage * AS_STG + r * SROWS + c * 16);
            if (SHIFT) {
                int k = kOff + k0 + c * 8;
                int j = k >> 8, cc = k & 255;
                int grow = bm + r;
                int tj = (grow & 511) + j - 1;
                if (tj >= 0 && tj < 512) {
                    size_t go = (size_t)(grow + j - 1) * 256 + cc;
                    CP_ASYNC16(dh, Ah + go);
                    CP_ASYNC16(dl, Al + go);
                } else {
                    STS128Z(dh);
                    STS128Z(dl);
                }
            } else {
                size_t go = (size_t)(bm + r) * K + kOff + k0 + c * 8;
                CP_ASYNC16(dh, Ah + go);
                CP_ASYNC16(dl, Al + go);
            }
        }
#pragma unroll
        for (int i = 0; i < 2; i++) {   // B: 256 rows x 4 chunks = 1024 = 2/thread
            int q = i * 512 + tid;
            int r = q >> 2, c = q & 3;
            uint32_t d = (uint32_t)(stage * BS_STG + r * SROWS + c * 16);
            size_t go = (size_t)r * K + kOff + k0 + c * 8;
            CP_ASYNC16(sBh + d, Bh + go);
            CP_ASYNC16(sBl + d, Bl + go);
        }
    };

    issue(0, 0);
    CP_COMMIT();

    for (int kc = 0; kc < nc; kc++) {
        if (kc + 1 < nc) {
            issue((kc + 1) & 1, (kc + 1) * BKS);
            CP_COMMIT();
            CP_WAIT(1);
        } else {
            CP_WAIT(0);
        }
        __syncthreads();
        uint32_t stA = (uint32_t)((kc & 1) * AS_STG);
        uint32_t stB = (uint32_t)((kc & 1) * BS_STG);
#pragma unroll
        for (int kk = 0; kk < 2; kk++) {
            uint32_t ah[2][4], al[2][4];
#pragma unroll
            for (int mt = 0; mt < 2; mt++) {
                uint32_t ao = stA + (uint32_t)((aRow + mt * 16) * SROWS + (aCol + kk * 16) * 2);
                LDSM_X4(ah[mt][0], ah[mt][1], ah[mt][2], ah[mt][3], sAh + ao);
                LDSM_X4(al[mt][0], al[mt][1], al[mt][2], al[mt][3], sAl + ao);
            }
#pragma unroll
            for (int nt2 = 0; nt2 < 4; nt2++) {
                uint32_t bo = stB + (uint32_t)((bRow + nt2 * 16) * SROWS + (bCol + kk * 16) * 2);
                uint32_t bh[4], bl[4];
                LDSM_X4(bh[0], bh[1], bh[2], bh[3], sBh + bo);
                LDSM_X4(bl[0], bl[1], bl[2], bl[3], sBl + bo);
#pragma unroll
                for (int mt = 0; mt < 2; mt++) {
                    int n0 = nt2 * 2, n1 = n0 + 1;
                    MMA_BF16(acc[mt][n0], ah[mt][0], ah[mt][1], ah[mt][2], ah[mt][3], bh[0], bh[1]);
                    MMA_BF16(acc[mt][n0], ah[mt][0], ah[mt][1], ah[mt][2], ah[mt][3], bl[0], bl[1]);
                    MMA_BF16(acc[mt][n0], al[mt][0], al[mt][1], al[mt][2], al[mt][3], bh[0], bh[1]);
                    MMA_BF16(acc[mt][n1], ah[mt][0], ah[mt][1], ah[mt][2], ah[mt][3], bh[2], bh[3]);
                    MMA_BF16(acc[mt][n1], ah[mt][0], ah[mt][1], ah[mt][2], ah[mt][3], bl[2], bl[3]);
                    MMA_BF16(acc[mt][n1], al[mt][0], al[mt][1], al[mt][2], al[mt][3], bh[2], bh[3]);
                }
            }
        }
        __syncthreads();
    }

    // epilogue: raw fp32 partial
    int rbase = bm + wm * 32 + (lane >> 2);
    int cbase = wn * 64 + (lane & 3) * 2;
#pragma unroll
    for (int mt = 0; mt < 2; mt++) {
#pragma unroll
        for (int nt = 0; nt < 8; nt++) {
            int r = rbase + mt * 16;
            int c = cbase + nt * 8;
            *reinterpret_cast<float2*>(Cf + (size_t)r * 256 + c) =
                make_float2(acc[mt][nt][0], acc[mt][nt][1]);
            *reinterpret_cast<float2*>(Cf + (size_t)(r + 8) * 256 + c) =
                make_float2(acc[mt][nt][2], acc[mt][nt][3]);
        }
    }
}

// ---------------- split-K combine + epilogue ----------------
// EPI: 0 fp32 | 1 selu+bias fp32 | 2 split bf16 | 3 selu+bias split bf16
template <int EPI, int SK>
__global__ void combine_k(const float* __restrict__ part, size_t slice,
                          float* __restrict__ Cf, bf16* __restrict__ Ch, bf16* __restrict__ Cl,
                          const float* __restrict__ bias, int total4) {
    int idx = blockIdx.x * blockDim.x + threadIdx.x;
    if (idx >= total4) return;
    const float4* p4 = reinterpret_cast<const float4*>(part);
    size_t s4 = slice >> 2;
    float4 a = p4[idx];
#pragma unroll
    for (int s = 1; s < SK; s++) {
        float4 b = p4[idx + (size_t)s * s4];
        a.x += b.x; a.y += b.y; a.z += b.z; a.w += b.w;
    }
    float v[4] = {a.x, a.y, a.z, a.w};
    if (EPI == 1 || EPI == 3) {
        int c = (idx * 4) & 255;
        float4 b4 = *reinterpret_cast<const float4*>(bias + c);
        v[0] = selu_f(v[0] + b4.x); v[1] = selu_f(v[1] + b4.y);
        v[2] = selu_f(v[2] + b4.z); v[3] = selu_f(v[3] + b4.w);
    }
    if (EPI >= 2) {
        split_store4(v, Ch + (size_t)idx * 4, Cl + (size_t)idx * 4);
    } else {
        *reinterpret_cast<float4*>(Cf + (size_t)idx * 4) = make_float4(v[0], v[1], v[2], v[3]);
    }
}

// ---------------- pool + pos (+ adj zero, + split) ----------------
__global__ void pool_pos(const float* __restrict__ y2, const float* __restrict__ pos) {
    int idx = blockIdx.x * blockDim.x + threadIdx.x;
    if (idx < BB * NN) g_adj[idx] = 0ull;
    if (idx >= BB * NN * HH) return;
    int c = idx % HH;
    int n = (idx / HH) % NN;
    int b = idx / (HH * NN);
    float s = 0.f;
#pragma unroll
    for (int t = 0; t < 8; t++) s += y2[((size_t)b * TT + n * 8 + t) * HH + c];
    float v = s * 0.125f + pos[(size_t)n * HH + c];
    size_t o = ((size_t)b * NN + n) * HH + c;
    g_hn[o] = v;
    bf16 h, l;
    split_bf16(v, h, l);
    g_hnh[o] = h; g_hnl[o] = l;
}

// ---------------- adjacency ----------------
__global__ void adj_topk() {
    int b = blockIdx.x / NN, n = blockIdx.x % NN;
    __shared__ float sc[NN];
    int m = threadIdx.x;
    const float* hb = g_hn + (size_t)b * NN * HH;
    float s = 0.f;
    for (int k = 0; k < HH; k++) s = fmaf(hb[(size_t)n * HH + k], hb[(size_t)m * HH + k], s);
    sc[m] = s;
    __syncthreads();
    if (m == 0) {
        unsigned long long mask = 1ull << n;
        int sel[TOPK];
#pragma unroll 1
        for (int it = 0; it < TOPK; it++) {
            float best = -INFINITY; int bi = 0;
            for (int j = 0; j < NN; j++)
                if (sc[j] > best) { best = sc[j]; bi = j; }
            sel[it] = bi;
            sc[bi] = -INFINITY;
            mask |= 1ull << bi;
        }
        atomicOr(&g_adj[b * NN + n], mask);
        for (int it = 0; it < TOPK; it++)
            atomicOr(&g_adj[b * NN + sel[it]], 1ull << n);
    }
}

// ---------------- GAT ----------------
__global__ void gat_sd(const float* __restrict__ asrc, const float* __restrict__ adst) {
    int row = blockIdx.x;
    __shared__ float r1[HH], r2[HH];
    int t = threadIdx.x;
    float v = g_hw[(size_t)row * HH + t];
    r1[t] = v * asrc[t];
    r2[t] = v * adst[t];
    __syncthreads();
    for (int st = 128; st > 0; st >>= 1) {
        if (t < st) { r1[t] += r1[t + st]; r2[t] += r2[t + st]; }
        __syncthreads();
    }
    if (t == 0) { g_s[row] = r1[0]; g_d[row] = r2[0]; }
}

__global__ void gat_attn() {
    int b = blockIdx.x / NN, n = blockIdx.x % NN;
    __shared__ float attn[NN];
    __shared__ float inv_s;
    int t = threadIdx.x;
    unsigned long long mask = g_adj[b * NN + n];
    if (t < NN) {
        float e;
        if ((mask >> t) & 1ull) {
            float z = g_s[b * NN + n] + g_d[b * NN + t];
            e = z >= 0.f ? z : 0.2f * z;
        } else {
            e = -1e9f;
        }
        attn[t] = e;
    }
    __syncthreads();
    if (t == 0) {
        float mx = -INFINITY;
        for (int j = 0; j < NN; j++) mx = fmaxf(mx, attn[j]);
        float sum = 0.f;
        for (int j = 0; j < NN; j++) { float ex = expf(attn[j] - mx); attn[j] = ex; sum += ex; }
        inv_s = 1.f / sum;
    }
    __syncthreads();
    float inv = inv_s;
    float acc = 0.f;
    for (int m = 0; m < NN; m++)
        acc = fmaf(attn[m] * inv, g_hw[((size_t)b * NN + m) * HH + t], acc);
    float o = acc > 0.f ? acc : expm1f(acc);
    size_t oo = ((size_t)b * NN + n) * HH + t;
    float nh = g_hn[oo] + o;
    g_hn[oo] = nh;
    bf16 h, l;
    split_bf16(nh, h, l);
    g_hnh[oo] = h; g_hnl[oo] = l;
}

// ---------------- layernorm ----------------
__global__ void layernorm_k(const float* __restrict__ g, const float* __restrict__ bt) {
    int row = blockIdx.x;
    __shared__ float red[HH];
    __shared__ float mu_s, is_s;
    int t = threadIdx.x;
    float v = g_hn[(size_t)row * HH + t];
    red[t] = v;
    __syncthreads();
    for (int st = 128; st > 0; st >>= 1) { if (t < st) red[t] += red[t + st]; __syncthreads(); }
    if (t == 0) mu_s = red[0] * (1.f / HH);
    __syncthreads();
    float mu = mu_s;
    float dv = v - mu;
    red[t] = dv * dv;
    __syncthreads();
    for (int st = 128; st > 0; st >>= 1) { if (t < st) red[t] += red[t + st]; __syncthreads(); }
    if (t == 0) is_s = rsqrtf(red[0] * (1.f / HH) + 1e-5f);
    __syncthreads();
    g_ln[(size_t)row * HH + t] = dv * is_s * g[t] + bt[t];
}

// ---------------- pooling + classifier ----------------
__global__ void pool_emb(float* __restrict__ out) {
    int idx = blockIdx.x * blockDim.x + threadIdx.x;
    if (idx >= BB * HH) return;
    int b = idx / HH, c = idx % HH;
    float sm = 0.f, mx = -INFINITY;
    for (int n = 0; n < NN; n++) {
        float v = g_ln[((size_t)b * NN + n) * HH + c];
        sm += v;
        mx = fmaxf(mx, v);
    }
    out[BB * NCLS + (size_t)b * (2 * HH) + c] = sm * (1.f / NN);
    out[BB * NCLS + (size_t)b * (2 * HH) + HH + c] = mx;
}

__global__ void cls_kan(const float* __restrict__ cbw, const float* __restrict__ csw,
                        const float* __restrict__ csc, float* __restrict__ out) {
    int b = blockIdx.x;
    int t = threadIdx.x;
    __shared__ float r0[256], r1[256];
    float a0 = 0.f, a1 = 0.f;
    const float* emb = out + BB * NCLS + (size_t)b * (2 * HH);
    for (int i = t; i < 2 * HH; i += 256) {
        float x = emb[i];
        float sil = silu_f(x);
        float bs[8];
        bsplines8(x, bs);
        float p0 = sil * cbw[i];
        float p1 = sil * cbw[2 * HH + i];
        float s0 = csc[i], s1 = csc[2 * HH + i];
#pragma unroll
        for (int c = 0; c < 8; c++) {
            p0 = fmaf(bs[c] * csw[(size_t)i * 8 + c], s0, p0);
            p1 = fmaf(bs[c] * csw[(size_t)(2 * HH + i) * 8 + c], s1, p1);
        }
        a0 += p0;
        a1 += p1;
    }
    r0[t] = a0; r1[t] = a1;
    __syncthreads();
    for (int st = 128; st > 0; st >>= 1) {
        if (t < st) { r0[t] += r0[t + st]; r1[t] += r1[t + st]; }
        __syncthreads();
    }
    if (t == 0) { out[b * NCLS + 0] = r0[0]; out[b * NCLS + 1] = r1[0]; }
}

// ---------------- host launch ----------------
extern "C" void kernel_launch(void* const* d_in, const int* in_sizes, int n_in,
                              void* d_out, int out_size) {
    const float* x    = (const float*)d_in[0];
    const float* bbw  = (const float*)d_in[1];
    const float* bsw  = (const float*)d_in[2];
    const float* bsc  = (const float*)d_in[3];
    const float* c1w  = (const float*)d_in[4];
    const float* c1b  = (const float*)d_in[5];
    const float* c2w  = (const float*)d_in[6];
    const float* c2b  = (const float*)d_in[7];
    const float* pos  = (const float*)d_in[8];
    const float* gatW = (const float*)d_in[9];
    const float* asrc = (const float*)d_in[10];
    const float* adst = (const float*)d_in[11];
    const float* lng  = (const float*)d_in[12];
    const float* lnb  = (const float*)d_in[13];
    const float* cbw  = (const float*)d_in[14];
    const float* csw  = (const float*)d_in[15];
    const float* csc  = (const float*)d_in[16];
    float* out = (float*)d_out;

    bf16 *pfh, *pfl, *pwh, *pwl, *ph1h, *ph1l, *pwc1h, *pwc1l, *pwc2h, *pwc2l;
    bf16 *py1h, *py1l, *phnh, *phnl, *pwt0h, *pwt0l, *pwt1h, *pwt1l;
    float *py2, *phw, *ppart;
    cudaGetSymbolAddress((void**)&pfh, g_fh);
    cudaGetSymbolAddress((void**)&pfl, g_fl);
    cudaGetSymbolAddress((void**)&pwh, g_wh);
    cudaGetSymbolAddress((void**)&pwl, g_wl);
    cudaGetSymbolAddress((void**)&ph1h, g_h1h);
    cudaGetSymbolAddress((void**)&ph1l, g_h1l);
    cudaGetSymbolAddress((void**)&pwc1h, g_wc1h);
    cudaGetSymbolAddress((void**)&pwc1l, g_wc1l);
    cudaGetSymbolAddress((void**)&pwc2h, g_wc2h);
    cudaGetSymbolAddress((void**)&pwc2l, g_wc2l);
    cudaGetSymbolAddress((void**)&py1h, g_y1h);
    cudaGetSymbolAddress((void**)&py1l, g_y1l);
    cudaGetSymbolAddress((void**)&phnh, g_hnh);
    cudaGetSymbolAddress((void**)&phnl, g_hnl);
    cudaGetSymbolAddress((void**)&pwt0h, g_wt0h);
    cudaGetSymbolAddress((void**)&pwt0l, g_wt0l);
    cudaGetSymbolAddress((void**)&pwt1h, g_wt1h);
    cudaGetSymbolAddress((void**)&pwt1l, g_wt1l);
    cudaGetSymbolAddress((void**)&py2, g_y2);
    cudaGetSymbolAddress((void**)&phw, g_hw);
    cudaGetSymbolAddress((void**)&ppart, g_part);

    cudaFuncSetAttribute(gemm_mma<0>, cudaFuncAttributeMaxDynamicSharedMemorySize, GEMM_SMEM);
    cudaFuncSetAttribute(gemm_mma<1>, cudaFuncAttributeMaxDynamicSharedMemorySize, GEMM_SMEM);

    const int TPB = 256;
    const size_t SLICE_BIG = (size_t)MROWS * HH;      // 2M elems per split slice
    const size_t SLICE_SMALL = (size_t)NROWS * HH;
    const int T4_BIG = MROWS * HH / 4;
    const int T4_SMALL = NROWS * HH / 4;

    // prep (launches 1-5)
    bridge_features_bf16<<<MROWS * (DIN / 4) / TPB, TPB>>>(x);
    build_wcat_bf16<<<(HH * DIN + TPB - 1) / TPB, TPB>>>(bbw, bsw, bsc);
    conv_w_bf16<<<(HH * HH + TPB - 1) / TPB, TPB>>>(c1w, pwc1h, pwc1l);
    conv_w_bf16<<<(HH * HH + TPB - 1) / TPB, TPB>>>(c2w, pwc2h, pwc2l);
    gatwt_bf16<<<(HH * HH + TPB - 1) / TPB, TPB>>>(gatW, pwt0h, pwt0l);

    // bridge GEMM: split-K 4 (launch #6) + combine -> split bf16
    gemm_mma<0><<<dim3(MROWS / 128, 4), 512, GEMM_SMEM>>>(pfh, pfl, pwh, pwl,
                                                          ppart, KBRIDGE, KBRIDGE / 4);
    combine_k<2, 4><<<(T4_BIG + TPB - 1) / TPB, TPB>>>(ppart, SLICE_BIG,
                                                       nullptr, ph1h, ph1l, nullptr, T4_BIG);

    // conv1: split-K 2 + combine -> selu+bias split bf16
    gemm_mma<1><<<dim3(MROWS / 128, 2), 512, GEMM_SMEM>>>(ph1h, ph1l, pwc1h, pwc1l,
                                                          ppart, KCONV, KCONV / 2);
    combine_k<3, 2><<<(T4_BIG + TPB - 1) / TPB, TPB>>>(ppart, SLICE_BIG,
                                                       nullptr, py1h, py1l, c1b, T4_BIG);

    // conv2: split-K 2 + combine -> selu+bias fp32
    gemm_mma<1><<<dim3(MROWS / 128, 2), 512, GEMM_SMEM>>>(py1h, py1l, pwc2h, pwc2l,
                                                          ppart, KCONV, KCONV / 2);
    combine_k<1, 2><<<(T4_BIG + TPB - 1) / TPB, TPB>>>(ppart, SLICE_BIG,
                                                       py2, nullptr, nullptr, c2b, T4_BIG);

    // pool + pos (+ adj zero + split)
    pool_pos<<<(BB * NN * HH + TPB - 1) / TPB, TPB>>>(py2, pos);

    // adjacency
    adj_topk<<<BB * NN, NN>>>();

    // GAT layer 0: split-K 4 + combine -> fp32
    gemm_mma<0><<<dim3(NROWS / 128, 4), 512, GEMM_SMEM>>>(phnh, phnl, pwt0h, pwt0l,
                                                          ppart, HH, HH / 4);
    combine_k<0, 4><<<(T4_SMALL + TPB - 1) / TPB, TPB>>>(ppart, SLICE_SMALL,
                                                         phw, nullptr, nullptr, nullptr, T4_SMALL);
    gat_sd<<<NROWS, HH>>>(asrc, adst);
    gat_attn<<<NROWS, HH>>>();

    // GAT layer 1
    gatwt_bf16<<<(HH * HH + TPB - 1) / TPB, TPB>>>(gatW + (size_t)HH * HH, pwt1h, pwt1l);
    gemm_mma<0><<<dim3(NROWS / 128, 4), 512, GEMM_SMEM>>>(phnh, phnl, pwt1h, pwt1l,
                                                          ppart, HH, HH / 4);
    combine_k<0, 4><<<(T4_SMALL + TPB - 1) / TPB, TPB>>>(ppart, SLICE_SMALL,
                                                         phw, nullptr, nullptr, nullptr, T4_SMALL);
    gat_sd<<<NROWS, HH>>>(asrc + HH, adst + HH);
    gat_attn<<<NROWS, HH>>>();

    // layernorm + pooling + classifier
    layernorm_k<<<NROWS, HH>>>(lng, lnb);
    pool_emb<<<(BB * HH + TPB - 1) / TPB, TPB>>>(out);
    cls_kan<<<BB, 256>>>(cbw, csw, csc, out);
}

// round 9
// speedup vs baseline: 1.1002x; 1.0408x over previous
#include <cuda_runtime.h>
#include <cuda_bf16.h>
#include <math.h>
#include <stdint.h>

typedef __nv_bfloat16 bf16;

// ---------------- problem constants ----------------
#define BB 16
#define TT 512
#define DIN 1024
#define HH 256
#define NN 64
#define TOPK 8
#define NCLS 2
#define KBRIDGE (DIN * 9)      // 9216
#define KCONV (HH * 3)         // 768
#define MROWS (BB * TT)        // 8192
#define NROWS (BB * NN)        // 1024

// ---------------- PTX helpers ----------------
__device__ __forceinline__ uint32_t smem_u32(const void* p) {
    uint32_t a;
    asm("{ .reg .u64 t; cvta.to.shared.u64 t, %1; cvt.u32.u64 %0, t; }" : "=r"(a) : "l"(p));
    return a;
}
#define CP_ASYNC16(dst, src) \
    asm volatile("cp.async.cg.shared.global [%0], [%1], 16;" :: "r"(dst), "l"(src) : "memory")
#define CP_COMMIT() asm volatile("cp.async.commit_group;" ::: "memory")
#define CP_WAIT(N)  asm volatile("cp.async.wait_group %0;" :: "n"(N) : "memory")
#define LDSM_X4(r0, r1, r2, r3, a) \
    asm volatile("ldmatrix.sync.aligned.m8n8.x4.shared.b16 {%0,%1,%2,%3}, [%4];" \
        : "=r"(r0), "=r"(r1), "=r"(r2), "=r"(r3) : "r"(a))
#define MMA_BF16(c, a0, a1, a2, a3, b0, b1) \
    asm volatile("mma.sync.aligned.m16n8k16.row.col.f32.bf16.bf16.f32 " \
        "{%0,%1,%2,%3}, {%4,%5,%6,%7}, {%8,%9}, {%0,%1,%2,%3};" \
        : "+f"((c)[0]), "+f"((c)[1]), "+f"((c)[2]), "+f"((c)[3]) \
        : "r"(a0), "r"(a1), "r"(a2), "r"(a3), "r"(b0), "r"(b1))
#define STS128Z(addr) \
    asm volatile("st.shared.v4.b32 [%0], {%1,%1,%1,%1};" :: "r"(addr), "r"(0u) : "memory")

// ---------------- scratch ----------------
__device__ bf16 g_fh[(size_t)MROWS * KBRIDGE];
__device__ bf16 g_fl[(size_t)MROWS * KBRIDGE];
__device__ bf16 g_wh[HH * KBRIDGE];
__device__ bf16 g_wl[HH * KBRIDGE];
__device__ float g_part[(size_t)4 * MROWS * HH];   // split-K partials
__device__ bf16 g_h1h[MROWS * HH];
__device__ bf16 g_h1l[MROWS * HH];
__device__ bf16 g_wc1h[HH * KCONV];
__device__ bf16 g_wc1l[HH * KCONV];
__device__ bf16 g_wc2h[HH * KCONV];
__device__ bf16 g_wc2l[HH * KCONV];
__device__ bf16 g_y1h[MROWS * HH];
__device__ bf16 g_y1l[MROWS * HH];
__device__ float g_y2[MROWS * HH];
__device__ float g_hn[NROWS * HH];
__device__ bf16 g_hnh[NROWS * HH];
__device__ bf16 g_hnl[NROWS * HH];
__device__ bf16 g_wt0h[HH * HH];
__device__ bf16 g_wt0l[HH * HH];
__device__ bf16 g_wt1h[HH * HH];
__device__ bf16 g_wt1l[HH * HH];
__device__ float g_hw[NROWS * HH];
__device__ float g_s[NROWS];
__device__ float g_d[NROWS];
__device__ unsigned long long g_adj[BB * NN];
__device__ float g_ln[NROWS * HH];

// ---------------- math helpers ----------------
__device__ __forceinline__ float silu_f(float x) { return x * (1.f / (1.f + expf(-x))); }
__device__ __forceinline__ float selu_f(float x) {
    const float a = 1.6732632423543772f, s = 1.0507009873554805f;
    return x > 0.f ? s * x : s * a * expm1f(x);
}
__device__ __forceinline__ void split_bf16(float v, bf16& h, bf16& l) {
    h = __float2bfloat16_rn(v);
    l = __float2bfloat16_rn(v - __bfloat162float(h));
}
union Pack4 { bf16 b[4]; uint2 u; };
__device__ __forceinline__ void split_store4(const float* v, bf16* ph, bf16* pl) {
    Pack4 H, L;
#pragma unroll
    for (int j = 0; j < 4; j++) split_bf16(v[j], H.b[j], L.b[j]);
    *reinterpret_cast<uint2*>(ph) = H.u;
    *reinterpret_cast<uint2*>(pl) = L.u;
}
__device__ __forceinline__ void bsplines8(float x, float* out) {
    const float h = 0.4f;
    float b[11];
#pragma unroll
    for (int j = 0; j < 11; j++) {
        float gj = (float)(j - 3) * h - 1.0f;
        float gj1 = (float)(j - 2) * h - 1.0f;
        b[j] = (x >= gj && x < gj1) ? 1.f : 0.f;
    }
#pragma unroll
    for (int k = 1; k <= 3; k++) {
        float inv = 1.f / ((float)k * h);
#pragma unroll
        for (int j = 0; j < 11; j++) {
            if (j < 11 - k) {
                float gj = (float)(j - 3) * h - 1.0f;
                float gjk1 = (float)(j + k - 2) * h - 1.0f;
                b[j] = (x - gj) * inv * b[j] + (gjk1 - x) * inv * b[j + 1];
            }
        }
    }
#pragma unroll
    for (int j = 0; j < 8; j++) out[j] = b[j];
}

// ---------------- prep kernels ----------------
__global__ void bridge_features_bf16(const float* __restrict__ x) {
    int idx = blockIdx.x * blockDim.x + threadIdx.x;
    if (idx >= MROWS * (DIN / 4)) return;
    int r = idx >> 8, i4 = idx & 255;
    float4 xv = *reinterpret_cast<const float4*>(x + (size_t)r * DIN + i4 * 4);
    float vv[4] = {xv.x, xv.y, xv.z, xv.w};
    float f[9][4];
#pragma unroll
    for (int j = 0; j < 4; j++) {
        f[0][j] = silu_f(vv[j]);
        float bs[8];
        bsplines8(vv[j], bs);
#pragma unroll
        for (int c = 0; c < 8; c++) f[c + 1][j] = bs[c];
    }
    size_t base = (size_t)r * KBRIDGE + i4 * 4;
#pragma unroll
    for (int g = 0; g < 9; g++)
        split_store4(f[g], g_fh + base + (size_t)g * DIN, g_fl + base + (size_t)g * DIN);
}

__global__ void build_wcat_bf16(const float* __restrict__ bw, const float* __restrict__ sw,
                                const float* __restrict__ sc) {
    int idx = blockIdx.x * blockDim.x + threadIdx.x;
    if (idx >= HH * DIN) return;
    int i = idx % DIN, o = idx / DIN;
    size_t base = (size_t)o * KBRIDGE + i;
    bf16 h, l;
    split_bf16(bw[idx], h, l);
    g_wh[base] = h; g_wl[base] = l;
    float scale = sc[idx];
#pragma unroll
    for (int c = 0; c < 8; c++) {
        split_bf16(sw[(size_t)idx * 8 + c] * scale, h, l);
        size_t p = base + (size_t)(c + 1) * DIN;
        g_wh[p] = h; g_wl[p] = l;
    }
}

__global__ void conv_w_bf16(const float* __restrict__ w, bf16* __restrict__ wh, bf16* __restrict__ wl) {
    int idx = blockIdx.x * blockDim.x + threadIdx.x;
    if (idx >= HH * HH) return;
    int i = idx % HH, o = idx / HH;
#pragma unroll
    for (int j = 0; j < 3; j++) {
        bf16 h, l;
        split_bf16(w[((size_t)o * HH + i) * 3 + j], h, l);
        size_t p = (size_t)o * KCONV + j * HH + i;
        wh[p] = h; wl[p] = l;
    }
}

__global__ void gatwt_bf16(const float* __restrict__ w, bf16* __restrict__ wh, bf16* __restrict__ wl) {
    int idx = blockIdx.x * blockDim.x + threadIdx.x;
    if (idx >= HH * HH) return;
    int k = idx % HH, n = idx / HH;
    bf16 h, l;
    split_bf16(w[(size_t)k * HH + n], h, l);
    wh[idx] = h; wl[idx] = l;
}

// ===== split-bf16 split-K GEMM: 512 thr, warp tile 32x64, 3-stage, 1 barrier/chunk =====
// Tile 128(M) x 256(N), BK=32. Grid (M/128, SPLITK).
#define BKS 32
#define SROWS 80
#define AS_STG (128 * SROWS)      // 10240 (one array)
#define BS_STG (256 * SROWS)      // 20480
#define STG_TOT (2 * AS_STG + 2 * BS_STG)     // 61440 per stage (Ah,Al,Bh,Bl)
#define GEMM_SMEM (3 * STG_TOT)               // 184320

template <int SHIFT>
__global__ __launch_bounds__(512, 1) void gemm_mma(
    const bf16* __restrict__ Ah, const bf16* __restrict__ Al,
    const bf16* __restrict__ Bh, const bf16* __restrict__ Bl,
    float* __restrict__ Cpart, int K, int kLen) {
    extern __shared__ char smem[];
    uint32_t s0 = smem_u32(smem);

    int tid = threadIdx.x, lane = tid & 31, wid = tid >> 5;
    int wm = wid & 3, wn = wid >> 2;      // 4 x 4 warp grid, warp tile 32x64
    int bm = blockIdx.x * 128;
    int kOff = blockIdx.y * kLen;
    float* Cf = Cpart + (size_t)blockIdx.y * gridDim.x * 128 * 256;
    const int nc = kLen / BKS;

    int aRow = wm * 32 + (lane & 15);
    int aCol = (lane >> 4) * 8;
    int bRow = wn * 64 + (lane & 7) + ((lane >> 4) << 3);
    int bCol = ((lane >> 3) & 1) * 8;

    float acc[2][8][4];
#pragma unroll
    for (int i = 0; i < 2; i++)
#pragma unroll
        for (int j = 0; j < 8; j++)
#pragma unroll
            for (int q = 0; q < 4; q++) acc[i][j][q] = 0.f;

    auto issue = [&](int st, int k0) {
        uint32_t sb = s0 + (uint32_t)(st * STG_TOT);
        {   // A: 128 rows x 4 chunks = 512 = 1/thread per array
            int r = tid >> 2, c = tid & 3;
            uint32_t dh = sb + (uint32_t)(r * SROWS + c * 16);
            uint32_t dl = dh + AS_STG;
            if (SHIFT) {
                int k = kOff + k0 + c * 8;
                int j = k >> 8, cc = k & 255;
                int grow = bm + r;
                int tj = (grow & 511) + j - 1;
                if (tj >= 0 && tj < 512) {
                    size_t go = (size_t)(grow + j - 1) * 256 + cc;
                    CP_ASYNC16(dh, Ah + go);
                    CP_ASYNC16(dl, Al + go);
                } else {
                    STS128Z(dh);
                    STS128Z(dl);
                }
            } else {
                size_t go = (size_t)(bm + r) * K + kOff + k0 + c * 8;
                CP_ASYNC16(dh, Ah + go);
                CP_ASYNC16(dl, Al + go);
            }
        }
#pragma unroll
        for (int i = 0; i < 2; i++) {   // B: 256 rows x 4 chunks = 1024 = 2/thread
            int q = i * 512 + tid;
            int r = q >> 2, c = q & 3;
            uint32_t d = sb + (uint32_t)(2 * AS_STG + r * SROWS + c * 16);
            size_t go = (size_t)r * K + kOff + k0 + c * 8;
            CP_ASYNC16(d, Bh + go);
            CP_ASYNC16(d + BS_STG, Bl + go);
        }
    };

    issue(0, 0);
    CP_COMMIT();
    if (nc > 1) { issue(1, BKS); CP_COMMIT(); }

    int st = 0;
    for (int kc = 0; kc < nc; kc++) {
        if (kc + 1 < nc) { CP_WAIT(1); } else { CP_WAIT(0); }
        __syncthreads();     // all threads done reading stage (kc-1) and see stage kc data
        if (kc + 2 < nc) {
            int nst = st + 2; if (nst >= 3) nst -= 3;
            issue(nst, (kc + 2) * BKS);
            CP_COMMIT();
        }
        uint32_t sb = s0 + (uint32_t)(st * STG_TOT);
        uint32_t sAh = sb, sAl = sb + AS_STG;
        uint32_t sBh = sb + 2 * AS_STG, sBl = sBh + BS_STG;
#pragma unroll
        for (int kk = 0; kk < 2; kk++) {
            uint32_t ah[2][4], al[2][4];
#pragma unroll
            for (int mt = 0; mt < 2; mt++) {
                uint32_t ao = (uint32_t)((aRow + mt * 16) * SROWS + (aCol + kk * 16) * 2);
                LDSM_X4(ah[mt][0], ah[mt][1], ah[mt][2], ah[mt][3], sAh + ao);
                LDSM_X4(al[mt][0], al[mt][1], al[mt][2], al[mt][3], sAl + ao);
            }
#pragma unroll
            for (int nt2 = 0; nt2 < 4; nt2++) {
                uint32_t bo = (uint32_t)((bRow + nt2 * 16) * SROWS + (bCol + kk * 16) * 2);
                uint32_t bh[4], bl[4];
                LDSM_X4(bh[0], bh[1], bh[2], bh[3], sBh + bo);
                LDSM_X4(bl[0], bl[1], bl[2], bl[3], sBl + bo);
#pragma unroll
                for (int mt = 0; mt < 2; mt++) {
                    int n0 = nt2 * 2, n1 = n0 + 1;
                    MMA_BF16(acc[mt][n0], ah[mt][0], ah[mt][1], ah[mt][2], ah[mt][3], bh[0], bh[1]);
                    MMA_BF16(acc[mt][n0], ah[mt][0], ah[mt][1], ah[mt][2], ah[mt][3], bl[0], bl[1]);
                    MMA_BF16(acc[mt][n0], al[mt][0], al[mt][1], al[mt][2], al[mt][3], bh[0], bh[1]);
                    MMA_BF16(acc[mt][n1], ah[mt][0], ah[mt][1], ah[mt][2], ah[mt][3], bh[2], bh[3]);
                    MMA_BF16(acc[mt][n1], ah[mt][0], ah[mt][1], ah[mt][2], ah[mt][3], bl[2], bl[3]);
                    MMA_BF16(acc[mt][n1], al[mt][0], al[mt][1], al[mt][2], al[mt][3], bh[2], bh[3]);
                }
            }
        }
        if (++st == 3) st = 0;
    }

    // epilogue: raw fp32 partial
    int rbase = bm + wm * 32 + (lane >> 2);
    int cbase = wn * 64 + (lane & 3) * 2;
#pragma unroll
    for (int mt = 0; mt < 2; mt++) {
#pragma unroll
        for (int nt = 0; nt < 8; nt++) {
            int r = rbase + mt * 16;
            int c = cbase + nt * 8;
            *reinterpret_cast<float2*>(Cf + (size_t)r * 256 + c) =
                make_float2(acc[mt][nt][0], acc[mt][nt][1]);
            *reinterpret_cast<float2*>(Cf + (size_t)(r + 8) * 256 + c) =
                make_float2(acc[mt][nt][2], acc[mt][nt][3]);
        }
    }
}

// ---------------- split-K combine + epilogue ----------------
// EPI: 0 fp32 | 1 selu+bias fp32 | 2 split bf16 | 3 selu+bias split bf16
template <int EPI, int SK>
__global__ void combine_k(const float* __restrict__ part, size_t slice,
                          float* __restrict__ Cf, bf16* __restrict__ Ch, bf16* __restrict__ Cl,
                          const float* __restrict__ bias, int total4) {
    int idx = blockIdx.x * blockDim.x + threadIdx.x;
    if (idx >= total4) return;
    const float4* p4 = reinterpret_cast<const float4*>(part);
    size_t s4 = slice >> 2;
    float4 a = p4[idx];
#pragma unroll
    for (int s = 1; s < SK; s++) {
        float4 b = p4[idx + (size_t)s * s4];
        a.x += b.x; a.y += b.y; a.z += b.z; a.w += b.w;
    }
    float v[4] = {a.x, a.y, a.z, a.w};
    if (EPI == 1 || EPI == 3) {
        int c = (idx * 4) & 255;
        float4 b4 = *reinterpret_cast<const float4*>(bias + c);
        v[0] = selu_f(v[0] + b4.x); v[1] = selu_f(v[1] + b4.y);
        v[2] = selu_f(v[2] + b4.z); v[3] = selu_f(v[3] + b4.w);
    }
    if (EPI >= 2) {
        split_store4(v, Ch + (size_t)idx * 4, Cl + (size_t)idx * 4);
    } else {
        *reinterpret_cast<float4*>(Cf + (size_t)idx * 4) = make_float4(v[0], v[1], v[2], v[3]);
    }
}

// ---------------- pool + pos (+ adj zero, + split) ----------------
__global__ void pool_pos(const float* __restrict__ y2, const float* __restrict__ pos) {
    int idx = blockIdx.x * blockDim.x + threadIdx.x;
    if (idx < BB * NN) g_adj[idx] = 0ull;
    if (idx >= BB * NN * HH) return;
    int c = idx % HH;
    int n = (idx / HH) % NN;
    int b = idx / (HH * NN);
    float s = 0.f;
#pragma unroll
    for (int t = 0; t < 8; t++) s += y2[((size_t)b * TT + n * 8 + t) * HH + c];
    float v = s * 0.125f + pos[(size_t)n * HH + c];
    size_t o = ((size_t)b * NN + n) * HH + c;
    g_hn[o] = v;
    bf16 h, l;
    split_bf16(v, h, l);
    g_hnh[o] = h; g_hnl[o] = l;
}

// ---------------- adjacency ----------------
__global__ void adj_topk() {
    int b = blockIdx.x / NN, n = blockIdx.x % NN;
    __shared__ float sc[NN];
    int m = threadIdx.x;
    const float* hb = g_hn + (size_t)b * NN * HH;
    float s = 0.f;
    for (int k = 0; k < HH; k++) s = fmaf(hb[(size_t)n * HH + k], hb[(size_t)m * HH + k], s);
    sc[m] = s;
    __syncthreads();
    if (m == 0) {
        unsigned long long mask = 1ull << n;
        int sel[TOPK];
#pragma unroll 1
        for (int it = 0; it < TOPK; it++) {
            float best = -INFINITY; int bi = 0;
            for (int j = 0; j < NN; j++)
                if (sc[j] > best) { best = sc[j]; bi = j; }
            sel[it] = bi;
            sc[bi] = -INFINITY;
            mask |= 1ull << bi;
        }
        atomicOr(&g_adj[b * NN + n], mask);
        for (int it = 0; it < TOPK; it++)
            atomicOr(&g_adj[b * NN + sel[it]], 1ull << n);
    }
}

// ---------------- GAT ----------------
__global__ void gat_sd(const float* __restrict__ asrc, const float* __restrict__ adst) {
    int row = blockIdx.x;
    __shared__ float r1[HH], r2[HH];
    int t = threadIdx.x;
    float v = g_hw[(size_t)row * HH + t];
    r1[t] = v * asrc[t];
    r2[t] = v * adst[t];
    __syncthreads();
    for (int st = 128; st > 0; st >>= 1) {
        if (t < st) { r1[t] += r1[t + st]; r2[t] += r2[t + st]; }
        __syncthreads();
    }
    if (t == 0) { g_s[row] = r1[0]; g_d[row] = r2[0]; }
}

__global__ void gat_attn() {
    int b = blockIdx.x / NN, n = blockIdx.x % NN;
    __shared__ float attn[NN];
    __shared__ float inv_s;
    int t = threadIdx.x;
    unsigned long long mask = g_adj[b * NN + n];
    if (t < NN) {
        float e;
        if ((mask >> t) & 1ull) {
            float z = g_s[b * NN + n] + g_d[b * NN + t];
            e = z >= 0.f ? z : 0.2f * z;
        } else {
            e = -1e9f;
        }
        attn[t] = e;
    }
    __syncthreads();
    if (t == 0) {
        float mx = -INFINITY;
        for (int j = 0; j < NN; j++) mx = fmaxf(mx, attn[j]);
        float sum = 0.f;
        for (int j = 0; j < NN; j++) { float ex = expf(attn[j] - mx); attn[j] = ex; sum += ex; }
        inv_s = 1.f / sum;
    }
    __syncthreads();
    float inv = inv_s;
    float acc = 0.f;
    for (int m = 0; m < NN; m++)
        acc = fmaf(attn[m] * inv, g_hw[((size_t)b * NN + m) * HH + t], acc);
    float o = acc > 0.f ? acc : expm1f(acc);
    size_t oo = ((size_t)b * NN + n) * HH + t;
    float nh = g_hn[oo] + o;
    g_hn[oo] = nh;
    bf16 h, l;
    split_bf16(nh, h, l);
    g_hnh[oo] = h; g_hnl[oo] = l;
}

// ---------------- layernorm ----------------
__global__ void layernorm_k(const float* __restrict__ g, const float* __restrict__ bt) {
    int row = blockIdx.x;
    __shared__ float red[HH];
    __shared__ float mu_s, is_s;
    int t = threadIdx.x;
    float v = g_hn[(size_t)row * HH + t];
    red[t] = v;
    __syncthreads();
    for (int st = 128; st > 0; st >>= 1) { if (t < st) red[t] += red[t + st]; __syncthreads(); }
    if (t == 0) mu_s = red[0] * (1.f / HH);
    __syncthreads();
    float mu = mu_s;
    float dv = v - mu;
    red[t] = dv * dv;
    __syncthreads();
    for (int st = 128; st > 0; st >>= 1) { if (t < st) red[t] += red[t + st]; __syncthreads(); }
    if (t == 0) is_s = rsqrtf(red[0] * (1.f / HH) + 1e-5f);
    __syncthreads();
    g_ln[(size_t)row * HH + t] = dv * is_s * g[t] + bt[t];
}

// ---------------- pooling + classifier ----------------
__global__ void pool_emb(float* __restrict__ out) {
    int idx = blockIdx.x * blockDim.x + threadIdx.x;
    if (idx >= BB * HH) return;
    int b = idx / HH, c = idx % HH;
    float sm = 0.f, mx = -INFINITY;
    for (int n = 0; n < NN; n++) {
        float v = g_ln[((size_t)b * NN + n) * HH + c];
        sm += v;
        mx = fmaxf(mx, v);
    }
    out[BB * NCLS + (size_t)b * (2 * HH) + c] = sm * (1.f / NN);
    out[BB * NCLS + (size_t)b * (2 * HH) + HH + c] = mx;
}

__global__ void cls_kan(const float* __restrict__ cbw, const float* __restrict__ csw,
                        const float* __restrict__ csc, float* __restrict__ out) {
    int b = blockIdx.x;
    int t = threadIdx.x;
    __shared__ float r0[256], r1[256];
    float a0 = 0.f, a1 = 0.f;
    const float* emb = out + BB * NCLS + (size_t)b * (2 * HH);
    for (int i = t; i < 2 * HH; i += 256) {
        float x = emb[i];
        float sil = silu_f(x);
        float bs[8];
        bsplines8(x, bs);
        float p0 = sil * cbw[i];
        float p1 = sil * cbw[2 * HH + i];
        float s0 = csc[i], s1 = csc[2 * HH + i];
#pragma unroll
        for (int c = 0; c < 8; c++) {
            p0 = fmaf(bs[c] * csw[(size_t)i * 8 + c], s0, p0);
            p1 = fmaf(bs[c] * csw[(size_t)(2 * HH + i) * 8 + c], s1, p1);
        }
        a0 += p0;
        a1 += p1;
    }
    r0[t] = a0; r1[t] = a1;
    __syncthreads();
    for (int st = 128; st > 0; st >>= 1) {
        if (t < st) { r0[t] += r0[t + st]; r1[t] += r1[t + st]; }
        __syncthreads();
    }
    if (t == 0) { out[b * NCLS + 0] = r0[0]; out[b * NCLS + 1] = r1[0]; }
}

// ---------------- host launch ----------------
extern "C" void kernel_launch(void* const* d_in, const int* in_sizes, int n_in,
                              void* d_out, int out_size) {
    const float* x    = (const float*)d_in[0];
    const float* bbw  = (const float*)d_in[1];
    const float* bsw  = (const float*)d_in[2];
    const float* bsc  = (const float*)d_in[3];
    const float* c1w  = (const float*)d_in[4];
    const float* c1b  = (const float*)d_in[5];
    const float* c2w  = (const float*)d_in[6];
    const float* c2b  = (const float*)d_in[7];
    const float* pos  = (const float*)d_in[8];
    const float* gatW = (const float*)d_in[9];
    const float* asrc = (const float*)d_in[10];
    const float* adst = (const float*)d_in[11];
    const float* lng  = (const float*)d_in[12];
    const float* lnb  = (const float*)d_in[13];
    const float* cbw  = (const float*)d_in[14];
    const float* csw  = (const float*)d_in[15];
    const float* csc  = (const float*)d_in[16];
    float* out = (float*)d_out;

    bf16 *pfh, *pfl, *pwh, *pwl, *ph1h, *ph1l, *pwc1h, *pwc1l, *pwc2h, *pwc2l;
    bf16 *py1h, *py1l, *phnh, *phnl, *pwt0h, *pwt0l, *pwt1h, *pwt1l;
    float *py2, *phw, *ppart;
    cudaGetSymbolAddress((void**)&pfh, g_fh);
    cudaGetSymbolAddress((void**)&pfl, g_fl);
    cudaGetSymbolAddress((void**)&pwh, g_wh);
    cudaGetSymbolAddress((void**)&pwl, g_wl);
    cudaGetSymbolAddress((void**)&ph1h, g_h1h);
    cudaGetSymbolAddress((void**)&ph1l, g_h1l);
    cudaGetSymbolAddress((void**)&pwc1h, g_wc1h);
    cudaGetSymbolAddress((void**)&pwc1l, g_wc1l);
    cudaGetSymbolAddress((void**)&pwc2h, g_wc2h);
    cudaGetSymbolAddress((void**)&pwc2l, g_wc2l);
    cudaGetSymbolAddress((void**)&py1h, g_y1h);
    cudaGetSymbolAddress((void**)&py1l, g_y1l);
    cudaGetSymbolAddress((void**)&phnh, g_hnh);
    cudaGetSymbolAddress((void**)&phnl, g_hnl);
    cudaGetSymbolAddress((void**)&pwt0h, g_wt0h);
    cudaGetSymbolAddress((void**)&pwt0l, g_wt0l);
    cudaGetSymbolAddress((void**)&pwt1h, g_wt1h);
    cudaGetSymbolAddress((void**)&pwt1l, g_wt1l);
    cudaGetSymbolAddress((void**)&py2, g_y2);
    cudaGetSymbolAddress((void**)&phw, g_hw);
    cudaGetSymbolAddress((void**)&ppart, g_part);

    cudaFuncSetAttribute(gemm_mma<0>, cudaFuncAttributeMaxDynamicSharedMemorySize, GEMM_SMEM);
    cudaFuncSetAttribute(gemm_mma<1>, cudaFuncAttributeMaxDynamicSharedMemorySize, GEMM_SMEM);

    const int TPB = 256;
    const size_t SLICE_BIG = (size_t)MROWS * HH;
    const size_t SLICE_SMALL = (size_t)NROWS * HH;
    const int T4_BIG = MROWS * HH / 4;
    const int T4_SMALL = NROWS * HH / 4;

    // prep
    bridge_features_bf16<<<MROWS * (DIN / 4) / TPB, TPB>>>(x);
    build_wcat_bf16<<<(HH * DIN + TPB - 1) / TPB, TPB>>>(bbw, bsw, bsc);
    conv_w_bf16<<<(HH * HH + TPB - 1) / TPB, TPB>>>(c1w, pwc1h, pwc1l);
    conv_w_bf16<<<(HH * HH + TPB - 1) / TPB, TPB>>>(c2w, pwc2h, pwc2l);
    gatwt_bf16<<<(HH * HH + TPB - 1) / TPB, TPB>>>(gatW, pwt0h, pwt0l);

    // bridge GEMM: split-K 2 (wave-equivalent, half the partial traffic)
    gemm_mma<0><<<dim3(MROWS / 128, 2), 512, GEMM_SMEM>>>(pfh, pfl, pwh, pwl,
                                                          ppart, KBRIDGE, KBRIDGE / 2);
    combine_k<2, 2><<<(T4_BIG + TPB - 1) / TPB, TPB>>>(ppart, SLICE_BIG,
                                                       nullptr, ph1h, ph1l, nullptr, T4_BIG);

    // conv1: split-K 2 + combine -> selu+bias split bf16
    gemm_mma<1><<<dim3(MROWS / 128, 2), 512, GEMM_SMEM>>>(ph1h, ph1l, pwc1h, pwc1l,
                                                          ppart, KCONV, KCONV / 2);
    combine_k<3, 2><<<(T4_BIG + TPB - 1) / TPB, TPB>>>(ppart, SLICE_BIG,
                                                       nullptr, py1h, py1l, c1b, T4_BIG);

    // conv2: split-K 2 + combine -> selu+bias fp32
    gemm_mma<1><<<dim3(MROWS / 128, 2), 512, GEMM_SMEM>>>(py1h, py1l, pwc2h, pwc2l,
                                                          ppart, KCONV, KCONV / 2);
    combine_k<1, 2><<<(T4_BIG + TPB - 1) / TPB, TPB>>>(ppart, SLICE_BIG,
                                                       py2, nullptr, nullptr, c2b, T4_BIG);

    // pool + pos (+ adj zero + split)
    pool_pos<<<(BB * NN * HH + TPB - 1) / TPB, TPB>>>(py2, pos);

    // adjacency
    adj_topk<<<BB * NN, NN>>>();

    // GAT layer 0: split-K 4 + combine -> fp32
    gemm_mma<0><<<dim3(NROWS / 128, 4), 512, GEMM_SMEM>>>(phnh, phnl, pwt0h, pwt0l,
                                                          ppart, HH, HH / 4);
    combine_k<0, 4><<<(T4_SMALL + TPB - 1) / TPB, TPB>>>(ppart, SLICE_SMALL,
                                                         phw, nullptr, nullptr, nullptr, T4_SMALL);
    gat_sd<<<NROWS, HH>>>(asrc, adst);
    gat_attn<<<NROWS, HH>>>();

    // GAT layer 1
    gatwt_bf16<<<(HH * HH + TPB - 1) / TPB, TPB>>>(gatW + (size_t)HH * HH, pwt1h, pwt1l);
    gemm_mma<0><<<dim3(NROWS / 128, 4), 512, GEMM_SMEM>>>(phnh, phnl, pwt1h, pwt1l,
                                                          ppart, HH, HH / 4);
    combine_k<0, 4><<<(T4_SMALL + TPB - 1) / TPB, TPB>>>(ppart, SLICE_SMALL,
                                                         phw, nullptr, nullptr, nullptr, T4_SMALL);
    gat_sd<<<NROWS, HH>>>(asrc + HH, adst + HH);
    gat_attn<<<NROWS, HH>>>();

    // layernorm + pooling + classifier
    layernorm_k<<<NROWS, HH>>>(lng, lnb);
    pool_emb<<<(BB * HH + TPB - 1) / TPB, TPB>>>(out);
    cls_kan<<<BB, 256>>>(cbw, csw, csc, out);
}

// round 10
// speedup vs baseline: 1.1063x; 1.0055x over previous
#include <cuda_runtime.h>
#include <cuda_bf16.h>
#include <math.h>
#include <stdint.h>

typedef __nv_bfloat16 bf16;

// ---------------- problem constants ----------------
#define BB 16
#define TT 512
#define DIN 1024
#define HH 256
#define NN 64
#define TOPK 8
#define NCLS 2
#define KBRIDGE (DIN * 9)      // 9216
#define KCONV (HH * 3)         // 768
#define MROWS (BB * TT)        // 8192
#define NROWS (BB * NN)        // 1024

// ---------------- PTX helpers ----------------
__device__ __forceinline__ uint32_t smem_u32(const void* p) {
    uint32_t a;
    asm("{ .reg .u64 t; cvta.to.shared.u64 t, %1; cvt.u32.u64 %0, t; }" : "=r"(a) : "l"(p));
    return a;
}
#define CP_ASYNC16(dst, src) \
    asm volatile("cp.async.cg.shared.global [%0], [%1], 16;" :: "r"(dst), "l"(src) : "memory")
#define CP_COMMIT() asm volatile("cp.async.commit_group;" ::: "memory")
#define CP_WAIT(N)  asm volatile("cp.async.wait_group %0;" :: "n"(N) : "memory")
#define LDSM_X4(r0, r1, r2, r3, a) \
    asm volatile("ldmatrix.sync.aligned.m8n8.x4.shared.b16 {%0,%1,%2,%3}, [%4];" \
        : "=r"(r0), "=r"(r1), "=r"(r2), "=r"(r3) : "r"(a))
#define MMA_BF16(c, a0, a1, a2, a3, b0, b1) \
    asm volatile("mma.sync.aligned.m16n8k16.row.col.f32.bf16.bf16.f32 " \
        "{%0,%1,%2,%3}, {%4,%5,%6,%7}, {%8,%9}, {%0,%1,%2,%3};" \
        : "+f"((c)[0]), "+f"((c)[1]), "+f"((c)[2]), "+f"((c)[3]) \
        : "r"(a0), "r"(a1), "r"(a2), "r"(a3), "r"(b0), "r"(b1))
#define STS128Z(addr) \
    asm volatile("st.shared.v4.b32 [%0], {%1,%1,%1,%1};" :: "r"(addr), "r"(0u) : "memory")

// ---------------- scratch ----------------
__device__ bf16 g_fh[(size_t)MROWS * KBRIDGE];
__device__ bf16 g_fl[(size_t)MROWS * KBRIDGE];
__device__ bf16 g_wh[HH * KBRIDGE];
__device__ bf16 g_wl[HH * KBRIDGE];
__device__ float g_part[(size_t)4 * MROWS * HH];   // split-K partials
__device__ bf16 g_h1h[MROWS * HH];
__device__ bf16 g_h1l[MROWS * HH];
__device__ bf16 g_wc1h[HH * KCONV];
__device__ bf16 g_wc1l[HH * KCONV];
__device__ bf16 g_wc2h[HH * KCONV];
__device__ bf16 g_wc2l[HH * KCONV];
__device__ bf16 g_y1h[MROWS * HH];
__device__ bf16 g_y1l[MROWS * HH];
__device__ float g_y2[MROWS * HH];
__device__ float g_hn[NROWS * HH];
__device__ bf16 g_hnh[NROWS * HH];
__device__ bf16 g_hnl[NROWS * HH];
__device__ bf16 g_wt0h[HH * HH];
__device__ bf16 g_wt0l[HH * HH];
__device__ bf16 g_wt1h[HH * HH];
__device__ bf16 g_wt1l[HH * HH];
__device__ float g_hw[NROWS * HH];
__device__ float g_s[NROWS];
__device__ float g_d[NROWS];
__device__ unsigned long long g_adj[BB * NN];
__device__ float g_ln[NROWS * HH];

// ---------------- math helpers ----------------
__device__ __forceinline__ float silu_f(float x) { return x * (1.f / (1.f + expf(-x))); }
__device__ __forceinline__ float selu_f(float x) {
    const float a = 1.6732632423543772f, s = 1.0507009873554805f;
    return x > 0.f ? s * x : s * a * expm1f(x);
}
__device__ __forceinline__ void split_bf16(float v, bf16& h, bf16& l) {
    h = __float2bfloat16_rn(v);
    l = __float2bfloat16_rn(v - __bfloat162float(h));
}
union Pack4 { bf16 b[4]; uint2 u; };
__device__ __forceinline__ void split_store4(const float* v, bf16* ph, bf16* pl) {
    Pack4 H, L;
#pragma unroll
    for (int j = 0; j < 4; j++) split_bf16(v[j], H.b[j], L.b[j]);
    *reinterpret_cast<uint2*>(ph) = H.u;
    *reinterpret_cast<uint2*>(pl) = L.u;
}
__device__ __forceinline__ void bsplines8(float x, float* out) {
    const float h = 0.4f;
    float b[11];
#pragma unroll
    for (int j = 0; j < 11; j++) {
        float gj = (float)(j - 3) * h - 1.0f;
        float gj1 = (float)(j - 2) * h - 1.0f;
        b[j] = (x >= gj && x < gj1) ? 1.f : 0.f;
    }
#pragma unroll
    for (int k = 1; k <= 3; k++) {
        float inv = 1.f / ((float)k * h);
#pragma unroll
        for (int j = 0; j < 11; j++) {
            if (j < 11 - k) {
                float gj = (float)(j - 3) * h - 1.0f;
                float gjk1 = (float)(j + k - 2) * h - 1.0f;
                b[j] = (x - gj) * inv * b[j] + (gjk1 - x) * inv * b[j + 1];
            }
        }
    }
#pragma unroll
    for (int j = 0; j < 8; j++) out[j] = b[j];
}

// ---------------- prep kernels ----------------
__global__ void bridge_features_bf16(const float* __restrict__ x) {
    int idx = blockIdx.x * blockDim.x + threadIdx.x;
    if (idx >= MROWS * (DIN / 4)) return;
    int r = idx >> 8, i4 = idx & 255;
    float4 xv = *reinterpret_cast<const float4*>(x + (size_t)r * DIN + i4 * 4);
    float vv[4] = {xv.x, xv.y, xv.z, xv.w};
    float f[9][4];
#pragma unroll
    for (int j = 0; j < 4; j++) {
        f[0][j] = silu_f(vv[j]);
        float bs[8];
        bsplines8(vv[j], bs);
#pragma unroll
        for (int c = 0; c < 8; c++) f[c + 1][j] = bs[c];
    }
    size_t base = (size_t)r * KBRIDGE + i4 * 4;
#pragma unroll
    for (int g = 0; g < 9; g++)
        split_store4(f[g], g_fh + base + (size_t)g * DIN, g_fl + base + (size_t)g * DIN);
}

__global__ void build_wcat_bf16(const float* __restrict__ bw, const float* __restrict__ sw,
                                const float* __restrict__ sc) {
    int idx = blockIdx.x * blockDim.x + threadIdx.x;
    if (idx >= HH * DIN) return;
    int i = idx % DIN, o = idx / DIN;
    size_t base = (size_t)o * KBRIDGE + i;
    bf16 h, l;
    split_bf16(bw[idx], h, l);
    g_wh[base] = h; g_wl[base] = l;
    float scale = sc[idx];
#pragma unroll
    for (int c = 0; c < 8; c++) {
        split_bf16(sw[(size_t)idx * 8 + c] * scale, h, l);
        size_t p = base + (size_t)(c + 1) * DIN;
        g_wh[p] = h; g_wl[p] = l;
    }
}

__global__ void conv_w_bf16(const float* __restrict__ w, bf16* __restrict__ wh, bf16* __restrict__ wl) {
    int idx = blockIdx.x * blockDim.x + threadIdx.x;
    if (idx >= HH * HH) return;
    int i = idx % HH, o = idx / HH;
#pragma unroll
    for (int j = 0; j < 3; j++) {
        bf16 h, l;
        split_bf16(w[((size_t)o * HH + i) * 3 + j], h, l);
        size_t p = (size_t)o * KCONV + j * HH + i;
        wh[p] = h; wl[p] = l;
    }
}

__global__ void gatwt_bf16(const float* __restrict__ w, bf16* __restrict__ wh, bf16* __restrict__ wl) {
    int idx = blockIdx.x * blockDim.x + threadIdx.x;
    if (idx >= HH * HH) return;
    int k = idx % HH, n = idx / HH;
    bf16 h, l;
    split_bf16(w[(size_t)k * HH + n], h, l);
    wh[idx] = h; wl[idx] = l;
}

// ===== split-bf16 split-K GEMM: 512 thr, warp tile 32x64, 3-stage, 1 barrier/chunk =====
// Tile 128(M) x 256(N), BK=32. Grid (M/128, SPLITK).
// MMA issue is product-major within each nt2 so same-accumulator reuse distance is 4
// (was 1 -> chained HMMA RAW stalls).
#define BKS 32
#define SROWS 80
#define AS_STG (128 * SROWS)      // 10240 (one array)
#define BS_STG (256 * SROWS)      // 20480
#define STG_TOT (2 * AS_STG + 2 * BS_STG)     // 61440 per stage (Ah,Al,Bh,Bl)
#define GEMM_SMEM (3 * STG_TOT)               // 184320

template <int SHIFT>
__global__ __launch_bounds__(512, 1) void gemm_mma(
    const bf16* __restrict__ Ah, const bf16* __restrict__ Al,
    const bf16* __restrict__ Bh, const bf16* __restrict__ Bl,
    float* __restrict__ Cpart, int K, int kLen) {
    extern __shared__ char smem[];
    uint32_t s0 = smem_u32(smem);

    int tid = threadIdx.x, lane = tid & 31, wid = tid >> 5;
    int wm = wid & 3, wn = wid >> 2;      // 4 x 4 warp grid, warp tile 32x64
    int bm = blockIdx.x * 128;
    int kOff = blockIdx.y * kLen;
    float* Cf = Cpart + (size_t)blockIdx.y * gridDim.x * 128 * 256;
    const int nc = kLen / BKS;

    int aRow = wm * 32 + (lane & 15);
    int aCol = (lane >> 4) * 8;
    int bRow = wn * 64 + (lane & 7) + ((lane >> 4) << 3);
    int bCol = ((lane >> 3) & 1) * 8;

    float acc[2][8][4];
#pragma unroll
    for (int i = 0; i < 2; i++)
#pragma unroll
        for (int j = 0; j < 8; j++)
#pragma unroll
            for (int q = 0; q < 4; q++) acc[i][j][q] = 0.f;

    auto issue = [&](int st, int k0) {
        uint32_t sb = s0 + (uint32_t)(st * STG_TOT);
        {   // A: 128 rows x 4 chunks = 512 = 1/thread per array
            int r = tid >> 2, c = tid & 3;
            uint32_t dh = sb + (uint32_t)(r * SROWS + c * 16);
            uint32_t dl = dh + AS_STG;
            if (SHIFT) {
                int k = kOff + k0 + c * 8;
                int j = k >> 8, cc = k & 255;
                int grow = bm + r;
                int tj = (grow & 511) + j - 1;
                if (tj >= 0 && tj < 512) {
                    size_t go = (size_t)(grow + j - 1) * 256 + cc;
                    CP_ASYNC16(dh, Ah + go);
                    CP_ASYNC16(dl, Al + go);
                } else {
                    STS128Z(dh);
                    STS128Z(dl);
                }
            } else {
                size_t go = (size_t)(bm + r) * K + kOff + k0 + c * 8;
                CP_ASYNC16(dh, Ah + go);
                CP_ASYNC16(dl, Al + go);
            }
        }
#pragma unroll
        for (int i = 0; i < 2; i++) {   // B: 256 rows x 4 chunks = 1024 = 2/thread
            int q = i * 512 + tid;
            int r = q >> 2, c = q & 3;
            uint32_t d = sb + (uint32_t)(2 * AS_STG + r * SROWS + c * 16);
            size_t go = (size_t)r * K + kOff + k0 + c * 8;
            CP_ASYNC16(d, Bh + go);
            CP_ASYNC16(d + BS_STG, Bl + go);
        }
    };

    issue(0, 0);
    CP_COMMIT();
    if (nc > 1) { issue(1, BKS); CP_COMMIT(); }

    int st = 0;
    for (int kc = 0; kc < nc; kc++) {
        if (kc + 1 < nc) { CP_WAIT(1); } else { CP_WAIT(0); }
        __syncthreads();
        if (kc + 2 < nc) {
            int nst = st + 2; if (nst >= 3) nst -= 3;
            issue(nst, (kc + 2) * BKS);
            CP_COMMIT();
        }
        uint32_t sb = s0 + (uint32_t)(st * STG_TOT);
        uint32_t sAh = sb, sAl = sb + AS_STG;
        uint32_t sBh = sb + 2 * AS_STG, sBl = sBh + BS_STG;
#pragma unroll
        for (int kk = 0; kk < 2; kk++) {
            uint32_t ah[2][4], al[2][4];
#pragma unroll
            for (int mt = 0; mt < 2; mt++) {
                uint32_t ao = (uint32_t)((aRow + mt * 16) * SROWS + (aCol + kk * 16) * 2);
                LDSM_X4(ah[mt][0], ah[mt][1], ah[mt][2], ah[mt][3], sAh + ao);
                LDSM_X4(al[mt][0], al[mt][1], al[mt][2], al[mt][3], sAl + ao);
            }
#pragma unroll
            for (int nt2 = 0; nt2 < 4; nt2++) {
                uint32_t bo = (uint32_t)((bRow + nt2 * 16) * SROWS + (bCol + kk * 16) * 2);
                uint32_t bh[4], bl[4];
                LDSM_X4(bh[0], bh[1], bh[2], bh[3], sBh + bo);
                LDSM_X4(bl[0], bl[1], bl[2], bl[3], sBl + bo);
                int n0 = nt2 * 2, n1 = n0 + 1;
                // product-major: same-acc reuse distance = 4
                MMA_BF16(acc[0][n0], ah[0][0], ah[0][1], ah[0][2], ah[0][3], bh[0], bh[1]);
                MMA_BF16(acc[0][n1], ah[0][0], ah[0][1], ah[0][2], ah[0][3], bh[2], bh[3]);
                MMA_BF16(acc[1][n0], ah[1][0], ah[1][1], ah[1][2], ah[1][3], bh[0], bh[1]);
                MMA_BF16(acc[1][n1], ah[1][0], ah[1][1], ah[1][2], ah[1][3], bh[2], bh[3]);
                MMA_BF16(acc[0][n0], ah[0][0], ah[0][1], ah[0][2], ah[0][3], bl[0], bl[1]);
                MMA_BF16(acc[0][n1], ah[0][0], ah[0][1], ah[0][2], ah[0][3], bl[2], bl[3]);
                MMA_BF16(acc[1][n0], ah[1][0], ah[1][1], ah[1][2], ah[1][3], bl[0], bl[1]);
                MMA_BF16(acc[1][n1], ah[1][0], ah[1][1], ah[1][2], ah[1][3], bl[2], bl[3]);
                MMA_BF16(acc[0][n0], al[0][0], al[0][1], al[0][2], al[0][3], bh[0], bh[1]);
                MMA_BF16(acc[0][n1], al[0][0], al[0][1], al[0][2], al[0][3], bh[2], bh[3]);
                MMA_BF16(acc[1][n0], al[1][0], al[1][1], al[1][2], al[1][3], bh[0], bh[1]);
                MMA_BF16(acc[1][n1], al[1][0], al[1][1], al[1][2], al[1][3], bh[2], bh[3]);
            }
        }
        if (++st == 3) st = 0;
    }

    // epilogue: raw fp32 partial
    int rbase = bm + wm * 32 + (lane >> 2);
    int cbase = wn * 64 + (lane & 3) * 2;
#pragma unroll
    for (int mt = 0; mt < 2; mt++) {
#pragma unroll
        for (int nt = 0; nt < 8; nt++) {
            int r = rbase + mt * 16;
            int c = cbase + nt * 8;
            *reinterpret_cast<float2*>(Cf + (size_t)r * 256 + c) =
                make_float2(acc[mt][nt][0], acc[mt][nt][1]);
            *reinterpret_cast<float2*>(Cf + (size_t)(r + 8) * 256 + c) =
                make_float2(acc[mt][nt][2], acc[mt][nt][3]);
        }
    }
}

// ---------------- split-K combine + epilogue ----------------
template <int EPI, int SK>
__global__ void combine_k(const float* __restrict__ part, size_t slice,
                          float* __restrict__ Cf, bf16* __restrict__ Ch, bf16* __restrict__ Cl,
                          const float* __restrict__ bias, int total4) {
    int idx = blockIdx.x * blockDim.x + threadIdx.x;
    if (idx >= total4) return;
    const float4* p4 = reinterpret_cast<const float4*>(part);
    size_t s4 = slice >> 2;
    float4 a = p4[idx];
#pragma unroll
    for (int s = 1; s < SK; s++) {
        float4 b = p4[idx + (size_t)s * s4];
        a.x += b.x; a.y += b.y; a.z += b.z; a.w += b.w;
    }
    float v[4] = {a.x, a.y, a.z, a.w};
    if (EPI == 1 || EPI == 3) {
        int c = (idx * 4) & 255;
        float4 b4 = *reinterpret_cast<const float4*>(bias + c);
        v[0] = selu_f(v[0] + b4.x); v[1] = selu_f(v[1] + b4.y);
        v[2] = selu_f(v[2] + b4.z); v[3] = selu_f(v[3] + b4.w);
    }
    if (EPI >= 2) {
        split_store4(v, Ch + (size_t)idx * 4, Cl + (size_t)idx * 4);
    } else {
        *reinterpret_cast<float4*>(Cf + (size_t)idx * 4) = make_float4(v[0], v[1], v[2], v[3]);
    }
}

// ---------------- pool + pos (+ adj zero, + split) ----------------
__global__ void pool_pos(const float* __restrict__ y2, const float* __restrict__ pos) {
    int idx = blockIdx.x * blockDim.x + threadIdx.x;
    if (idx < BB * NN) g_adj[idx] = 0ull;
    if (idx >= BB * NN * HH) return;
    int c = idx % HH;
    int n = (idx / HH) % NN;
    int b = idx / (HH * NN);
    float s = 0.f;
#pragma unroll
    for (int t = 0; t < 8; t++) s += y2[((size_t)b * TT + n * 8 + t) * HH + c];
    float v = s * 0.125f + pos[(size_t)n * HH + c];
    size_t o = ((size_t)b * NN + n) * HH + c;
    g_hn[o] = v;
    bf16 h, l;
    split_bf16(v, h, l);
    g_hnh[o] = h; g_hnl[o] = l;
}

// ---------------- adjacency ----------------
__global__ void adj_topk() {
    int b = blockIdx.x / NN, n = blockIdx.x % NN;
    __shared__ float sc[NN];
    int m = threadIdx.x;
    const float* hb = g_hn + (size_t)b * NN * HH;
    float s = 0.f;
    for (int k = 0; k < HH; k++) s = fmaf(hb[(size_t)n * HH + k], hb[(size_t)m * HH + k], s);
    sc[m] = s;
    __syncthreads();
    if (m == 0) {
        unsigned long long mask = 1ull << n;
        int sel[TOPK];
#pragma unroll 1
        for (int it = 0; it < TOPK; it++) {
            float best = -INFINITY; int bi = 0;
            for (int j = 0; j < NN; j++)
                if (sc[j] > best) { best = sc[j]; bi = j; }
            sel[it] = bi;
            sc[bi] = -INFINITY;
            mask |= 1ull << bi;
        }
        atomicOr(&g_adj[b * NN + n], mask);
        for (int it = 0; it < TOPK; it++)
            atomicOr(&g_adj[b * NN + sel[it]], 1ull << n);
    }
}

// ---------------- GAT ----------------
__global__ void gat_sd(const float* __restrict__ asrc, const float* __restrict__ adst) {
    int row = blockIdx.x;
    __shared__ float r1[HH], r2[HH];
    int t = threadIdx.x;
    float v = g_hw[(size_t)row * HH + t];
    r1[t] = v * asrc[t];
    r2[t] = v * adst[t];
    __syncthreads();
    for (int st = 128; st > 0; st >>= 1) {
        if (t < st) { r1[t] += r1[t + st]; r2[t] += r2[t + st]; }
        __syncthreads();
    }
    if (t == 0) { g_s[row] = r1[0]; g_d[row] = r2[0]; }
}

__global__ void gat_attn() {
    int b = blockIdx.x / NN, n = blockIdx.x % NN;
    __shared__ float attn[NN];
    __shared__ float inv_s;
    int t = threadIdx.x;
    unsigned long long mask = g_adj[b * NN + n];
    if (t < NN) {
        float e;
        if ((mask >> t) & 1ull) {
            float z = g_s[b * NN + n] + g_d[b * NN + t];
            e = z >= 0.f ? z : 0.2f * z;
        } else {
            e = -1e9f;
        }
        attn[t] = e;
    }
    __syncthreads();
    if (t == 0) {
        float mx = -INFINITY;
        for (int j = 0; j < NN; j++) mx = fmaxf(mx, attn[j]);
        float sum = 0.f;
        for (int j = 0; j < NN; j++) { float ex = expf(attn[j] - mx); attn[j] = ex; sum += ex; }
        inv_s = 1.f / sum;
    }
    __syncthreads();
    float inv = inv_s;
    float acc = 0.f;
    for (int m = 0; m < NN; m++)
        acc = fmaf(attn[m] * inv, g_hw[((size_t)b * NN + m) * HH + t], acc);
    float o = acc > 0.f ? acc : expm1f(acc);
    size_t oo = ((size_t)b * NN + n) * HH + t;
    float nh = g_hn[oo] + o;
    g_hn[oo] = nh;
    bf16 h, l;
    split_bf16(nh, h, l);
    g_hnh[oo] = h; g_hnl[oo] = l;
}

// ---------------- layernorm ----------------
__global__ void layernorm_k(const float* __restrict__ g, const float* __restrict__ bt) {
    int row = blockIdx.x;
    __shared__ float red[HH];
    __shared__ float mu_s, is_s;
    int t = threadIdx.x;
    float v = g_hn[(size_t)row * HH + t];
    red[t] = v;
    __syncthreads();
    for (int st = 128; st > 0; st >>= 1) { if (t < st) red[t] += red[t + st]; __syncthreads(); }
    if (t == 0) mu_s = red[0] * (1.f / HH);
    __syncthreads();
    float mu = mu_s;
    float dv = v - mu;
    red[t] = dv * dv;
    __syncthreads();
    for (int st = 128; st > 0; st >>= 1) { if (t < st) red[t] += red[t + st]; __syncthreads(); }
    if (t == 0) is_s = rsqrtf(red[0] * (1.f / HH) + 1e-5f);
    __syncthreads();
    g_ln[(size_t)row * HH + t] = dv * is_s * g[t] + bt[t];
}

// ---------------- pooling + classifier ----------------
__global__ void pool_emb(float* __restrict__ out) {
    int idx = blockIdx.x * blockDim.x + threadIdx.x;
    if (idx >= BB * HH) return;
    int b = idx / HH, c = idx % HH;
    float sm = 0.f, mx = -INFINITY;
    for (int n = 0; n < NN; n++) {
        float v = g_ln[((size_t)b * NN + n) * HH + c];
        sm += v;
        mx = fmaxf(mx, v);
    }
    out[BB * NCLS + (size_t)b * (2 * HH) + c] = sm * (1.f / NN);
    out[BB * NCLS + (size_t)b * (2 * HH) + HH + c] = mx;
}

__global__ void cls_kan(const float* __restrict__ cbw, const float* __restrict__ csw,
                        const float* __restrict__ csc, float* __restrict__ out) {
    int b = blockIdx.x;
    int t = threadIdx.x;
    __shared__ float r0[256], r1[256];
    float a0 = 0.f, a1 = 0.f;
    const float* emb = out + BB * NCLS + (size_t)b * (2 * HH);
    for (int i = t; i < 2 * HH; i += 256) {
        float x = emb[i];
        float sil = silu_f(x);
        float bs[8];
        bsplines8(x, bs);
        float p0 = sil * cbw[i];
        float p1 = sil * cbw[2 * HH + i];
        float s0 = csc[i], s1 = csc[2 * HH + i];
#pragma unroll
        for (int c = 0; c < 8; c++) {
            p0 = fmaf(bs[c] * csw[(size_t)i * 8 + c], s0, p0);
            p1 = fmaf(bs[c] * csw[(size_t)(2 * HH + i) * 8 + c], s1, p1);
        }
        a0 += p0;
        a1 += p1;
    }
    r0[t] = a0; r1[t] = a1;
    __syncthreads();
    for (int st = 128; st > 0; st >>= 1) {
        if (t < st) { r0[t] += r0[t + st]; r1[t] += r1[t + st]; }
        __syncthreads();
    }
    if (t == 0) { out[b * NCLS + 0] = r0[0]; out[b * NCLS + 1] = r1[0]; }
}

// ---------------- host launch ----------------
extern "C" void kernel_launch(void* const* d_in, const int* in_sizes, int n_in,
                              void* d_out, int out_size) {
    const float* x    = (const float*)d_in[0];
    const float* bbw  = (const float*)d_in[1];
    const float* bsw  = (const float*)d_in[2];
    const float* bsc  = (const float*)d_in[3];
    const float* c1w  = (const float*)d_in[4];
    const float* c1b  = (const float*)d_in[5];
    const float* c2w  = (const float*)d_in[6];
    const float* c2b  = (const float*)d_in[7];
    const float* pos  = (const float*)d_in[8];
    const float* gatW = (const float*)d_in[9];
    const float* asrc = (const float*)d_in[10];
    const float* adst = (const float*)d_in[11];
    const float* lng  = (const float*)d_in[12];
    const float* lnb  = (const float*)d_in[13];
    const float* cbw  = (const float*)d_in[14];
    const float* csw  = (const float*)d_in[15];
    const float* csc  = (const float*)d_in[16];
    float* out = (float*)d_out;

    bf16 *pfh, *pfl, *pwh, *pwl, *ph1h, *ph1l, *pwc1h, *pwc1l, *pwc2h, *pwc2l;
    bf16 *py1h, *py1l, *phnh, *phnl, *pwt0h, *pwt0l, *pwt1h, *pwt1l;
    float *py2, *phw, *ppart;
    cudaGetSymbolAddress((void**)&pfh, g_fh);
    cudaGetSymbolAddress((void**)&pfl, g_fl);
    cudaGetSymbolAddress((void**)&pwh, g_wh);
    cudaGetSymbolAddress((void**)&pwl, g_wl);
    cudaGetSymbolAddress((void**)&ph1h, g_h1h);
    cudaGetSymbolAddress((void**)&ph1l, g_h1l);
    cudaGetSymbolAddress((void**)&pwc1h, g_wc1h);
    cudaGetSymbolAddress((void**)&pwc1l, g_wc1l);
    cudaGetSymbolAddress((void**)&pwc2h, g_wc2h);
    cudaGetSymbolAddress((void**)&pwc2l, g_wc2l);
    cudaGetSymbolAddress((void**)&py1h, g_y1h);
    cudaGetSymbolAddress((void**)&py1l, g_y1l);
    cudaGetSymbolAddress((void**)&phnh, g_hnh);
    cudaGetSymbolAddress((void**)&phnl, g_hnl);
    cudaGetSymbolAddress((void**)&pwt0h, g_wt0h);
    cudaGetSymbolAddress((void**)&pwt0l, g_wt0l);
    cudaGetSymbolAddress((void**)&pwt1h, g_wt1h);
    cudaGetSymbolAddress((void**)&pwt1l, g_wt1l);
    cudaGetSymbolAddress((void**)&py2, g_y2);
    cudaGetSymbolAddress((void**)&phw, g_hw);
    cudaGetSymbolAddress((void**)&ppart, g_part);

    cudaFuncSetAttribute(gemm_mma<0>, cudaFuncAttributeMaxDynamicSharedMemorySize, GEMM_SMEM);
    cudaFuncSetAttribute(gemm_mma<1>, cudaFuncAttributeMaxDynamicSharedMemorySize, GEMM_SMEM);

    const int TPB = 256;
    const size_t SLICE_BIG = (size_t)MROWS * HH;
    const size_t SLICE_SMALL = (size_t)NROWS * HH;
    const int T4_BIG = MROWS * HH / 4;
    const int T4_SMALL = NROWS * HH / 4;

    // prep
    bridge_features_bf16<<<MROWS * (DIN / 4) / TPB, TPB>>>(x);
    build_wcat_bf16<<<(HH * DIN + TPB - 1) / TPB, TPB>>>(bbw, bsw, bsc);
    conv_w_bf16<<<(HH * HH + TPB - 1) / TPB, TPB>>>(c1w, pwc1h, pwc1l);
    conv_w_bf16<<<(HH * HH + TPB - 1) / TPB, TPB>>>(c2w, pwc2h, pwc2l);
    gatwt_bf16<<<(HH * HH + TPB - 1) / TPB, TPB>>>(gatW, pwt0h, pwt0l);

    // bridge GEMM: split-K 2 + combine -> split bf16
    gemm_mma<0><<<dim3(MROWS / 128, 2), 512, GEMM_SMEM>>>(pfh, pfl, pwh, pwl,
                                                          ppart, KBRIDGE, KBRIDGE / 2);
    combine_k<2, 2><<<(T4_BIG + TPB - 1) / TPB, TPB>>>(ppart, SLICE_BIG,
                                                       nullptr, ph1h, ph1l, nullptr, T4_BIG);

    // conv1: split-K 2 + combine -> selu+bias split bf16
    gemm_mma<1><<<dim3(MROWS / 128, 2), 512, GEMM_SMEM>>>(ph1h, ph1l, pwc1h, pwc1l,
                                                          ppart, KCONV, KCONV / 2);
    combine_k<3, 2><<<(T4_BIG + TPB - 1) / TPB, TPB>>>(ppart, SLICE_BIG,
                                                       nullptr, py1h, py1l, c1b, T4_BIG);

    // conv2: split-K 2 + combine -> selu+bias fp32
    gemm_mma<1><<<dim3(MROWS / 128, 2), 512, GEMM_SMEM>>>(py1h, py1l, pwc2h, pwc2l,
                                                          ppart, KCONV, KCONV / 2);
    combine_k<1, 2><<<(T4_BIG + TPB - 1) / TPB, TPB>>>(ppart, SLICE_BIG,
                                                       py2, nullptr, nullptr, c2b, T4_BIG);

    // pool + pos (+ adj zero + split)
    pool_pos<<<(BB * NN * HH + TPB - 1) / TPB, TPB>>>(py2, pos);

    // adjacency
    adj_topk<<<BB * NN, NN>>>();

    // GAT layer 0: split-K 8 + combine -> fp32
    gemm_mma<0><<<dim3(NROWS / 128, 8), 512, GEMM_SMEM>>>(phnh, phnl, pwt0h, pwt0l,
                                                          ppart, HH, HH / 8);
    combine_k<0, 8><<<(T4_SMALL + TPB - 1) / TPB, TPB>>>(ppart, SLICE_SMALL,
                                                         phw, nullptr, nullptr, nullptr, T4_SMALL);
    gat_sd<<<NROWS, HH>>>(asrc, adst);
    gat_attn<<<NROWS, HH>>>();

    // GAT layer 1
    gatwt_bf16<<<(HH * HH + TPB - 1) / TPB, TPB>>>(gatW + (size_t)HH * HH, pwt1h, pwt1l);
    gemm_mma<0><<<dim3(NROWS / 128, 8), 512, GEMM_SMEM>>>(phnh, phnl, pwt1h, pwt1l,
                                                          ppart, HH, HH / 8);
    combine_k<0, 8><<<(T4_SMALL + TPB - 1) / TPB, TPB>>>(ppart, SLICE_SMALL,
                                                         phw, nullptr, nullptr, nullptr, T4_SMALL);
    gat_sd<<<NROWS, HH>>>(asrc + HH, adst + HH);
    gat_attn<<<NROWS, HH>>>();

    // layernorm + pooling + classifier
    layernorm_k<<<NROWS, HH>>>(lng, lnb);
    pool_emb<<<(BB * HH + TPB - 1) / TPB, TPB>>>(out);
    cls_kan<<<BB, 256>>>(cbw, csw, csc, out);
}

// round 12
// speedup vs baseline: 1.1200x; 1.0123x over previous
#include <cuda_runtime.h>
#include <cuda_bf16.h>
#include <math.h>
#include <stdint.h>

typedef __nv_bfloat16 bf16;

// ---------------- problem constants ----------------
#define BB 16
#define TT 512
#define DIN 1024
#define HH 256
#define NN 64
#define TOPK 8
#define NCLS 2
#define KBRIDGE (DIN * 9)      // 9216
#define KCONV (HH * 3)         // 768
#define MROWS (BB * TT)        // 8192
#define NROWS (BB * NN)        // 1024

// ---------------- PTX helpers ----------------
__device__ __forceinline__ uint32_t smem_u32(const void* p) {
    uint32_t a;
    asm("{ .reg .u64 t; cvta.to.shared.u64 t, %1; cvt.u32.u64 %0, t; }" : "=r"(a) : "l"(p));
    return a;
}
#define CP_ASYNC16(dst, src) \
    asm volatile("cp.async.cg.shared.global [%0], [%1], 16;" :: "r"(dst), "l"(src) : "memory")
#define CP_COMMIT() asm volatile("cp.async.commit_group;" ::: "memory")
#define CP_WAIT(N)  asm volatile("cp.async.wait_group %0;" :: "n"(N) : "memory")
#define LDSM_X4(r0, r1, r2, r3, a) \
    asm volatile("ldmatrix.sync.aligned.m8n8.x4.shared.b16 {%0,%1,%2,%3}, [%4];" \
        : "=r"(r0), "=r"(r1), "=r"(r2), "=r"(r3) : "r"(a))
#define MMA_BF16(c, a0, a1, a2, a3, b0, b1) \
    asm volatile("mma.sync.aligned.m16n8k16.row.col.f32.bf16.bf16.f32 " \
        "{%0,%1,%2,%3}, {%4,%5,%6,%7}, {%8,%9}, {%0,%1,%2,%3};" \
        : "+f"((c)[0]), "+f"((c)[1]), "+f"((c)[2]), "+f"((c)[3]) \
        : "r"(a0), "r"(a1), "r"(a2), "r"(a3), "r"(b0), "r"(b1))
#define STS128Z(addr) \
    asm volatile("st.shared.v4.b32 [%0], {%1,%1,%1,%1};" :: "r"(addr), "r"(0u) : "memory")

// ---------------- scratch ----------------
__device__ bf16 g_fh[(size_t)MROWS * KBRIDGE];
__device__ bf16 g_fl[(size_t)MROWS * KBRIDGE];
__device__ bf16 g_wh[HH * KBRIDGE];
__device__ bf16 g_wl[HH * KBRIDGE];
__device__ float g_part[(size_t)8 * NROWS * HH > (size_t)2 * MROWS * HH ?
                        (size_t)8 * NROWS * HH : (size_t)2 * MROWS * HH];
__device__ bf16 g_h1h[MROWS * HH];
__device__ bf16 g_h1l[MROWS * HH];
__device__ bf16 g_wc1h[HH * KCONV];
__device__ bf16 g_wc1l[HH * KCONV];
__device__ bf16 g_wc2h[HH * KCONV];
__device__ bf16 g_wc2l[HH * KCONV];
__device__ bf16 g_y1h[MROWS * HH];
__device__ bf16 g_y1l[MROWS * HH];
__device__ float g_y2[MROWS * HH];
__device__ float g_hn[NROWS * HH];
__device__ bf16 g_hnh[NROWS * HH];
__device__ bf16 g_hnl[NROWS * HH];
__device__ bf16 g_wt0h[HH * HH];
__device__ bf16 g_wt0l[HH * HH];
__device__ bf16 g_wt1h[HH * HH];
__device__ bf16 g_wt1l[HH * HH];
__device__ float g_hw[NROWS * HH];
__device__ float g_s[NROWS];
__device__ float g_d[NROWS];
__device__ unsigned long long g_adj[BB * NN];
__device__ float g_ln[NROWS * HH];

// ---------------- math helpers ----------------
__device__ __forceinline__ float silu_f(float x) { return x * (1.f / (1.f + expf(-x))); }
__device__ __forceinline__ float selu_f(float x) {
    const float a = 1.6732632423543772f, s = 1.0507009873554805f;
    return x > 0.f ? s * x : s * a * expm1f(x);
}
__device__ __forceinline__ void split_bf16(float v, bf16& h, bf16& l) {
    h = __float2bfloat16_rn(v);
    l = __float2bfloat16_rn(v - __bfloat162float(h));
}
union Pack4 { bf16 b[4]; uint2 u; };
__device__ __forceinline__ void split_store4(const float* v, bf16* ph, bf16* pl) {
    Pack4 H, L;
#pragma unroll
    for (int j = 0; j < 4; j++) split_bf16(v[j], H.b[j], L.b[j]);
    *reinterpret_cast<uint2*>(ph) = H.u;
    *reinterpret_cast<uint2*>(pl) = L.u;
}
__device__ __forceinline__ void bsplines8(float x, float* out) {
    const float h = 0.4f;
    float b[11];
#pragma unroll
    for (int j = 0; j < 11; j++) {
        float gj = (float)(j - 3) * h - 1.0f;
        float gj1 = (float)(j - 2) * h - 1.0f;
        b[j] = (x >= gj && x < gj1) ? 1.f : 0.f;
    }
#pragma unroll
    for (int k = 1; k <= 3; k++) {
        float inv = 1.f / ((float)k * h);
#pragma unroll
        for (int j = 0; j < 11; j++) {
            if (j < 11 - k) {
                float gj = (float)(j - 3) * h - 1.0f;
                float gjk1 = (float)(j + k - 2) * h - 1.0f;
                b[j] = (x - gj) * inv * b[j] + (gjk1 - x) * inv * b[j + 1];
            }
        }
    }
#pragma unroll
    for (int j = 0; j < 8; j++) out[j] = b[j];
}

// ---------------- prep kernels ----------------
__global__ void bridge_features_bf16(const float* __restrict__ x) {
    int idx = blockIdx.x * blockDim.x + threadIdx.x;
    if (idx >= MROWS * (DIN / 4)) return;
    int r = idx >> 8, i4 = idx & 255;
    float4 xv = *reinterpret_cast<const float4*>(x + (size_t)r * DIN + i4 * 4);
    float vv[4] = {xv.x, xv.y, xv.z, xv.w};
    float f[9][4];
#pragma unroll
    for (int j = 0; j < 4; j++) {
        f[0][j] = silu_f(vv[j]);
        float bs[8];
        bsplines8(vv[j], bs);
#pragma unroll
        for (int c = 0; c < 8; c++) f[c + 1][j] = bs[c];
    }
    size_t base = (size_t)r * KBRIDGE + i4 * 4;
#pragma unroll
    for (int g = 0; g < 9; g++)
        split_store4(f[g], g_fh + base + (size_t)g * DIN, g_fl + base + (size_t)g * DIN);
}

__global__ void build_wcat_bf16(const float* __restrict__ bw, const float* __restrict__ sw,
                                const float* __restrict__ sc) {
    int idx = blockIdx.x * blockDim.x + threadIdx.x;
    if (idx >= HH * DIN) return;
    int i = idx % DIN, o = idx / DIN;
    size_t base = (size_t)o * KBRIDGE + i;
    bf16 h, l;
    split_bf16(bw[idx], h, l);
    g_wh[base] = h; g_wl[base] = l;
    float scale = sc[idx];
#pragma unroll
    for (int c = 0; c < 8; c++) {
        split_bf16(sw[(size_t)idx * 8 + c] * scale, h, l);
        size_t p = base + (size_t)(c + 1) * DIN;
        g_wh[p] = h; g_wl[p] = l;
    }
}

__global__ void conv_w_bf16(const float* __restrict__ w, bf16* __restrict__ wh, bf16* __restrict__ wl) {
    int idx = blockIdx.x * blockDim.x + threadIdx.x;
    if (idx >= HH * HH) return;
    int i = idx % HH, o = idx / HH;
#pragma unroll
    for (int j = 0; j < 3; j++) {
        bf16 h, l;
        split_bf16(w[((size_t)o * HH + i) * 3 + j], h, l);
        size_t p = (size_t)o * KCONV + j * HH + i;
        wh[p] = h; wl[p] = l;
    }
}

__global__ void gatwt_bf16(const float* __restrict__ w, bf16* __restrict__ wh, bf16* __restrict__ wl) {
    int idx = blockIdx.x * blockDim.x + threadIdx.x;
    if (idx >= HH * HH) return;
    int k = idx % HH, n = idx / HH;
    bf16 h, l;
    split_bf16(w[(size_t)k * HH + n], h, l);
    wh[idx] = h; wl[idx] = l;
}

// ===== split-bf16 split-K GEMM: 512 thr, warp tile 32x64, 3-stage, 1 barrier/chunk =====
#define BKS 32
#define SROWS 80
#define AS_STG (128 * SROWS)      // 10240 (one array)
#define BS_STG (256 * SROWS)      // 20480
#define STG_TOT (2 * AS_STG + 2 * BS_STG)     // 61440 per stage
#define GEMM_SMEM (3 * STG_TOT)               // 184320

template <int SHIFT>
__global__ __launch_bounds__(512, 1) void gemm_mma(
    const bf16* __restrict__ Ah, const bf16* __restrict__ Al,
    const bf16* __restrict__ Bh, const bf16* __restrict__ Bl,
    float* __restrict__ Cpart, int K, int kLen) {
    extern __shared__ char smem[];
    uint32_t s0 = smem_u32(smem);

    int tid = threadIdx.x, lane = tid & 31, wid = tid >> 5;
    int wm = wid & 3, wn = wid >> 2;      // 4 x 4 warp grid, warp tile 32x64
    int bm = blockIdx.x * 128;
    int kOff = blockIdx.y * kLen;
    float* Cf = Cpart + (size_t)blockIdx.y * gridDim.x * 128 * 256;
    const int nc = kLen / BKS;

    int aRow = wm * 32 + (lane & 15);
    int aCol = (lane >> 4) * 8;
    int bRow = wn * 64 + (lane & 7) + ((lane >> 4) << 3);
    int bCol = ((lane >> 3) & 1) * 8;

    float acc[2][8][4];
#pragma unroll
    for (int i = 0; i < 2; i++)
#pragma unroll
        for (int j = 0; j < 8; j++)
#pragma unroll
            for (int q = 0; q < 4; q++) acc[i][j][q] = 0.f;

    auto issue = [&](int st, int k0) {
        uint32_t sb = s0 + (uint32_t)(st * STG_TOT);
        {
            int r = tid >> 2, c = tid & 3;
            uint32_t dh = sb + (uint32_t)(r * SROWS + c * 16);
            uint32_t dl = dh + AS_STG;
            if (SHIFT) {
                int k = kOff + k0 + c * 8;
                int j = k >> 8, cc = k & 255;
                int grow = bm + r;
                int tj = (grow & 511) + j - 1;
                if (tj >= 0 && tj < 512) {
                    size_t go = (size_t)(grow + j - 1) * 256 + cc;
                    CP_ASYNC16(dh, Ah + go);
                    CP_ASYNC16(dl, Al + go);
                } else {
                    STS128Z(dh);
                    STS128Z(dl);
                }
            } else {
                size_t go = (size_t)(bm + r) * K + kOff + k0 + c * 8;
                CP_ASYNC16(dh, Ah + go);
                CP_ASYNC16(dl, Al + go);
            }
        }
#pragma unroll
        for (int i = 0; i < 2; i++) {
            int q = i * 512 + tid;
            int r = q >> 2, c = q & 3;
            uint32_t d = sb + (uint32_t)(2 * AS_STG + r * SROWS + c * 16);
            size_t go = (size_t)r * K + kOff + k0 + c * 8;
            CP_ASYNC16(d, Bh + go);
            CP_ASYNC16(d + BS_STG, Bl + go);
        }
    };

    issue(0, 0);
    CP_COMMIT();
    if (nc > 1) { issue(1, BKS); CP_COMMIT(); }

    int st = 0;
    for (int kc = 0; kc < nc; kc++) {
        if (kc + 1 < nc) { CP_WAIT(1); } else { CP_WAIT(0); }
        __syncthreads();
        if (kc + 2 < nc) {
            int nst = st + 2; if (nst >= 3) nst -= 3;
            issue(nst, (kc + 2) * BKS);
            CP_COMMIT();
        }
        uint32_t sb = s0 + (uint32_t)(st * STG_TOT);
        uint32_t sAh = sb, sAl = sb + AS_STG;
        uint32_t sBh = sb + 2 * AS_STG, sBl = sBh + BS_STG;
#pragma unroll
        for (int kk = 0; kk < 2; kk++) {
            uint32_t ah[2][4], al[2][4];
#pragma unroll
            for (int mt = 0; mt < 2; mt++) {
                uint32_t ao = (uint32_t)((aRow + mt * 16) * SROWS + (aCol + kk * 16) * 2);
                LDSM_X4(ah[mt][0], ah[mt][1], ah[mt][2], ah[mt][3], sAh + ao);
                LDSM_X4(al[mt][0], al[mt][1], al[mt][2], al[mt][3], sAl + ao);
            }
#pragma unroll
            for (int nt2 = 0; nt2 < 4; nt2++) {
                uint32_t bo = (uint32_t)((bRow + nt2 * 16) * SROWS + (bCol + kk * 16) * 2);
                uint32_t bh[4], bl[4];
                LDSM_X4(bh[0], bh[1], bh[2], bh[3], sBh + bo);
                LDSM_X4(bl[0], bl[1], bl[2], bl[3], sBl + bo);
                int n0 = nt2 * 2, n1 = n0 + 1;
                MMA_BF16(acc[0][n0], ah[0][0], ah[0][1], ah[0][2], ah[0][3], bh[0], bh[1]);
                MMA_BF16(acc[0][n1], ah[0][0], ah[0][1], ah[0][2], ah[0][3], bh[2], bh[3]);
                MMA_BF16(acc[1][n0], ah[1][0], ah[1][1], ah[1][2], ah[1][3], bh[0], bh[1]);
                MMA_BF16(acc[1][n1], ah[1][0], ah[1][1], ah[1][2], ah[1][3], bh[2], bh[3]);
                MMA_BF16(acc[0][n0], ah[0][0], ah[0][1], ah[0][2], ah[0][3], bl[0], bl[1]);
                MMA_BF16(acc[0][n1], ah[0][0], ah[0][1], ah[0][2], ah[0][3], bl[2], bl[3]);
                MMA_BF16(acc[1][n0], ah[1][0], ah[1][1], ah[1][2], ah[1][3], bl[0], bl[1]);
                MMA_BF16(acc[1][n1], ah[1][0], ah[1][1], ah[1][2], ah[1][3], bl[2], bl[3]);
                MMA_BF16(acc[0][n0], al[0][0], al[0][1], al[0][2], al[0][3], bh[0], bh[1]);
                MMA_BF16(acc[0][n1], al[0][0], al[0][1], al[0][2], al[0][3], bh[2], bh[3]);
                MMA_BF16(acc[1][n0], al[1][0], al[1][1], al[1][2], al[1][3], bh[0], bh[1]);
                MMA_BF16(acc[1][n1], al[1][0], al[1][1], al[1][2], al[1][3], bh[2], bh[3]);
            }
        }
        if (++st == 3) st = 0;
    }

    int rbase = bm + wm * 32 + (lane >> 2);
    int cbase = wn * 64 + (lane & 3) * 2;
#pragma unroll
    for (int mt = 0; mt < 2; mt++) {
#pragma unroll
        for (int nt = 0; nt < 8; nt++) {
            int r = rbase + mt * 16;
            int c = cbase + nt * 8;
            *reinterpret_cast<float2*>(Cf + (size_t)r * 256 + c) =
                make_float2(acc[mt][nt][0], acc[mt][nt][1]);
            *reinterpret_cast<float2*>(Cf + (size_t)(r + 8) * 256 + c) =
                make_float2(acc[mt][nt][2], acc[mt][nt][3]);
        }
    }
}

// ---------------- split-K combine + epilogue ----------------
// EPI: 0 fp32 | 1 selu+bias fp32 | 2 split bf16 | 3 selu+bias split bf16
template <int EPI, int SK>
__global__ void combine_k(const float* __restrict__ part, size_t slice,
                          float* __restrict__ Cf, bf16* __restrict__ Ch, bf16* __restrict__ Cl,
                          const float* __restrict__ bias, int total4) {
    int idx = blockIdx.x * blockDim.x + threadIdx.x;
    if (idx >= total4) return;
    const float4* p4 = reinterpret_cast<const float4*>(part);
    size_t s4 = slice >> 2;
    float4 a = p4[idx];
#pragma unroll
    for (int s = 1; s < SK; s++) {
        float4 b = p4[idx + (size_t)s * s4];
        a.x += b.x; a.y += b.y; a.z += b.z; a.w += b.w;
    }
    float v[4] = {a.x, a.y, a.z, a.w};
    if (EPI == 1 || EPI == 3) {
        int c = (idx * 4) & 255;
        float4 b4 = *reinterpret_cast<const float4*>(bias + c);
        v[0] = selu_f(v[0] + b4.x); v[1] = selu_f(v[1] + b4.y);
        v[2] = selu_f(v[2] + b4.z); v[3] = selu_f(v[3] + b4.w);
    }
    if (EPI >= 2) {
        split_store4(v, Ch + (size_t)idx * 4, Cl + (size_t)idx * 4);
    } else {
        *reinterpret_cast<float4*>(Cf + (size_t)idx * 4) = make_float4(v[0], v[1], v[2], v[3]);
    }
}

// ---------------- fused GAT split-K combine + source/dest reductions ----------------
__global__ void gat_combine_sd(const float* __restrict__ part,
                               const float* __restrict__ asrc, const float* __restrict__ adst) {
    int row = blockIdx.x;
    int t = threadIdx.x;
    size_t off = (size_t)row * HH + t;
    float v = 0.f;
#pragma unroll
    for (int s = 0; s < 8; s++) v += part[(size_t)s * NROWS * HH + off];
    g_hw[off] = v;
    __shared__ float r1[HH], r2[HH];
    r1[t] = v * asrc[t];
    r2[t] = v * adst[t];
    __syncthreads();
    for (int st = 128; st > 0; st >>= 1) {
        if (t < st) { r1[t] += r1[t + st]; r2[t] += r2[t + st]; }
        __syncthreads();
    }
    if (t == 0) { g_s[row] = r1[0]; g_d[row] = r2[0]; }
}

// ---------------- pool + pos (+ adj zero, + split) ----------------
__global__ void pool_pos(const float* __restrict__ y2, const float* __restrict__ pos) {
    int idx = blockIdx.x * blockDim.x + threadIdx.x;
    if (idx < BB * NN) g_adj[idx] = 0ull;
    if (idx >= BB * NN * HH) return;
    int c = idx % HH;
    int n = (idx / HH) % NN;
    int b = idx / (HH * NN);
    float s = 0.f;
#pragma unroll
    for (int t = 0; t < 8; t++) s += y2[((size_t)b * TT + n * 8 + t) * HH + c];
    float v = s * 0.125f + pos[(size_t)n * HH + c];
    size_t o = ((size_t)b * NN + n) * HH + c;
    g_hn[o] = v;
    bf16 h, l;
    split_bf16(v, h, l);
    g_hnh[o] = h; g_hnl[o] = l;
}

// ---------------- adjacency ----------------
__global__ void adj_topk() {
    int b = blockIdx.x / NN, n = blockIdx.x % NN;
    __shared__ float sc[NN];
    int m = threadIdx.x;
    const float* hb = g_hn + (size_t)b * NN * HH;
    float s = 0.f;
    for (int k = 0; k < HH; k++) s = fmaf(hb[(size_t)n * HH + k], hb[(size_t)m * HH + k], s);
    sc[m] = s;
    __syncthreads();
    if (m == 0) {
        unsigned long long mask = 1ull << n;
        int sel[TOPK];
#pragma unroll 1
        for (int it = 0; it < TOPK; it++) {
            float best = -INFINITY; int bi = 0;
            for (int j = 0; j < NN; j++)
                if (sc[j] > best) { best = sc[j]; bi = j; }
            sel[it] = bi;
            sc[bi] = -INFINITY;
            mask |= 1ull << bi;
        }
        atomicOr(&g_adj[b * NN + n], mask);
        for (int it = 0; it < TOPK; it++)
            atomicOr(&g_adj[b * NN + sel[it]], 1ull << n);
    }
}

// ---------------- GAT attention ----------------
__global__ void gat_attn() {
    int b = blockIdx.x / NN, n = blockIdx.x % NN;
    __shared__ float attn[NN];
    __shared__ float inv_s;
    int t = threadIdx.x;
    unsigned long long mask = g_adj[b * NN + n];
    if (t < NN) {
        float e;
        if ((mask >> t) & 1ull) {
            float z = g_s[b * NN + n] + g_d[b * NN + t];
            e = z >= 0.f ? z : 0.2f * z;
        } else {
            e = -1e9f;
        }
        attn[t] = e;
    }
    __syncthreads();
    if (t == 0) {
        float mx = -INFINITY;
        for (int j = 0; j < NN; j++) mx = fmaxf(mx, attn[j]);
        float sum = 0.f;
        for (int j = 0; j < NN; j++) { float ex = expf(attn[j] - mx); attn[j] = ex; sum += ex; }
        inv_s = 1.f / sum;
    }
    __syncthreads();
    float inv = inv_s;
    float acc = 0.f;
    for (int m = 0; m < NN; m++)
        acc = fmaf(attn[m] * inv, g_hw[((size_t)b * NN + m) * HH + t], acc);
    float o = acc > 0.f ? acc : expm1f(acc);
    size_t oo = ((size_t)b * NN + n) * HH + t;
    float nh = g_hn[oo] + o;
    g_hn[oo] = nh;
    bf16 h, l;
    split_bf16(nh, h, l);
    g_hnh[oo] = h; g_hnl[oo] = l;
}

// ---------------- layernorm ----------------
__global__ void layernorm_k(const float* __restrict__ g, const float* __restrict__ bt) {
    int row = blockIdx.x;
    __shared__ float red[HH];
    __shared__ float mu_s, is_s;
    int t = threadIdx.x;
    float v = g_hn[(size_t)row * HH + t];
    red[t] = v;
    __syncthreads();
    for (int st = 128; st > 0; st >>= 1) { if (t < st) red[t] += red[t + st]; __syncthreads(); }
    if (t == 0) mu_s = red[0] * (1.f / HH);
    __syncthreads();
    float mu = mu_s;
    float dv = v - mu;
    red[t] = dv * dv;
    __syncthreads();
    for (int st = 128; st > 0; st >>= 1) { if (t < st) red[t] += red[t + st]; __syncthreads(); }
    if (t == 0) is_s = rsqrtf(red[0] * (1.f / HH) + 1e-5f);
    __syncthreads();
    g_ln[(size_t)row * HH + t] = dv * is_s * g[t] + bt[t];
}

// ---------------- fused emb pooling + classifier KAN ----------------
__global__ void emb_cls(const float* __restrict__ cbw, const float* __restrict__ csw,
                        const float* __restrict__ csc, float* __restrict__ out) {
    int b = blockIdx.x;
    int t = threadIdx.x;   // 256
    __shared__ float emb[2 * HH];
    __shared__ float r0[256], r1[256];

    // pool: thread t handles channel t (mean -> emb[t], max -> emb[HH+t])
    {
        float sm = 0.f, mx = -INFINITY;
        const float* lb = g_ln + (size_t)b * NN * HH + t;
        for (int n = 0; n < NN; n++) {
            float v = lb[(size_t)n * HH];
            sm += v;
            mx = fmaxf(mx, v);
        }
        float mean = sm * (1.f / NN);
        emb[t] = mean;
        emb[HH + t] = mx;
        out[BB * NCLS + (size_t)b * (2 * HH) + t] = mean;
        out[BB * NCLS + (size_t)b * (2 * HH) + HH + t] = mx;
    }
    __syncthreads();

    // classifier KAN on emb (from smem)
    float a0 = 0.f, a1 = 0.f;
    for (int i = t; i < 2 * HH; i += 256) {
        float x = emb[i];
        float sil = silu_f(x);
        float bs[8];
        bsplines8(x, bs);
        float p0 = sil * cbw[i];
        float p1 = sil * cbw[2 * HH + i];
        float s0 = csc[i], s1 = csc[2 * HH + i];
#pragma unroll
        for (int c = 0; c < 8; c++) {
            p0 = fmaf(bs[c] * csw[(size_t)i * 8 + c], s0, p0);
            p1 = fmaf(bs[c] * csw[(size_t)(2 * HH + i) * 8 + c], s1, p1);
        }
        a0 += p0;
        a1 += p1;
    }
    r0[t] = a0; r1[t] = a1;
    __syncthreads();
    for (int st = 128; st > 0; st >>= 1) {
        if (t < st) { r0[t] += r0[t + st]; r1[t] += r1[t + st]; }
        __syncthreads();
    }
    if (t == 0) { out[b * NCLS + 0] = r0[0]; out[b * NCLS + 1] = r1[0]; }
}

// ---------------- host launch ----------------
extern "C" void kernel_launch(void* const* d_in, const int* in_sizes, int n_in,
                              void* d_out, int out_size) {
    const float* x    = (const float*)d_in[0];
    const float* bbw  = (const float*)d_in[1];
    const float* bsw  = (const float*)d_in[2];
    const float* bsc  = (const float*)d_in[3];
    const float* c1w  = (const float*)d_in[4];
    const float* c1b  = (const float*)d_in[5];
    const float* c2w  = (const float*)d_in[6];
    const float* c2b  = (const float*)d_in[7];
    const float* pos  = (const float*)d_in[8];
    const float* gatW = (const float*)d_in[9];
    const float* asrc = (const float*)d_in[10];
    const float* adst = (const float*)d_in[11];
    const float* lng  = (const float*)d_in[12];
    const float* lnb  = (const float*)d_in[13];
    const float* cbw  = (const float*)d_in[14];
    const float* csw  = (const float*)d_in[15];
    const float* csc  = (const float*)d_in[16];
    float* out = (float*)d_out;

    bf16 *pfh, *pfl, *pwh, *pwl, *ph1h, *ph1l, *pwc1h, *pwc1l, *pwc2h, *pwc2l;
    bf16 *py1h, *py1l, *phnh, *phnl, *pwt0h, *pwt0l, *pwt1h, *pwt1l;
    float *py2, *ppart;
    cudaGetSymbolAddress((void**)&pfh, g_fh);
    cudaGetSymbolAddress((void**)&pfl, g_fl);
    cudaGetSymbolAddress((void**)&pwh, g_wh);
    cudaGetSymbolAddress((void**)&pwl, g_wl);
    cudaGetSymbolAddress((void**)&ph1h, g_h1h);
    cudaGetSymbolAddress((void**)&ph1l, g_h1l);
    cudaGetSymbolAddress((void**)&pwc1h, g_wc1h);
    cudaGetSymbolAddress((void**)&pwc1l, g_wc1l);
    cudaGetSymbolAddress((void**)&pwc2h, g_wc2h);
    cudaGetSymbolAddress((void**)&pwc2l, g_wc2l);
    cudaGetSymbolAddress((void**)&py1h, g_y1h);
    cudaGetSymbolAddress((void**)&py1l, g_y1l);
    cudaGetSymbolAddress((void**)&phnh, g_hnh);
    cudaGetSymbolAddress((void**)&phnl, g_hnl);
    cudaGetSymbolAddress((void**)&pwt0h, g_wt0h);
    cudaGetSymbolAddress((void**)&pwt0l, g_wt0l);
    cudaGetSymbolAddress((void**)&pwt1h, g_wt1h);
    cudaGetSymbolAddress((void**)&pwt1l, g_wt1l);
    cudaGetSymbolAddress((void**)&py2, g_y2);
    cudaGetSymbolAddress((void**)&ppart, g_part);

    cudaFuncSetAttribute(gemm_mma<0>, cudaFuncAttributeMaxDynamicSharedMemorySize, GEMM_SMEM);
    cudaFuncSetAttribute(gemm_mma<1>, cudaFuncAttributeMaxDynamicSharedMemorySize, GEMM_SMEM);

    const int TPB = 256;
    const size_t SLICE_BIG = (size_t)MROWS * HH;
    const int T4_BIG = MROWS * HH / 4;

    // prep
    bridge_features_bf16<<<MROWS * (DIN / 4) / TPB, TPB>>>(x);
    build_wcat_bf16<<<(HH * DIN + TPB - 1) / TPB, TPB>>>(bbw, bsw, bsc);
    conv_w_bf16<<<(HH * HH + TPB - 1) / TPB, TPB>>>(c1w, pwc1h, pwc1l);
    conv_w_bf16<<<(HH * HH + TPB - 1) / TPB, TPB>>>(c2w, pwc2h, pwc2l);
    gatwt_bf16<<<(HH * HH + TPB - 1) / TPB, TPB>>>(gatW, pwt0h, pwt0l);
    gatwt_bf16<<<(HH * HH + TPB - 1) / TPB, TPB>>>(gatW + (size_t)HH * HH, pwt1h, pwt1l);

    // bridge GEMM: split-K 2 + combine -> split bf16
    gemm_mma<0><<<dim3(MROWS / 128, 2), 512, GEMM_SMEM>>>(pfh, pfl, pwh, pwl,
                                                          ppart, KBRIDGE, KBRIDGE / 2);
    combine_k<2, 2><<<(T4_BIG + TPB - 1) / TPB, TPB>>>(ppart, SLICE_BIG,
                                                       nullptr, ph1h, ph1l, nullptr, T4_BIG);

    // conv1: split-K 2 + combine -> selu+bias split bf16
    gemm_mma<1><<<dim3(MROWS / 128, 2), 512, GEMM_SMEM>>>(ph1h, ph1l, pwc1h, pwc1l,
                                                          ppart, KCONV, KCONV / 2);
    combine_k<3, 2><<<(T4_BIG + TPB - 1) / TPB, TPB>>>(ppart, SLICE_BIG,
                                                       nullptr, py1h, py1l, c1b, T4_BIG);

    // conv2: split-K 2 + combine -> selu+bias fp32
    gemm_mma<1><<<dim3(MROWS / 128, 2), 512, GEMM_SMEM>>>(py1h, py1l, pwc2h, pwc2l,
                                                          ppart, KCONV, KCONV / 2);
    combine_k<1, 2><<<(T4_BIG + TPB - 1) / TPB, TPB>>>(ppart, SLICE_BIG,
                                                       py2, nullptr, nullptr, c2b, T4_BIG);

    // pool + pos (+ adj zero + split)
    pool_pos<<<(BB * NN * HH + TPB - 1) / TPB, TPB>>>(py2, pos);

    // adjacency
    adj_topk<<<BB * NN, NN>>>();

    // GAT layer 0: split-K 8 + fused combine/sd + attn
    gemm_mma<0><<<dim3(NROWS / 128, 8), 512, GEMM_SMEM>>>(phnh, phnl, pwt0h, pwt0l,
                                                          ppart, HH, HH / 8);
    gat_combine_sd<<<NROWS, HH>>>(ppart, asrc, adst);
    gat_attn<<<NROWS, HH>>>();

    // GAT layer 1
    gemm_mma<0><<<dim3(NROWS / 128, 8), 512, GEMM_SMEM>>>(phnh, phnl, pwt1h, pwt1l,
                                                          ppart, HH, HH / 8);
    gat_combine_sd<<<NROWS, HH>>>(ppart, asrc + HH, adst + HH);
    gat_attn<<<NROWS, HH>>>();

    // layernorm + fused emb pooling/classifier
    layernorm_k<<<NROWS, HH>>>(lng, lnb);
    emb_cls<<<BB, 256>>>(cbw, csw, csc, out);
}

// round 13
// speedup vs baseline: 1.1249x; 1.0044x over previous
#include <cuda_runtime.h>
#include <cuda_bf16.h>
#include <math.h>
#include <stdint.h>

typedef __nv_bfloat16 bf16;

// ---------------- problem constants ----------------
#define BB 16
#define TT 512
#define DIN 1024
#define HH 256
#define NN 64
#define TOPK 8
#define NCLS 2
#define KBRIDGE (DIN * 9)      // 9216
#define KCONV (HH * 3)         // 768
#define MROWS (BB * TT)        // 8192
#define NROWS (BB * NN)        // 1024

// ---------------- PTX helpers ----------------
__device__ __forceinline__ uint32_t smem_u32(const void* p) {
    uint32_t a;
    asm("{ .reg .u64 t; cvta.to.shared.u64 t, %1; cvt.u32.u64 %0, t; }" : "=r"(a) : "l"(p));
    return a;
}
#define CP_ASYNC16(dst, src) \
    asm volatile("cp.async.cg.shared.global [%0], [%1], 16;" :: "r"(dst), "l"(src) : "memory")
#define CP_COMMIT() asm volatile("cp.async.commit_group;" ::: "memory")
#define CP_WAIT(N)  asm volatile("cp.async.wait_group %0;" :: "n"(N) : "memory")
#define LDSM_X4(r0, r1, r2, r3, a) \
    asm volatile("ldmatrix.sync.aligned.m8n8.x4.shared.b16 {%0,%1,%2,%3}, [%4];" \
        : "=r"(r0), "=r"(r1), "=r"(r2), "=r"(r3) : "r"(a))
#define MMA_BF16(c, a0, a1, a2, a3, b0, b1) \
    asm volatile("mma.sync.aligned.m16n8k16.row.col.f32.bf16.bf16.f32 " \
        "{%0,%1,%2,%3}, {%4,%5,%6,%7}, {%8,%9}, {%0,%1,%2,%3};" \
        : "+f"((c)[0]), "+f"((c)[1]), "+f"((c)[2]), "+f"((c)[3]) \
        : "r"(a0), "r"(a1), "r"(a2), "r"(a3), "r"(b0), "r"(b1))
#define STS128Z(addr) \
    asm volatile("st.shared.v4.b32 [%0], {%1,%1,%1,%1};" :: "r"(addr), "r"(0u) : "memory")

// ---------------- scratch ----------------
__device__ bf16 g_fh[(size_t)MROWS * KBRIDGE];
__device__ bf16 g_fl[(size_t)MROWS * KBRIDGE];
__device__ bf16 g_wh[HH * KBRIDGE];
__device__ bf16 g_wl[HH * KBRIDGE];
__device__ float g_part[(size_t)8 * NROWS * HH > (size_t)2 * MROWS * HH ?
                        (size_t)8 * NROWS * HH : (size_t)2 * MROWS * HH];
__device__ bf16 g_h1h[MROWS * HH];
__device__ bf16 g_h1l[MROWS * HH];
__device__ bf16 g_wc1h[HH * KCONV];
__device__ bf16 g_wc1l[HH * KCONV];
__device__ bf16 g_wc2h[HH * KCONV];
__device__ bf16 g_wc2l[HH * KCONV];
__device__ bf16 g_y1h[MROWS * HH];
__device__ bf16 g_y1l[MROWS * HH];
__device__ float g_y2[MROWS * HH];
__device__ float g_hn[NROWS * HH];
__device__ bf16 g_hnh[NROWS * HH];
__device__ bf16 g_hnl[NROWS * HH];
__device__ bf16 g_wt0h[HH * HH];
__device__ bf16 g_wt0l[HH * HH];
__device__ bf16 g_wt1h[HH * HH];
__device__ bf16 g_wt1l[HH * HH];
__device__ float g_hw[NROWS * HH];
__device__ float g_s[NROWS];
__device__ float g_d[NROWS];
__device__ unsigned long long g_adj[BB * NN];
__device__ float g_ln[NROWS * HH];

// ---------------- math helpers ----------------
__device__ __forceinline__ float silu_f(float x) { return x * (1.f / (1.f + expf(-x))); }
__device__ __forceinline__ float selu_f(float x) {
    const float a = 1.6732632423543772f, s = 1.0507009873554805f;
    return x > 0.f ? s * x : s * a * expm1f(x);
}
__device__ __forceinline__ void split_bf16(float v, bf16& h, bf16& l) {
    h = __float2bfloat16_rn(v);
    l = __float2bfloat16_rn(v - __bfloat162float(h));
}
union Pack4 { bf16 b[4]; uint2 u; };
__device__ __forceinline__ void split_store4(const float* v, bf16* ph, bf16* pl) {
    Pack4 H, L;
#pragma unroll
    for (int j = 0; j < 4; j++) split_bf16(v[j], H.b[j], L.b[j]);
    *reinterpret_cast<uint2*>(ph) = H.u;
    *reinterpret_cast<uint2*>(pl) = L.u;
}
__device__ __forceinline__ void bsplines8(float x, float* out) {
    const float h = 0.4f;
    float b[11];
#pragma unroll
    for (int j = 0; j < 11; j++) {
        float gj = (float)(j - 3) * h - 1.0f;
        float gj1 = (float)(j - 2) * h - 1.0f;
        b[j] = (x >= gj && x < gj1) ? 1.f : 0.f;
    }
#pragma unroll
    for (int k = 1; k <= 3; k++) {
        float inv = 1.f / ((float)k * h);
#pragma unroll
        for (int j = 0; j < 11; j++) {
            if (j < 11 - k) {
                float gj = (float)(j - 3) * h - 1.0f;
                float gjk1 = (float)(j + k - 2) * h - 1.0f;
                b[j] = (x - gj) * inv * b[j] + (gjk1 - x) * inv * b[j + 1];
            }
        }
    }
#pragma unroll
    for (int j = 0; j < 8; j++) out[j] = b[j];
}

// ---------------- prep kernels ----------------
__global__ void bridge_features_bf16(const float* __restrict__ x) {
    int idx = blockIdx.x * blockDim.x + threadIdx.x;
    if (idx >= MROWS * (DIN / 4)) return;
    int r = idx >> 8, i4 = idx & 255;
    float4 xv = *reinterpret_cast<const float4*>(x + (size_t)r * DIN + i4 * 4);
    float vv[4] = {xv.x, xv.y, xv.z, xv.w};
    float f[9][4];
#pragma unroll
    for (int j = 0; j < 4; j++) {
        f[0][j] = silu_f(vv[j]);
        float bs[8];
        bsplines8(vv[j], bs);
#pragma unroll
        for (int c = 0; c < 8; c++) f[c + 1][j] = bs[c];
    }
    size_t base = (size_t)r * KBRIDGE + i4 * 4;
#pragma unroll
    for (int g = 0; g < 9; g++)
        split_store4(f[g], g_fh + base + (size_t)g * DIN, g_fl + base + (size_t)g * DIN);
}

__global__ void build_wcat_bf16(const float* __restrict__ bw, const float* __restrict__ sw,
                                const float* __restrict__ sc) {
    int idx = blockIdx.x * blockDim.x + threadIdx.x;
    if (idx >= HH * DIN) return;
    int i = idx % DIN, o = idx / DIN;
    size_t base = (size_t)o * KBRIDGE + i;
    bf16 h, l;
    split_bf16(bw[idx], h, l);
    g_wh[base] = h; g_wl[base] = l;
    float scale = sc[idx];
#pragma unroll
    for (int c = 0; c < 8; c++) {
        split_bf16(sw[(size_t)idx * 8 + c] * scale, h, l);
        size_t p = base + (size_t)(c + 1) * DIN;
        g_wh[p] = h; g_wl[p] = l;
    }
}

__global__ void conv_w_bf16(const float* __restrict__ w, bf16* __restrict__ wh, bf16* __restrict__ wl) {
    int idx = blockIdx.x * blockDim.x + threadIdx.x;
    if (idx >= HH * HH) return;
    int i = idx % HH, o = idx / HH;
#pragma unroll
    for (int j = 0; j < 3; j++) {
        bf16 h, l;
        split_bf16(w[((size_t)o * HH + i) * 3 + j], h, l);
        size_t p = (size_t)o * KCONV + j * HH + i;
        wh[p] = h; wl[p] = l;
    }
}

// both GAT layers in one launch: grid.y selects layer
__global__ void gatwt_bf16(const float* __restrict__ w) {
    int idx = blockIdx.x * blockDim.x + threadIdx.x;
    if (idx >= HH * HH) return;
    int L = blockIdx.y;
    int k = idx % HH, n = idx / HH;
    bf16 h, l;
    split_bf16(w[(size_t)L * HH * HH + (size_t)k * HH + n], h, l);
    if (L == 0) { g_wt0h[idx] = h; g_wt0l[idx] = l; }
    else        { g_wt1h[idx] = h; g_wt1l[idx] = l; }
}

// ===== split-bf16 split-K GEMM: 512 thr, warp tile 32x64, 3-stage, 1 barrier/chunk =====
#define BKS 32
#define SROWS 80
#define AS_STG (128 * SROWS)
#define BS_STG (256 * SROWS)
#define STG_TOT (2 * AS_STG + 2 * BS_STG)
#define GEMM_SMEM (3 * STG_TOT)

template <int SHIFT>
__global__ __launch_bounds__(512, 1) void gemm_mma(
    const bf16* __restrict__ Ah, const bf16* __restrict__ Al,
    const bf16* __restrict__ Bh, const bf16* __restrict__ Bl,
    float* __restrict__ Cpart, int K, int kLen) {
    extern __shared__ char smem[];
    uint32_t s0 = smem_u32(smem);

    int tid = threadIdx.x, lane = tid & 31, wid = tid >> 5;
    int wm = wid & 3, wn = wid >> 2;
    int bm = blockIdx.x * 128;
    int kOff = blockIdx.y * kLen;
    float* Cf = Cpart + (size_t)blockIdx.y * gridDim.x * 128 * 256;
    const int nc = kLen / BKS;

    int aRow = wm * 32 + (lane & 15);
    int aCol = (lane >> 4) * 8;
    int bRow = wn * 64 + (lane & 7) + ((lane >> 4) << 3);
    int bCol = ((lane >> 3) & 1) * 8;

    float acc[2][8][4];
#pragma unroll
    for (int i = 0; i < 2; i++)
#pragma unroll
        for (int j = 0; j < 8; j++)
#pragma unroll
            for (int q = 0; q < 4; q++) acc[i][j][q] = 0.f;

    auto issue = [&](int st, int k0) {
        uint32_t sb = s0 + (uint32_t)(st * STG_TOT);
        {
            int r = tid >> 2, c = tid & 3;
            uint32_t dh = sb + (uint32_t)(r * SROWS + c * 16);
            uint32_t dl = dh + AS_STG;
            if (SHIFT) {
                int k = kOff + k0 + c * 8;
                int j = k >> 8, cc = k & 255;
                int grow = bm + r;
                int tj = (grow & 511) + j - 1;
                if (tj >= 0 && tj < 512) {
                    size_t go = (size_t)(grow + j - 1) * 256 + cc;
                    CP_ASYNC16(dh, Ah + go);
                    CP_ASYNC16(dl, Al + go);
                } else {
                    STS128Z(dh);
                    STS128Z(dl);
                }
            } else {
                size_t go = (size_t)(bm + r) * K + kOff + k0 + c * 8;
                CP_ASYNC16(dh, Ah + go);
                CP_ASYNC16(dl, Al + go);
            }
        }
#pragma unroll
        for (int i = 0; i < 2; i++) {
            int q = i * 512 + tid;
            int r = q >> 2, c = q & 3;
            uint32_t d = sb + (uint32_t)(2 * AS_STG + r * SROWS + c * 16);
            size_t go = (size_t)r * K + kOff + k0 + c * 8;
            CP_ASYNC16(d, Bh + go);
            CP_ASYNC16(d + BS_STG, Bl + go);
        }
    };

    issue(0, 0);
    CP_COMMIT();
    if (nc > 1) { issue(1, BKS); CP_COMMIT(); }

    int st = 0;
    for (int kc = 0; kc < nc; kc++) {
        if (kc + 1 < nc) { CP_WAIT(1); } else { CP_WAIT(0); }
        __syncthreads();
        if (kc + 2 < nc) {
            int nst = st + 2; if (nst >= 3) nst -= 3;
            issue(nst, (kc + 2) * BKS);
            CP_COMMIT();
        }
        uint32_t sb = s0 + (uint32_t)(st * STG_TOT);
        uint32_t sAh = sb, sAl = sb + AS_STG;
        uint32_t sBh = sb + 2 * AS_STG, sBl = sBh + BS_STG;
#pragma unroll
        for (int kk = 0; kk < 2; kk++) {
            uint32_t ah[2][4], al[2][4];
#pragma unroll
            for (int mt = 0; mt < 2; mt++) {
                uint32_t ao = (uint32_t)((aRow + mt * 16) * SROWS + (aCol + kk * 16) * 2);
                LDSM_X4(ah[mt][0], ah[mt][1], ah[mt][2], ah[mt][3], sAh + ao);
                LDSM_X4(al[mt][0], al[mt][1], al[mt][2], al[mt][3], sAl + ao);
            }
#pragma unroll
            for (int nt2 = 0; nt2 < 4; nt2++) {
                uint32_t bo = (uint32_t)((bRow + nt2 * 16) * SROWS + (bCol + kk * 16) * 2);
                uint32_t bh[4], bl[4];
                LDSM_X4(bh[0], bh[1], bh[2], bh[3], sBh + bo);
                LDSM_X4(bl[0], bl[1], bl[2], bl[3], sBl + bo);
                int n0 = nt2 * 2, n1 = n0 + 1;
                MMA_BF16(acc[0][n0], ah[0][0], ah[0][1], ah[0][2], ah[0][3], bh[0], bh[1]);
                MMA_BF16(acc[0][n1], ah[0][0], ah[0][1], ah[0][2], ah[0][3], bh[2], bh[3]);
                MMA_BF16(acc[1][n0], ah[1][0], ah[1][1], ah[1][2], ah[1][3], bh[0], bh[1]);
                MMA_BF16(acc[1][n1], ah[1][0], ah[1][1], ah[1][2], ah[1][3], bh[2], bh[3]);
                MMA_BF16(acc[0][n0], ah[0][0], ah[0][1], ah[0][2], ah[0][3], bl[0], bl[1]);
                MMA_BF16(acc[0][n1], ah[0][0], ah[0][1], ah[0][2], ah[0][3], bl[2], bl[3]);
                MMA_BF16(acc[1][n0], ah[1][0], ah[1][1], ah[1][2], ah[1][3], bl[0], bl[1]);
                MMA_BF16(acc[1][n1], ah[1][0], ah[1][1], ah[1][2], ah[1][3], bl[2], bl[3]);
                MMA_BF16(acc[0][n0], al[0][0], al[0][1], al[0][2], al[0][3], bh[0], bh[1]);
                MMA_BF16(acc[0][n1], al[0][0], al[0][1], al[0][2], al[0][3], bh[2], bh[3]);
                MMA_BF16(acc[1][n0], al[1][0], al[1][1], al[1][2], al[1][3], bh[0], bh[1]);
                MMA_BF16(acc[1][n1], al[1][0], al[1][1], al[1][2], al[1][3], bh[2], bh[3]);
            }
        }
        if (++st == 3) st = 0;
    }

    int rbase = bm + wm * 32 + (lane >> 2);
    int cbase = wn * 64 + (lane & 3) * 2;
#pragma unroll
    for (int mt = 0; mt < 2; mt++) {
#pragma unroll
        for (int nt = 0; nt < 8; nt++) {
            int r = rbase + mt * 16;
            int c = cbase + nt * 8;
            *reinterpret_cast<float2*>(Cf + (size_t)r * 256 + c) =
                make_float2(acc[mt][nt][0], acc[mt][nt][1]);
            *reinterpret_cast<float2*>(Cf + (size_t)(r + 8) * 256 + c) =
                make_float2(acc[mt][nt][2], acc[mt][nt][3]);
        }
    }
}

// ---------------- split-K combine + epilogue ----------------
template <int EPI, int SK>
__global__ void combine_k(const float* __restrict__ part, size_t slice,
                          float* __restrict__ Cf, bf16* __restrict__ Ch, bf16* __restrict__ Cl,
                          const float* __restrict__ bias, int total4) {
    int idx = blockIdx.x * blockDim.x + threadIdx.x;
    if (idx >= total4) return;
    const float4* p4 = reinterpret_cast<const float4*>(part);
    size_t s4 = slice >> 2;
    float4 a = p4[idx];
#pragma unroll
    for (int s = 1; s < SK; s++) {
        float4 b = p4[idx + (size_t)s * s4];
        a.x += b.x; a.y += b.y; a.z += b.z; a.w += b.w;
    }
    float v[4] = {a.x, a.y, a.z, a.w};
    if (EPI == 1 || EPI == 3) {
        int c = (idx * 4) & 255;
        float4 b4 = *reinterpret_cast<const float4*>(bias + c);
        v[0] = selu_f(v[0] + b4.x); v[1] = selu_f(v[1] + b4.y);
        v[2] = selu_f(v[2] + b4.z); v[3] = selu_f(v[3] + b4.w);
    }
    if (EPI >= 2) {
        split_store4(v, Ch + (size_t)idx * 4, Cl + (size_t)idx * 4);
    } else {
        *reinterpret_cast<float4*>(Cf + (size_t)idx * 4) = make_float4(v[0], v[1], v[2], v[3]);
    }
}

// ---------------- fused GAT split-K combine + source/dest reductions ----------------
__global__ void gat_combine_sd(const float* __restrict__ part,
                               const float* __restrict__ asrc, const float* __restrict__ adst) {
    int row = blockIdx.x;
    int t = threadIdx.x;
    size_t off = (size_t)row * HH + t;
    float v = 0.f;
#pragma unroll
    for (int s = 0; s < 8; s++) v += part[(size_t)s * NROWS * HH + off];
    g_hw[off] = v;
    __shared__ float r1[HH], r2[HH];
    r1[t] = v * asrc[t];
    r2[t] = v * adst[t];
    __syncthreads();
    for (int st = 128; st > 0; st >>= 1) {
        if (t < st) { r1[t] += r1[t + st]; r2[t] += r2[t + st]; }
        __syncthreads();
    }
    if (t == 0) { g_s[row] = r1[0]; g_d[row] = r2[0]; }
}

// ---------------- pool + pos (+ adj zero, + split) ----------------
__global__ void pool_pos(const float* __restrict__ y2, const float* __restrict__ pos) {
    int idx = blockIdx.x * blockDim.x + threadIdx.x;
    if (idx < BB * NN) g_adj[idx] = 0ull;
    if (idx >= BB * NN * HH) return;
    int c = idx % HH;
    int n = (idx / HH) % NN;
    int b = idx / (HH * NN);
    float s = 0.f;
#pragma unroll
    for (int t = 0; t < 8; t++) s += y2[((size_t)b * TT + n * 8 + t) * HH + c];
    float v = s * 0.125f + pos[(size_t)n * HH + c];
    size_t o = ((size_t)b * NN + n) * HH + c;
    g_hn[o] = v;
    bf16 h, l;
    split_bf16(v, h, l);
    g_hnh[o] = h; g_hnl[o] = l;
}

// ---------------- adjacency ----------------
__global__ void adj_topk() {
    int b = blockIdx.x / NN, n = blockIdx.x % NN;
    __shared__ float sc[NN];
    int m = threadIdx.x;
    const float* hb = g_hn + (size_t)b * NN * HH;
    float s = 0.f;
    for (int k = 0; k < HH; k++) s = fmaf(hb[(size_t)n * HH + k], hb[(size_t)m * HH + k], s);
    sc[m] = s;
    __syncthreads();
    if (m == 0) {
        unsigned long long mask = 1ull << n;
        int sel[TOPK];
#pragma unroll 1
        for (int it = 0; it < TOPK; it++) {
            float best = -INFINITY; int bi = 0;
            for (int j = 0; j < NN; j++)
                if (sc[j] > best) { best = sc[j]; bi = j; }
            sel[it] = bi;
            sc[bi] = -INFINITY;
            mask |= 1ull << bi;
        }
        atomicOr(&g_adj[b * NN + n], mask);
        for (int it = 0; it < TOPK; it++)
            atomicOr(&g_adj[b * NN + sel[it]], 1ull << n);
    }
}

// ---------------- GAT attention (LAST=1 fuses layernorm, writes g_ln) ----------------
template <int LAST>
__global__ void gat_attn(const float* __restrict__ lng, const float* __restrict__ lnb) {
    int b = blockIdx.x / NN, n = blockIdx.x % NN;
    __shared__ float attn[NN];
    __shared__ float inv_s;
    __shared__ float red[HH];
    __shared__ float mu_s, is_s;
    int t = threadIdx.x;
    unsigned long long mask = g_adj[b * NN + n];
    if (t < NN) {
        float e;
        if ((mask >> t) & 1ull) {
            float z = g_s[b * NN + n] + g_d[b * NN + t];
            e = z >= 0.f ? z : 0.2f * z;
        } else {
            e = -1e9f;
        }
        attn[t] = e;
    }
    __syncthreads();
    if (t == 0) {
        float mx = -INFINITY;
        for (int j = 0; j < NN; j++) mx = fmaxf(mx, attn[j]);
        float sum = 0.f;
        for (int j = 0; j < NN; j++) { float ex = expf(attn[j] - mx); attn[j] = ex; sum += ex; }
        inv_s = 1.f / sum;
    }
    __syncthreads();
    float inv = inv_s;
    float acc = 0.f;
    for (int m = 0; m < NN; m++)
        acc = fmaf(attn[m] * inv, g_hw[((size_t)b * NN + m) * HH + t], acc);
    float o = acc > 0.f ? acc : expm1f(acc);
    size_t oo = ((size_t)b * NN + n) * HH + t;
    float nh = g_hn[oo] + o;
    if (LAST == 0) {
        g_hn[oo] = nh;
        bf16 h, l;
        split_bf16(nh, h, l);
        g_hnh[oo] = h; g_hnl[oo] = l;
    } else {
        // fused layernorm over the 256 channels of this row
        red[t] = nh;
        __syncthreads();
        for (int st = 128; st > 0; st >>= 1) { if (t < st) red[t] += red[t + st]; __syncthreads(); }
        if (t == 0) mu_s = red[0] * (1.f / HH);
        __syncthreads();
        float mu = mu_s;
        float dv = nh - mu;
        red[t] = dv * dv;
        __syncthreads();
        for (int st = 128; st > 0; st >>= 1) { if (t < st) red[t] += red[t + st]; __syncthreads(); }
        if (t == 0) is_s = rsqrtf(red[0] * (1.f / HH) + 1e-5f);
        __syncthreads();
        g_ln[oo] = dv * is_s * lng[t] + lnb[t];
    }
}

// ---------------- fused emb pooling + classifier KAN ----------------
__global__ void emb_cls(const float* __restrict__ cbw, const float* __restrict__ csw,
                        const float* __restrict__ csc, float* __restrict__ out) {
    int b = blockIdx.x;
    int t = threadIdx.x;
    __shared__ float emb[2 * HH];
    __shared__ float r0[256], r1[256];
    {
        float sm = 0.f, mx = -INFINITY;
        const float* lb = g_ln + (size_t)b * NN * HH + t;
        for (int n = 0; n < NN; n++) {
            float v = lb[(size_t)n * HH];
            sm += v;
            mx = fmaxf(mx, v);
        }
        float mean = sm * (1.f / NN);
        emb[t] = mean;
        emb[HH + t] = mx;
        out[BB * NCLS + (size_t)b * (2 * HH) + t] = mean;
        out[BB * NCLS + (size_t)b * (2 * HH) + HH + t] = mx;
    }
    __syncthreads();
    float a0 = 0.f, a1 = 0.f;
    for (int i = t; i < 2 * HH; i += 256) {
        float x = emb[i];
        float sil = silu_f(x);
        float bs[8];
        bsplines8(x, bs);
        float p0 = sil * cbw[i];
        float p1 = sil * cbw[2 * HH + i];
        float s0 = csc[i], s1 = csc[2 * HH + i];
#pragma unroll
        for (int c = 0; c < 8; c++) {
            p0 = fmaf(bs[c] * csw[(size_t)i * 8 + c], s0, p0);
            p1 = fmaf(bs[c] * csw[(size_t)(2 * HH + i) * 8 + c], s1, p1);
        }
        a0 += p0;
        a1 += p1;
    }
    r0[t] = a0; r1[t] = a1;
    __syncthreads();
    for (int st = 128; st > 0; st >>= 1) {
        if (t < st) { r0[t] += r0[t + st]; r1[t] += r1[t + st]; }
        __syncthreads();
    }
    if (t == 0) { out[b * NCLS + 0] = r0[0]; out[b * NCLS + 1] = r1[0]; }
}

// ---------------- host launch ----------------
extern "C" void kernel_launch(void* const* d_in, const int* in_sizes, int n_in,
                              void* d_out, int out_size) {
    const float* x    = (const float*)d_in[0];
    const float* bbw  = (const float*)d_in[1];
    const float* bsw  = (const float*)d_in[2];
    const float* bsc  = (const float*)d_in[3];
    const float* c1w  = (const float*)d_in[4];
    const float* c1b  = (const float*)d_in[5];
    const float* c2w  = (const float*)d_in[6];
    const float* c2b  = (const float*)d_in[7];
    const float* pos  = (const float*)d_in[8];
    const float* gatW = (const float*)d_in[9];
    const float* asrc = (const float*)d_in[10];
    const float* adst = (const float*)d_in[11];
    const float* lng  = (const float*)d_in[12];
    const float* lnb  = (const float*)d_in[13];
    const float* cbw  = (const float*)d_in[14];
    const float* csw  = (const float*)d_in[15];
    const float* csc  = (const float*)d_in[16];
    float* out = (float*)d_out;

    bf16 *pfh, *pfl, *pwh, *pwl, *ph1h, *ph1l, *pwc1h, *pwc1l, *pwc2h, *pwc2l;
    bf16 *py1h, *py1l, *phnh, *phnl, *pwt0h, *pwt0l, *pwt1h, *pwt1l;
    float *py2, *ppart;
    cudaGetSymbolAddress((void**)&pfh, g_fh);
    cudaGetSymbolAddress((void**)&pfl, g_fl);
    cudaGetSymbolAddress((void**)&pwh, g_wh);
    cudaGetSymbolAddress((void**)&pwl, g_wl);
    cudaGetSymbolAddress((void**)&ph1h, g_h1h);
    cudaGetSymbolAddress((void**)&ph1l, g_h1l);
    cudaGetSymbolAddress((void**)&pwc1h, g_wc1h);
    cudaGetSymbolAddress((void**)&pwc1l, g_wc1l);
    cudaGetSymbolAddress((void**)&pwc2h, g_wc2h);
    cudaGetSymbolAddress((void**)&pwc2l, g_wc2l);
    cudaGetSymbolAddress((void**)&py1h, g_y1h);
    cudaGetSymbolAddress((void**)&py1l, g_y1l);
    cudaGetSymbolAddress((void**)&phnh, g_hnh);
    cudaGetSymbolAddress((void**)&phnl, g_hnl);
    cudaGetSymbolAddress((void**)&pwt0h, g_wt0h);
    cudaGetSymbolAddress((void**)&pwt0l, g_wt0l);
    cudaGetSymbolAddress((void**)&pwt1h, g_wt1h);
    cudaGetSymbolAddress((void**)&pwt1l, g_wt1l);
    cudaGetSymbolAddress((void**)&py2, g_y2);
    cudaGetSymbolAddress((void**)&ppart, g_part);

    cudaFuncSetAttribute(gemm_mma<0>, cudaFuncAttributeMaxDynamicSharedMemorySize, GEMM_SMEM);
    cudaFuncSetAttribute(gemm_mma<1>, cudaFuncAttributeMaxDynamicSharedMemorySize, GEMM_SMEM);

    const int TPB = 256;
    const size_t SLICE_BIG = (size_t)MROWS * HH;
    const int T4_BIG = MROWS * HH / 4;

    // prep (5 launches) -> bridge GEMM is launch #6 for ncu -s 5
    bridge_features_bf16<<<MROWS * (DIN / 4) / TPB, TPB>>>(x);                         // 1
    build_wcat_bf16<<<(HH * DIN + TPB - 1) / TPB, TPB>>>(bbw, bsw, bsc);               // 2
    conv_w_bf16<<<(HH * HH + TPB - 1) / TPB, TPB>>>(c1w, pwc1h, pwc1l);                // 3
    conv_w_bf16<<<(HH * HH + TPB - 1) / TPB, TPB>>>(c2w, pwc2h, pwc2l);                // 4
    gatwt_bf16<<<dim3((HH * HH + TPB - 1) / TPB, 2), TPB>>>(gatW);                     // 5

    // bridge GEMM: split-K 2 + combine -> split bf16                                   // 6
    gemm_mma<0><<<dim3(MROWS / 128, 2), 512, GEMM_SMEM>>>(pfh, pfl, pwh, pwl,
                                                          ppart, KBRIDGE, KBRIDGE / 2);
    combine_k<2, 2><<<(T4_BIG + TPB - 1) / TPB, TPB>>>(ppart, SLICE_BIG,
                                                       nullptr, ph1h, ph1l, nullptr, T4_BIG);

    // conv1: split-K 2 + combine -> selu+bias split bf16
    gemm_mma<1><<<dim3(MROWS / 128, 2), 512, GEMM_SMEM>>>(ph1h, ph1l, pwc1h, pwc1l,
                                                          ppart, KCONV, KCONV / 2);
    combine_k<3, 2><<<(T4_BIG + TPB - 1) / TPB, TPB>>>(ppart, SLICE_BIG,
                                                       nullptr, py1h, py1l, c1b, T4_BIG);

    // conv2: split-K 2 + combine -> selu+bias fp32
    gemm_mma<1><<<dim3(MROWS / 128, 2), 512, GEMM_SMEM>>>(py1h, py1l, pwc2h, pwc2l,
                                                          ppart, KCONV, KCONV / 2);
    combine_k<1, 2><<<(T4_BIG + TPB - 1) / TPB, TPB>>>(ppart, SLICE_BIG,
                                                       py2, nullptr, nullptr, c2b, T4_BIG);

    // pool + pos (+ adj zero + split)
    pool_pos<<<(BB * NN * HH + TPB - 1) / TPB, TPB>>>(py2, pos);

    // adjacency
    adj_topk<<<BB * NN, NN>>>();

    // GAT layer 0
    gemm_mma<0><<<dim3(NROWS / 128, 8), 512, GEMM_SMEM>>>(phnh, phnl, pwt0h, pwt0l,
                                                          ppart, HH, HH / 8);
    gat_combine_sd<<<NROWS, HH>>>(ppart, asrc, adst);
    gat_attn<0><<<NROWS, HH>>>(nullptr, nullptr);

    // GAT layer 1 (fused layernorm)
    gemm_mma<0><<<dim3(NROWS / 128, 8), 512, GEMM_SMEM>>>(phnh, phnl, pwt1h, pwt1l,
                                                          ppart, HH, HH / 8);
    gat_combine_sd<<<NROWS, HH>>>(ppart, asrc + HH, adst + HH);
    gat_attn<1><<<NROWS, HH>>>(lng, lnb);

    // fused emb pooling + classifier
    emb_cls<<<BB, 256>>>(cbw, csw, csc, out);
}

// round 15
// speedup vs baseline: 1.2007x; 1.0674x over previous
#include <cuda_runtime.h>
#include <cuda_bf16.h>
#include <math.h>
#include <stdint.h>

typedef __nv_bfloat16 bf16;

// ---------------- problem constants ----------------
#define BB 16
#define TT 512
#define DIN 1024
#define HH 256
#define NN 64
#define TOPK 8
#define NCLS 2
#define KBRIDGE (DIN * 9)      // 9216
#define KCONV (HH * 3)         // 768
#define MROWS (BB * TT)        // 8192
#define NROWS (BB * NN)        // 1024

// ---------------- PTX helpers ----------------
__device__ __forceinline__ uint32_t smem_u32(const void* p) {
    uint32_t a;
    asm("{ .reg .u64 t; cvta.to.shared.u64 t, %1; cvt.u32.u64 %0, t; }" : "=r"(a) : "l"(p));
    return a;
}
#define CP_ASYNC16(dst, src) \
    asm volatile("cp.async.cg.shared.global [%0], [%1], 16;" :: "r"(dst), "l"(src) : "memory")
#define CP_COMMIT() asm volatile("cp.async.commit_group;" ::: "memory")
#define CP_WAIT(N)  asm volatile("cp.async.wait_group %0;" :: "n"(N) : "memory")
#define LDSM_X4(r0, r1, r2, r3, a) \
    asm volatile("ldmatrix.sync.aligned.m8n8.x4.shared.b16 {%0,%1,%2,%3}, [%4];" \
        : "=r"(r0), "=r"(r1), "=r"(r2), "=r"(r3) : "r"(a))
#define MMA_BF16(c, a0, a1, a2, a3, b0, b1) \
    asm volatile("mma.sync.aligned.m16n8k16.row.col.f32.bf16.bf16.f32 " \
        "{%0,%1,%2,%3}, {%4,%5,%6,%7}, {%8,%9}, {%0,%1,%2,%3};" \
        : "+f"((c)[0]), "+f"((c)[1]), "+f"((c)[2]), "+f"((c)[3]) \
        : "r"(a0), "r"(a1), "r"(a2), "r"(a3), "r"(b0), "r"(b1))
#define STS128Z(addr) \
    asm volatile("st.shared.v4.b32 [%0], {%1,%1,%1,%1};" :: "r"(addr), "r"(0u) : "memory")

// ---------------- scratch ----------------
__device__ bf16 g_fh[(size_t)MROWS * KBRIDGE];
__device__ bf16 g_fl[(size_t)MROWS * KBRIDGE];
__device__ bf16 g_wh[HH * KBRIDGE];
__device__ bf16 g_wl[HH * KBRIDGE];
__device__ float g_part[(size_t)4 * MROWS * HH];   // stream-K / split-K partials (32 MB)
__device__ bf16 g_h1h[MROWS * HH];
__device__ bf16 g_h1l[MROWS * HH];
__device__ bf16 g_wc1h[HH * KCONV];
__device__ bf16 g_wc1l[HH * KCONV];
__device__ bf16 g_wc2h[HH * KCONV];
__device__ bf16 g_wc2l[HH * KCONV];
__device__ bf16 g_y1h[MROWS * HH];
__device__ bf16 g_y1l[MROWS * HH];
__device__ float g_y2[MROWS * HH];
__device__ float g_hn[NROWS * HH];
__device__ bf16 g_hnh[NROWS * HH];
__device__ bf16 g_hnl[NROWS * HH];
__device__ bf16 g_wt0h[HH * HH];
__device__ bf16 g_wt0l[HH * HH];
__device__ bf16 g_wt1h[HH * HH];
__device__ bf16 g_wt1l[HH * HH];
__device__ float g_hw[NROWS * HH];
__device__ float g_s[NROWS];
__device__ float g_d[NROWS];
__device__ unsigned long long g_adj[BB * NN];
__device__ float g_ln[NROWS * HH];

// ---------------- math helpers ----------------
__device__ __forceinline__ float silu_f(float x) { return x * (1.f / (1.f + expf(-x))); }
__device__ __forceinline__ float selu_f(float x) {
    const float a = 1.6732632423543772f, s = 1.0507009873554805f;
    return x > 0.f ? s * x : s * a * expm1f(x);
}
__device__ __forceinline__ void split_bf16(float v, bf16& h, bf16& l) {
    h = __float2bfloat16_rn(v);
    l = __float2bfloat16_rn(v - __bfloat162float(h));
}
union Pack4 { bf16 b[4]; uint2 u; };
__device__ __forceinline__ void split_store4(const float* v, bf16* ph, bf16* pl) {
    Pack4 H, L;
#pragma unroll
    for (int j = 0; j < 4; j++) split_bf16(v[j], H.b[j], L.b[j]);
    *reinterpret_cast<uint2*>(ph) = H.u;
    *reinterpret_cast<uint2*>(pl) = L.u;
}
__device__ __forceinline__ void bsplines8(float x, float* out) {
    const float h = 0.4f;
    float b[11];
#pragma unroll
    for (int j = 0; j < 11; j++) {
        float gj = (float)(j - 3) * h - 1.0f;
        float gj1 = (float)(j - 2) * h - 1.0f;
        b[j] = (x >= gj && x < gj1) ? 1.f : 0.f;
    }
#pragma unroll
    for (int k = 1; k <= 3; k++) {
        float inv = 1.f / ((float)k * h);
#pragma unroll
        for (int j = 0; j < 11; j++) {
            if (j < 11 - k) {
                float gj = (float)(j - 3) * h - 1.0f;
                float gjk1 = (float)(j + k - 2) * h - 1.0f;
                b[j] = (x - gj) * inv * b[j] + (gjk1 - x) * inv * b[j + 1];
            }
        }
    }
#pragma unroll
    for (int j = 0; j < 8; j++) out[j] = b[j];
}

// ---------------- prep kernels ----------------
__global__ void bridge_features_bf16(const float* __restrict__ x) {
    int idx = blockIdx.x * blockDim.x + threadIdx.x;
    if (idx >= MROWS * (DIN / 4)) return;
    int r = idx >> 8, i4 = idx & 255;
    float4 xv = *reinterpret_cast<const float4*>(x + (size_t)r * DIN + i4 * 4);
    float vv[4] = {xv.x, xv.y, xv.z, xv.w};
    float f[9][4];
#pragma unroll
    for (int j = 0; j < 4; j++) {
        f[0][j] = silu_f(vv[j]);
        float bs[8];
        bsplines8(vv[j], bs);
#pragma unroll
        for (int c = 0; c < 8; c++) f[c + 1][j] = bs[c];
    }
    size_t base = (size_t)r * KBRIDGE + i4 * 4;
#pragma unroll
    for (int g = 0; g < 9; g++)
        split_store4(f[g], g_fh + base + (size_t)g * DIN, g_fl + base + (size_t)g * DIN);
}

__global__ void build_wcat_bf16(const float* __restrict__ bw, const float* __restrict__ sw,
                                const float* __restrict__ sc) {
    int idx = blockIdx.x * blockDim.x + threadIdx.x;
    if (idx >= HH * DIN) return;
    int i = idx % DIN, o = idx / DIN;
    size_t base = (size_t)o * KBRIDGE + i;
    bf16 h, l;
    split_bf16(bw[idx], h, l);
    g_wh[base] = h; g_wl[base] = l;
    float scale = sc[idx];
#pragma unroll
    for (int c = 0; c < 8; c++) {
        split_bf16(sw[(size_t)idx * 8 + c] * scale, h, l);
        size_t p = base + (size_t)(c + 1) * DIN;
        g_wh[p] = h; g_wl[p] = l;
    }
}

__global__ void conv_w_bf16(const float* __restrict__ w, bf16* __restrict__ wh, bf16* __restrict__ wl) {
    int idx = blockIdx.x * blockDim.x + threadIdx.x;
    if (idx >= HH * HH) return;
    int i = idx % HH, o = idx / HH;
#pragma unroll
    for (int j = 0; j < 3; j++) {
        bf16 h, l;
        split_bf16(w[((size_t)o * HH + i) * 3 + j], h, l);
        size_t p = (size_t)o * KCONV + j * HH + i;
        wh[p] = h; wl[p] = l;
    }
}

__global__ void gatwt_bf16(const float* __restrict__ w) {
    int idx = blockIdx.x * blockDim.x + threadIdx.x;
    if (idx >= HH * HH) return;
    int L = blockIdx.y;
    int k = idx % HH, n = idx / HH;
    bf16 h, l;
    split_bf16(w[(size_t)L * HH * HH + (size_t)k * HH + n], h, l);
    if (L == 0) { g_wt0h[idx] = h; g_wt0l[idx] = l; }
    else        { g_wt1h[idx] = h; g_wt1l[idx] = l; }
}

// zero slot-3 plane of the stream-K partial buffer (only slot that may go unwritten)
__global__ void zero_slot3() {
    int idx = blockIdx.x * blockDim.x + threadIdx.x;
    if (idx < MROWS * HH / 4)
        reinterpret_cast<float4*>(g_part + (size_t)3 * MROWS * HH)[idx] =
            make_float4(0.f, 0.f, 0.f, 0.f);
}

// ===== shared GEMM config: 512 thr, warp tile 32x64, 3-stage, 1 barrier/chunk =====
#define BKS 32
#define SROWS 80
#define AS_STG (128 * SROWS)
#define BS_STG (256 * SROWS)
#define STG_TOT (2 * AS_STG + 2 * BS_STG)
#define GEMM_SMEM (3 * STG_TOT)

// ---------------- generic split-K GEMM (convs + GAT) ----------------
template <int SHIFT>
__global__ __launch_bounds__(512, 1) void gemm_mma(
    const bf16* __restrict__ Ah, const bf16* __restrict__ Al,
    const bf16* __restrict__ Bh, const bf16* __restrict__ Bl,
    float* __restrict__ Cpart, int K, int kLen) {
    extern __shared__ char smem[];
    uint32_t s0 = smem_u32(smem);

    int tid = threadIdx.x, lane = tid & 31, wid = tid >> 5;
    int wm = wid & 3, wn = wid >> 2;
    int bm = blockIdx.x * 128;
    int kOff = blockIdx.y * kLen;
    float* Cf = Cpart + (size_t)blockIdx.y * gridDim.x * 128 * 256;
    const int nc = kLen / BKS;

    int aRow = wm * 32 + (lane & 15);
    int aCol = (lane >> 4) * 8;
    int bRow = wn * 64 + (lane & 7) + ((lane >> 4) << 3);
    int bCol = ((lane >> 3) & 1) * 8;

    float acc[2][8][4];
#pragma unroll
    for (int i = 0; i < 2; i++)
#pragma unroll
        for (int j = 0; j < 8; j++)
#pragma unroll
            for (int q = 0; q < 4; q++) acc[i][j][q] = 0.f;

    auto issue = [&](int st, int k0) {
        uint32_t sb = s0 + (uint32_t)(st * STG_TOT);
        {
            int r = tid >> 2, c = tid & 3;
            uint32_t dh = sb + (uint32_t)(r * SROWS + c * 16);
            uint32_t dl = dh + AS_STG;
            if (SHIFT) {
                int k = kOff + k0 + c * 8;
                int j = k >> 8, cc = k & 255;
                int grow = bm + r;
                int tj = (grow & 511) + j - 1;
                if (tj >= 0 && tj < 512) {
                    size_t go = (size_t)(grow + j - 1) * 256 + cc;
                    CP_ASYNC16(dh, Ah + go);
                    CP_ASYNC16(dl, Al + go);
                } else {
                    STS128Z(dh);
                    STS128Z(dl);
                }
            } else {
                size_t go = (size_t)(bm + r) * K + kOff + k0 + c * 8;
                CP_ASYNC16(dh, Ah + go);
                CP_ASYNC16(dl, Al + go);
            }
        }
#pragma unroll
        for (int i = 0; i < 2; i++) {
            int q = i * 512 + tid;
            int r = q >> 2, c = q & 3;
            uint32_t d = sb + (uint32_t)(2 * AS_STG + r * SROWS + c * 16);
            size_t go = (size_t)r * K + kOff + k0 + c * 8;
            CP_ASYNC16(d, Bh + go);
            CP_ASYNC16(d + BS_STG, Bl + go);
        }
    };

    issue(0, 0);
    CP_COMMIT();
    if (nc > 1) { issue(1, BKS); CP_COMMIT(); }

    int st = 0;
    for (int kc = 0; kc < nc; kc++) {
        if (kc + 1 < nc) { CP_WAIT(1); } else { CP_WAIT(0); }
        __syncthreads();
        if (kc + 2 < nc) {
            int nst = st + 2; if (nst >= 3) nst -= 3;
            issue(nst, (kc + 2) * BKS);
            CP_COMMIT();
        }
        uint32_t sb = s0 + (uint32_t)(st * STG_TOT);
        uint32_t sAh = sb, sAl = sb + AS_STG;
        uint32_t sBh = sb + 2 * AS_STG, sBl = sBh + BS_STG;
#pragma unroll
        for (int kk = 0; kk < 2; kk++) {
            uint32_t ah[2][4], al[2][4];
#pragma unroll
            for (int mt = 0; mt < 2; mt++) {
                uint32_t ao = (uint32_t)((aRow + mt * 16) * SROWS + (aCol + kk * 16) * 2);
                LDSM_X4(ah[mt][0], ah[mt][1], ah[mt][2], ah[mt][3], sAh + ao);
                LDSM_X4(al[mt][0], al[mt][1], al[mt][2], al[mt][3], sAl + ao);
            }
#pragma unroll
            for (int nt2 = 0; nt2 < 4; nt2++) {
                uint32_t bo = (uint32_t)((bRow + nt2 * 16) * SROWS + (bCol + kk * 16) * 2);
                uint32_t bh[4], bl[4];
                LDSM_X4(bh[0], bh[1], bh[2], bh[3], sBh + bo);
                LDSM_X4(bl[0], bl[1], bl[2], bl[3], sBl + bo);
                int n0 = nt2 * 2, n1 = n0 + 1;
                MMA_BF16(acc[0][n0], ah[0][0], ah[0][1], ah[0][2], ah[0][3], bh[0], bh[1]);
                MMA_BF16(acc[0][n1], ah[0][0], ah[0][1], ah[0][2], ah[0][3], bh[2], bh[3]);
                MMA_BF16(acc[1][n0], ah[1][0], ah[1][1], ah[1][2], ah[1][3], bh[0], bh[1]);
                MMA_BF16(acc[1][n1], ah[1][0], ah[1][1], ah[1][2], ah[1][3], bh[2], bh[3]);
                MMA_BF16(acc[0][n0], ah[0][0], ah[0][1], ah[0][2], ah[0][3], bl[0], bl[1]);
                MMA_BF16(acc[0][n1], ah[0][0], ah[0][1], ah[0][2], ah[0][3], bl[2], bl[3]);
                MMA_BF16(acc[1][n0], ah[1][0], ah[1][1], ah[1][2], ah[1][3], bl[0], bl[1]);
                MMA_BF16(acc[1][n1], ah[1][0], ah[1][1], ah[1][2], ah[1][3], bl[2], bl[3]);
                MMA_BF16(acc[0][n0], al[0][0], al[0][1], al[0][2], al[0][3], bh[0], bh[1]);
                MMA_BF16(acc[0][n1], al[0][0], al[0][1], al[0][2], al[0][3], bh[2], bh[3]);
                MMA_BF16(acc[1][n0], al[1][0], al[1][1], al[1][2], al[1][3], bh[0], bh[1]);
                MMA_BF16(acc[1][n1], al[1][0], al[1][1], al[1][2], al[1][3], bh[2], bh[3]);
            }
        }
        if (++st == 3) st = 0;
    }

    int rbase = bm + wm * 32 + (lane >> 2);
    int cbase = wn * 64 + (lane & 3) * 2;
#pragma unroll
    for (int mt = 0; mt < 2; mt++) {
#pragma unroll
        for (int nt = 0; nt < 8; nt++) {
            int r = rbase + mt * 16;
            int c = cbase + nt * 8;
            *reinterpret_cast<float2*>(Cf + (size_t)r * 256 + c) =
                make_float2(acc[mt][nt][0], acc[mt][nt][1]);
            *reinterpret_cast<float2*>(Cf + (size_t)(r + 8) * 256 + c) =
                make_float2(acc[mt][nt][2], acc[mt][nt][3]);
        }
    }
}

// ---------------- stream-K bridge GEMM ----------------
// 64 m-tiles x 288 chunks = 18432 units over 148 CTAs (80x125 + 68x124).
// Each CTA: <=2 fragments; each m-tile: 3-4 fragments at deterministic slots.
// Slot plane layout: ((slot*64 + m)*128 + local_row)*256 + col == row-major
// over global rows within each slot plane, so combine_k<.,4> works unchanged.
#define SK_G 148
#define SK_NC 288
#define SK_MT 64
__device__ __forceinline__ int sk_start(int c) {
    return c < 80 ? 125 * c : 10000 + 124 * (c - 80);
}
__device__ __forceinline__ int sk_cta_of(int u) {
    return u < 10000 ? u / 125 : 80 + (u - 10000) / 124;
}

__global__ __launch_bounds__(512, 1) void gemm_bridge_sk(
    const bf16* __restrict__ Ah, const bf16* __restrict__ Al,
    const bf16* __restrict__ Bh, const bf16* __restrict__ Bl) {
    extern __shared__ char smem[];
    uint32_t s0 = smem_u32(smem);

    int tid = threadIdx.x, lane = tid & 31, wid = tid >> 5;
    int wm = wid & 3, wn = wid >> 2;
    int ctaid = blockIdx.x;
    int s = sk_start(ctaid);
    int e = sk_start(ctaid + 1);

    int aRow = wm * 32 + (lane & 15);
    int aCol = (lane >> 4) * 8;
    int bRow = wn * 64 + (lane & 7) + ((lane >> 4) << 3);
    int bCol = ((lane >> 3) & 1) * 8;

    int u = s;
    while (u < e) {
        int m = u / SK_NC;
        int cend = min(e, (m + 1) * SK_NC);
        int nc = cend - u;
        int kOff = (u - m * SK_NC) * BKS;
        int bm = m * 128;
        int slot = ctaid - sk_cta_of(m * SK_NC);
        float* Cf = g_part + ((size_t)slot * SK_MT + m) * 128 * 256;

        float acc[2][8][4];
#pragma unroll
        for (int i = 0; i < 2; i++)
#pragma unroll
            for (int j = 0; j < 8; j++)
#pragma unroll
                for (int q = 0; q < 4; q++) acc[i][j][q] = 0.f;

        auto issue = [&](int st, int k0) {
            uint32_t sb = s0 + (uint32_t)(st * STG_TOT);
            {
                int r = tid >> 2, c = tid & 3;
                uint32_t dh = sb + (uint32_t)(r * SROWS + c * 16);
                size_t go = (size_t)(bm + r) * KBRIDGE + kOff + k0 + c * 8;
                CP_ASYNC16(dh, Ah + go);
                CP_ASYNC16(dh + AS_STG, Al + go);
            }
#pragma unroll
            for (int i = 0; i < 2; i++) {
                int q = i * 512 + tid;
                int r = q >> 2, c = q & 3;
                uint32_t d = sb + (uint32_t)(2 * AS_STG + r * SROWS + c * 16);
                size_t go = (size_t)r * KBRIDGE + kOff + k0 + c * 8;
                CP_ASYNC16(d, Bh + go);
                CP_ASYNC16(d + BS_STG, Bl + go);
            }
        };

        issue(0, 0);
        CP_COMMIT();
        if (nc > 1) { issue(1, BKS); CP_COMMIT(); }

        int st = 0;
        for (int kc = 0; kc < nc; kc++) {
            if (kc + 1 < nc) { CP_WAIT(1); } else { CP_WAIT(0); }
            __syncthreads();
            if (kc + 2 < nc) {
                int nst = st + 2; if (nst >= 3) nst -= 3;
                issue(nst, (kc + 2) * BKS);
                CP_COMMIT();
            }
            uint32_t sb = s0 + (uint32_t)(st * STG_TOT);
            uint32_t sAh = sb, sAl = sb + AS_STG;
            uint32_t sBh = sb + 2 * AS_STG, sBl = sBh + BS_STG;
#pragma unroll
            for (int kk = 0; kk < 2; kk++) {
                uint32_t ah[2][4], al[2][4];
#pragma unroll
                for (int mt = 0; mt < 2; mt++) {
                    uint32_t ao = (uint32_t)((aRow + mt * 16) * SROWS + (aCol + kk * 16) * 2);
                    LDSM_X4(ah[mt][0], ah[mt][1], ah[mt][2], ah[mt][3], sAh + ao);
                    LDSM_X4(al[mt][0], al[mt][1], al[mt][2], al[mt][3], sAl + ao);
                }
#pragma unroll
                for (int nt2 = 0; nt2 < 4; nt2++) {
                    uint32_t bo = (uint32_t)((bRow + nt2 * 16) * SROWS + (bCol + kk * 16) * 2);
                    uint32_t bh[4], bl[4];
                    LDSM_X4(bh[0], bh[1], bh[2], bh[3], sBh + bo);
                    LDSM_X4(bl[0], bl[1], bl[2], bl[3], sBl + bo);
                    int n0 = nt2 * 2, n1 = n0 + 1;
                    MMA_BF16(acc[0][n0], ah[0][0], ah[0][1], ah[0][2], ah[0][3], bh[0], bh[1]);
                    MMA_BF16(acc[0][n1], ah[0][0], ah[0][1], ah[0][2], ah[0][3], bh[2], bh[3]);
                    MMA_BF16(acc[1][n0], ah[1][0], ah[1][1], ah[1][2], ah[1][3], bh[0], bh[1]);
                    MMA_BF16(acc[1][n1], ah[1][0], ah[1][1], ah[1][2], ah[1][3], bh[2], bh[3]);
                    MMA_BF16(acc[0][n0], ah[0][0], ah[0][1], ah[0][2], ah[0][3], bl[0], bl[1]);
                    MMA_BF16(acc[0][n1], ah[0][0], ah[0][1], ah[0][2], ah[0][3], bl[2], bl[3]);
                    MMA_BF16(acc[1][n0], ah[1][0], ah[1][1], ah[1][2], ah[1][3], bl[0], bl[1]);
                    MMA_BF16(acc[1][n1], ah[1][0], ah[1][1], ah[1][2], ah[1][3], bl[2], bl[3]);
                    MMA_BF16(acc[0][n0], al[0][0], al[0][1], al[0][2], al[0][3], bh[0], bh[1]);
                    MMA_BF16(acc[0][n1], al[0][0], al[0][1], al[0][2], al[0][3], bh[2], bh[3]);
                    MMA_BF16(acc[1][n0], al[1][0], al[1][1], al[1][2], al[1][3], bh[0], bh[1]);
                    MMA_BF16(acc[1][n1], al[1][0], al[1][1], al[1][2], al[1][3], bh[2], bh[3]);
                }
            }
            if (++st == 3) st = 0;
        }
        __syncthreads();   // protect smem stages before next fragment's issue(0)

        // epilogue: LOCAL rows (Cf already includes the tile offset)
        int rbase = wm * 32 + (lane >> 2);
        int cbase = wn * 64 + (lane & 3) * 2;
#pragma unroll
        for (int mt = 0; mt < 2; mt++) {
#pragma unroll
            for (int nt = 0; nt < 8; nt++) {
                int r = rbase + mt * 16;
                int c = cbase + nt * 8;
                *reinterpret_cast<float2*>(Cf + (size_t)r * 256 + c) =
                    make_float2(acc[mt][nt][0], acc[mt][nt][1]);
                *reinterpret_cast<float2*>(Cf + (size_t)(r + 8) * 256 + c) =
                    make_float2(acc[mt][nt][2], acc[mt][nt][3]);
            }
        }
        u = cend;
    }
}

// ---------------- split-K combine + epilogue ----------------
template <int EPI, int SK>
__global__ void combine_k(const float* __restrict__ part, size_t slice,
                          float* __restrict__ Cf, bf16* __restrict__ Ch, bf16* __restrict__ Cl,
                          const float* __restrict__ bias, int total4) {
    int idx = blockIdx.x * blockDim.x + threadIdx.x;
    if (idx >= total4) return;
    const float4* p4 = reinterpret_cast<const float4*>(part);
    size_t s4 = slice >> 2;
    float4 a = p4[idx];
#pragma unroll
    for (int s = 1; s < SK; s++) {
        float4 b = p4[idx + (size_t)s * s4];
        a.x += b.x; a.y += b.y; a.z += b.z; a.w += b.w;
    }
    float v[4] = {a.x, a.y, a.z, a.w};
    if (EPI == 1 || EPI == 3) {
        int c = (idx * 4) & 255;
        float4 b4 = *reinterpret_cast<const float4*>(bias + c);
        v[0] = selu_f(v[0] + b4.x); v[1] = selu_f(v[1] + b4.y);
        v[2] = selu_f(v[2] + b4.z); v[3] = selu_f(v[3] + b4.w);
    }
    if (EPI >= 2) {
        split_store4(v, Ch + (size_t)idx * 4, Cl + (size_t)idx * 4);
    } else {
        *reinterpret_cast<float4*>(Cf + (size_t)idx * 4) = make_float4(v[0], v[1], v[2], v[3]);
    }
}

// ---------------- fused GAT split-K combine + source/dest reductions ----------------
__global__ void gat_combine_sd(const float* __restrict__ part,
                               const float* __restrict__ asrc, const float* __restrict__ adst) {
    int row = blockIdx.x;
    int t = threadIdx.x;
    size_t off = (size_t)row * HH + t;
    float v = 0.f;
#pragma unroll
    for (int s = 0; s < 8; s++) v += part[(size_t)s * NROWS * HH + off];
    g_hw[off] = v;
    __shared__ float r1[HH], r2[HH];
    r1[t] = v * asrc[t];
    r2[t] = v * adst[t];
    __syncthreads();
    for (int st = 128; st > 0; st >>= 1) {
        if (t < st) { r1[t] += r1[t + st]; r2[t] += r2[t + st]; }
        __syncthreads();
    }
    if (t == 0) { g_s[row] = r1[0]; g_d[row] = r2[0]; }
}

// ---------------- pool + pos (+ adj zero, + split) ----------------
__global__ void pool_pos(const float* __restrict__ y2, const float* __restrict__ pos) {
    int idx = blockIdx.x * blockDim.x + threadIdx.x;
    if (idx < BB * NN) g_adj[idx] = 0ull;
    if (idx >= BB * NN * HH) return;
    int c = idx % HH;
    int n = (idx / HH) % NN;
    int b = idx / (HH * NN);
    float s = 0.f;
#pragma unroll
    for (int t = 0; t < 8; t++) s += y2[((size_t)b * TT + n * 8 + t) * HH + c];
    float v = s * 0.125f + pos[(size_t)n * HH + c];
    size_t o = ((size_t)b * NN + n) * HH + c;
    g_hn[o] = v;
    bf16 h, l;
    split_bf16(v, h, l);
    g_hnh[o] = h; g_hnl[o] = l;
}

// ---------------- adjacency ----------------
__global__ void adj_topk() {
    int b = blockIdx.x / NN, n = blockIdx.x % NN;
    __shared__ float sc[NN];
    int m = threadIdx.x;
    const float* hb = g_hn + (size_t)b * NN * HH;
    float s = 0.f;
    for (int k = 0; k < HH; k++) s = fmaf(hb[(size_t)n * HH + k], hb[(size_t)m * HH + k], s);
    sc[m] = s;
    __syncthreads();
    if (m == 0) {
        unsigned long long mask = 1ull << n;
        int sel[TOPK];
#pragma unroll 1
        for (int it = 0; it < TOPK; it++) {
            float best = -INFINITY; int bi = 0;
            for (int j = 0; j < NN; j++)
                if (sc[j] > best) { best = sc[j]; bi = j; }
            sel[it] = bi;
            sc[bi] = -INFINITY;
            mask |= 1ull << bi;
        }
        atomicOr(&g_adj[b * NN + n], mask);
        for (int it = 0; it < TOPK; it++)
            atomicOr(&g_adj[b * NN + sel[it]], 1ull << n);
    }
}

// ---------------- GAT attention (LAST=1 fuses layernorm) ----------------
template <int LAST>
__global__ void gat_attn(const float* __restrict__ lng, const float* __restrict__ lnb) {
    int b = blockIdx.x / NN, n = blockIdx.x % NN;
    __shared__ float attn[NN];
    __shared__ float inv_s;
    __shared__ float red[HH];
    __shared__ float mu_s, is_s;
    int t = threadIdx.x;
    unsigned long long mask = g_adj[b * NN + n];
    if (t < NN) {
        float e;
        if ((mask >> t) & 1ull) {
            float z = g_s[b * NN + n] + g_d[b * NN + t];
            e = z >= 0.f ? z : 0.2f * z;
        } else {
            e = -1e9f;
        }
        attn[t] = e;
    }
    __syncthreads();
    if (t == 0) {
        float mx = -INFINITY;
        for (int j = 0; j < NN; j++) mx = fmaxf(mx, attn[j]);
        float sum = 0.f;
        for (int j = 0; j < NN; j++) { float ex = expf(attn[j] - mx); attn[j] = ex; sum += ex; }
        inv_s = 1.f / sum;
    }
    __syncthreads();
    float inv = inv_s;
    float acc = 0.f;
    for (int m = 0; m < NN; m++)
        acc = fmaf(attn[m] * inv, g_hw[((size_t)b * NN + m) * HH + t], acc);
    float o = acc > 0.f ? acc : expm1f(acc);
    size_t oo = ((size_t)b * NN + n) * HH + t;
    float nh = g_hn[oo] + o;
    if (LAST == 0) {
        g_hn[oo] = nh;
        bf16 h, l;
        split_bf16(nh, h, l);
        g_hnh[oo] = h; g_hnl[oo] = l;
    } else {
        red[t] = nh;
        __syncthreads();
        for (int st = 128; st > 0; st >>= 1) { if (t < st) red[t] += red[t + st]; __syncthreads(); }
        if (t == 0) mu_s = red[0] * (1.f / HH);
        __syncthreads();
        float mu = mu_s;
        float dv = nh - mu;
        red[t] = dv * dv;
        __syncthreads();
        for (int st = 128; st > 0; st >>= 1) { if (t < st) red[t] += red[t + st]; __syncthreads(); }
        if (t == 0) is_s = rsqrtf(red[0] * (1.f / HH) + 1e-5f);
        __syncthreads();
        g_ln[oo] = dv * is_s * lng[t] + lnb[t];
    }
}

// ---------------- fused emb pooling + classifier KAN ----------------
__global__ void emb_cls(const float* __restrict__ cbw, const float* __restrict__ csw,
                        const float* __restrict__ csc, float* __restrict__ out) {
    int b = blockIdx.x;
    int t = threadIdx.x;
    __shared__ float emb[2 * HH];
    __shared__ float r0[256], r1[256];
    {
        float sm = 0.f, mx = -INFINITY;
        const float* lb = g_ln + (size_t)b * NN * HH + t;
        for (int n = 0; n < NN; n++) {
            float v = lb[(size_t)n * HH];
            sm += v;
            mx = fmaxf(mx, v);
        }
        float mean = sm * (1.f / NN);
        emb[t] = mean;
        emb[HH + t] = mx;
        out[BB * NCLS + (size_t)b * (2 * HH) + t] = mean;
        out[BB * NCLS + (size_t)b * (2 * HH) + HH + t] = mx;
    }
    __syncthreads();
    float a0 = 0.f, a1 = 0.f;
    for (int i = t; i < 2 * HH; i += 256) {
        float x = emb[i];
        float sil = silu_f(x);
        float bs[8];
        bsplines8(x, bs);
        float p0 = sil * cbw[i];
        float p1 = sil * cbw[2 * HH + i];
        float s0 = csc[i], s1 = csc[2 * HH + i];
#pragma unroll
        for (int c = 0; c < 8; c++) {
            p0 = fmaf(bs[c] * csw[(size_t)i * 8 + c], s0, p0);
            p1 = fmaf(bs[c] * csw[(size_t)(2 * HH + i) * 8 + c], s1, p1);
        }
        a0 += p0;
        a1 += p1;
    }
    r0[t] = a0; r1[t] = a1;
    __syncthreads();
    for (int st = 128; st > 0; st >>= 1) {
        if (t < st) { r0[t] += r0[t + st]; r1[t] += r1[t + st]; }
        __syncthreads();
    }
    if (t == 0) { out[b * NCLS + 0] = r0[0]; out[b * NCLS + 1] = r1[0]; }
}

// ---------------- host launch ----------------
extern "C" void kernel_launch(void* const* d_in, const int* in_sizes, int n_in,
                              void* d_out, int out_size) {
    const float* x    = (const float*)d_in[0];
    const float* bbw  = (const float*)d_in[1];
    const float* bsw  = (const float*)d_in[2];
    const float* bsc  = (const float*)d_in[3];
    const float* c1w  = (const float*)d_in[4];
    const float* c1b  = (const float*)d_in[5];
    const float* c2w  = (const float*)d_in[6];
    const float* c2b  = (const float*)d_in[7];
    const float* pos  = (const float*)d_in[8];
    const float* gatW = (const float*)d_in[9];
    const float* asrc = (const float*)d_in[10];
    const float* adst = (const float*)d_in[11];
    const float* lng  = (const float*)d_in[12];
    const float* lnb  = (const float*)d_in[13];
    const float* cbw  = (const float*)d_in[14];
    const float* csw  = (const float*)d_in[15];
    const float* csc  = (const float*)d_in[16];
    float* out = (float*)d_out;

    bf16 *pfh, *pfl, *pwh, *pwl, *ph1h, *ph1l, *pwc1h, *pwc1l, *pwc2h, *pwc2l;
    bf16 *py1h, *py1l, *phnh, *phnl, *pwt0h, *pwt0l, *pwt1h, *pwt1l;
    float *py2, *ppart;
    cudaGetSymbolAddress((void**)&pfh, g_fh);
    cudaGetSymbolAddress((void**)&pfl, g_fl);
    cudaGetSymbolAddress((void**)&pwh, g_wh);
    cudaGetSymbolAddress((void**)&pwl, g_wl);
    cudaGetSymbolAddress((void**)&ph1h, g_h1h);
    cudaGetSymbolAddress((void**)&ph1l, g_h1l);
    cudaGetSymbolAddress((void**)&pwc1h, g_wc1h);
    cudaGetSymbolAddress((void**)&pwc1l, g_wc1l);
    cudaGetSymbolAddress((void**)&pwc2h, g_wc2h);
    cudaGetSymbolAddress((void**)&pwc2l, g_wc2l);
    cudaGetSymbolAddress((void**)&py1h, g_y1h);
    cudaGetSymbolAddress((void**)&py1l, g_y1l);
    cudaGetSymbolAddress((void**)&phnh, g_hnh);
    cudaGetSymbolAddress((void**)&phnl, g_hnl);
    cudaGetSymbolAddress((void**)&pwt0h, g_wt0h);
    cudaGetSymbolAddress((void**)&pwt0l, g_wt0l);
    cudaGetSymbolAddress((void**)&pwt1h, g_wt1h);
    cudaGetSymbolAddress((void**)&pwt1l, g_wt1l);
    cudaGetSymbolAddress((void**)&py2, g_y2);
    cudaGetSymbolAddress((void**)&ppart, g_part);

    cudaFuncSetAttribute(gemm_bridge_sk, cudaFuncAttributeMaxDynamicSharedMemorySize, GEMM_SMEM);
    cudaFuncSetAttribute(gemm_mma<0>, cudaFuncAttributeMaxDynamicSharedMemorySize, GEMM_SMEM);
    cudaFuncSetAttribute(gemm_mma<1>, cudaFuncAttributeMaxDynamicSharedMemorySize, GEMM_SMEM);

    const int TPB = 256;
    const size_t SLICE_BIG = (size_t)MROWS * HH;
    const int T4_BIG = MROWS * HH / 4;

    // prep
    bridge_features_bf16<<<MROWS * (DIN / 4) / TPB, TPB>>>(x);
    build_wcat_bf16<<<(HH * DIN + TPB - 1) / TPB, TPB>>>(bbw, bsw, bsc);
    conv_w_bf16<<<(HH * HH + TPB - 1) / TPB, TPB>>>(c1w, pwc1h, pwc1l);
    conv_w_bf16<<<(HH * HH + TPB - 1) / TPB, TPB>>>(c2w, pwc2h, pwc2l);
    gatwt_bf16<<<dim3((HH * HH + TPB - 1) / TPB, 2), TPB>>>(gatW);
    zero_slot3<<<(MROWS * HH / 4 + TPB - 1) / TPB, TPB>>>();

    // bridge GEMM: stream-K over 148 CTAs + 4-slot combine -> split bf16
    gemm_bridge_sk<<<SK_G, 512, GEMM_SMEM>>>(pfh, pfl, pwh, pwl);
    combine_k<2, 4><<<(T4_BIG + TPB - 1) / TPB, TPB>>>(ppart, SLICE_BIG,
                                                       nullptr, ph1h, ph1l, nullptr, T4_BIG);

    // conv1: split-K 2 + combine -> selu+bias split bf16
    gemm_mma<1><<<dim3(MROWS / 128, 2), 512, GEMM_SMEM>>>(ph1h, ph1l, pwc1h, pwc1l,
                                                          ppart, KCONV, KCONV / 2);
    combine_k<3, 2><<<(T4_BIG + TPB - 1) / TPB, TPB>>>(ppart, SLICE_BIG,
                                                       nullptr, py1h, py1l, c1b, T4_BIG);

    // conv2: split-K 2 + combine -> selu+bias fp32
    gemm_mma<1><<<dim3(MROWS / 128, 2), 512, GEMM_SMEM>>>(py1h, py1l, pwc2h, pwc2l,
                                                          ppart, KCONV, KCONV / 2);
    combine_k<1, 2><<<(T4_BIG + TPB - 1) / TPB, TPB>>>(ppart, SLICE_BIG,
                                                       py2, nullptr, nullptr, c2b, T4_BIG);

    // pool + pos (+ adj zero + split)
    pool_pos<<<(BB * NN * HH + TPB - 1) / TPB, TPB>>>(py2, pos);

    // adjacency
    adj_topk<<<BB * NN, NN>>>();

    // GAT layer 0
    gemm_mma<0><<<dim3(NROWS / 128, 8), 512, GEMM_SMEM>>>(phnh, phnl, pwt0h, pwt0l,
                                                          ppart, HH, HH / 8);
    gat_combine_sd<<<NROWS, HH>>>(ppart, asrc, adst);
    gat_attn<0><<<NROWS, HH>>>(nullptr, nullptr);

    // GAT layer 1 (fused layernorm)
    gemm_mma<0><<<dim3(NROWS / 128, 8), 512, GEMM_SMEM>>>(phnh, phnl, pwt1h, pwt1l,
                                                          ppart, HH, HH / 8);
    gat_combine_sd<<<NROWS, HH>>>(ppart, asrc + HH, adst + HH);
    gat_attn<1><<<NROWS, HH>>>(lng, lnb);

    // fused emb pooling + classifier
    emb_cls<<<BB, 256>>>(cbw, csw, csc, out);
}

// round 17
// speedup vs baseline: 1.2191x; 1.0153x over previous
#include <cuda_runtime.h>
#include <cuda_bf16.h>
#include <math.h>
#include <stdint.h>

typedef __nv_bfloat16 bf16;

// ---------------- problem constants ----------------
#define BB 16
#define TT 512
#define DIN 1024
#define HH 256
#define NN 64
#define TOPK 8
#define NCLS 2
#define KBRIDGE (DIN * 9)      // 9216
#define KCONV (HH * 3)         // 768
#define MROWS (BB * TT)        // 8192
#define NROWS (BB * NN)        // 1024

// ---------------- PTX helpers ----------------
__device__ __forceinline__ uint32_t smem_u32(const void* p) {
    uint32_t a;
    asm("{ .reg .u64 t; cvta.to.shared.u64 t, %1; cvt.u32.u64 %0, t; }" : "=r"(a) : "l"(p));
    return a;
}
#define CP_ASYNC16(dst, src) \
    asm volatile("cp.async.cg.shared.global [%0], [%1], 16;" :: "r"(dst), "l"(src) : "memory")
#define CP_COMMIT() asm volatile("cp.async.commit_group;" ::: "memory")
#define CP_WAIT(N)  asm volatile("cp.async.wait_group %0;" :: "n"(N) : "memory")
#define LDSM_X4(r0, r1, r2, r3, a) \
    asm volatile("ldmatrix.sync.aligned.m8n8.x4.shared.b16 {%0,%1,%2,%3}, [%4];" \
        : "=r"(r0), "=r"(r1), "=r"(r2), "=r"(r3) : "r"(a))
#define MMA_BF16(c, a0, a1, a2, a3, b0, b1) \
    asm volatile("mma.sync.aligned.m16n8k16.row.col.f32.bf16.bf16.f32 " \
        "{%0,%1,%2,%3}, {%4,%5,%6,%7}, {%8,%9}, {%0,%1,%2,%3};" \
        : "+f"((c)[0]), "+f"((c)[1]), "+f"((c)[2]), "+f"((c)[3]) \
        : "r"(a0), "r"(a1), "r"(a2), "r"(a3), "r"(b0), "r"(b1))
#define STS128Z(addr) \
    asm volatile("st.shared.v4.b32 [%0], {%1,%1,%1,%1};" :: "r"(addr), "r"(0u) : "memory")

// ---------------- scratch ----------------
__device__ bf16 g_fh[(size_t)MROWS * KBRIDGE];
__device__ bf16 g_fl[(size_t)MROWS * KBRIDGE];
__device__ bf16 g_wh[HH * KBRIDGE];
__device__ bf16 g_wl[HH * KBRIDGE];
__device__ float g_part[(size_t)4 * MROWS * HH];   // stream-K / split-K partials (32 MB)
__device__ bf16 g_h1h[MROWS * HH];
__device__ bf16 g_h1l[MROWS * HH];
__device__ bf16 g_wc1h[HH * KCONV];
__device__ bf16 g_wc1l[HH * KCONV];
__device__ bf16 g_wc2h[HH * KCONV];
__device__ bf16 g_wc2l[HH * KCONV];
__device__ bf16 g_y1h[MROWS * HH];
__device__ bf16 g_y1l[MROWS * HH];
__device__ float g_y2[MROWS * HH];
__device__ float g_hn[NROWS * HH];
__device__ bf16 g_hnh[NROWS * HH];
__device__ bf16 g_hnl[NROWS * HH];
__device__ bf16 g_wt0h[HH * HH];
__device__ bf16 g_wt0l[HH * HH];
__device__ bf16 g_wt1h[HH * HH];
__device__ bf16 g_wt1l[HH * HH];
__device__ float g_hw[NROWS * HH];
__device__ float g_s[NROWS];
__device__ float g_d[NROWS];
__device__ unsigned long long g_adj[BB * NN];
__device__ float g_ln[NROWS * HH];

// ---------------- math helpers ----------------
__device__ __forceinline__ float silu_f(float x) { return x * (1.f / (1.f + expf(-x))); }
__device__ __forceinline__ float selu_f(float x) {
    const float a = 1.6732632423543772f, s = 1.0507009873554805f;
    return x > 0.f ? s * x : s * a * expm1f(x);
}
__device__ __forceinline__ void split_bf16(float v, bf16& h, bf16& l) {
    h = __float2bfloat16_rn(v);
    l = __float2bfloat16_rn(v - __bfloat162float(h));
}
union Pack4 { bf16 b[4]; uint2 u; };
__device__ __forceinline__ void split_store4(const float* v, bf16* ph, bf16* pl) {
    Pack4 H, L;
#pragma unroll
    for (int j = 0; j < 4; j++) split_bf16(v[j], H.b[j], L.b[j]);
    *reinterpret_cast<uint2*>(ph) = H.u;
    *reinterpret_cast<uint2*>(pl) = L.u;
}
__device__ __forceinline__ void bsplines8(float x, float* out) {
    const float h = 0.4f;
    float b[11];
#pragma unroll
    for (int j = 0; j < 11; j++) {
        float gj = (float)(j - 3) * h - 1.0f;
        float gj1 = (float)(j - 2) * h - 1.0f;
        b[j] = (x >= gj && x < gj1) ? 1.f : 0.f;
    }
#pragma unroll
    for (int k = 1; k <= 3; k++) {
        float inv = 1.f / ((float)k * h);
#pragma unroll
        for (int j = 0; j < 11; j++) {
            if (j < 11 - k) {
                float gj = (float)(j - 3) * h - 1.0f;
                float gjk1 = (float)(j + k - 2) * h - 1.0f;
                b[j] = (x - gj) * inv * b[j] + (gjk1 - x) * inv * b[j + 1];
            }
        }
    }
#pragma unroll
    for (int j = 0; j < 8; j++) out[j] = b[j];
}

// ---------------- unified prep kernel (all independent prep work, 1 launch) ----------------
// blocks [0,8192):       bridge features (4 inputs/thread)
// [8192,9216):           bridge weight concat + split
// [9216,9472):           conv1 weights
// [9472,9728):           conv2 weights
// [9728,10240):          GAT weights (both layers)
// [10240,12288):         zero slot-3 plane of stream-K partials (2048 blocks = 524288 float4)
#define PREP_GRID 12288
__global__ void prep_all(const float* __restrict__ x,
                         const float* __restrict__ bw, const float* __restrict__ sw,
                         const float* __restrict__ sc,
                         const float* __restrict__ c1w, const float* __restrict__ c2w,
                         const float* __restrict__ gw) {
    int blk = blockIdx.x;
    int tid = threadIdx.x;
    if (blk < 8192) {
        // bridge features
        int idx = blk * 256 + tid;
        int r = idx >> 8, i4 = idx & 255;
        float4 xv = *reinterpret_cast<const float4*>(x + (size_t)r * DIN + i4 * 4);
        float vv[4] = {xv.x, xv.y, xv.z, xv.w};
        float f[9][4];
#pragma unroll
        for (int j = 0; j < 4; j++) {
            f[0][j] = silu_f(vv[j]);
            float bs[8];
            bsplines8(vv[j], bs);
#pragma unroll
            for (int c = 0; c < 8; c++) f[c + 1][j] = bs[c];
        }
        size_t base = (size_t)r * KBRIDGE + i4 * 4;
#pragma unroll
        for (int g = 0; g < 9; g++)
            split_store4(f[g], g_fh + base + (size_t)g * DIN, g_fl + base + (size_t)g * DIN);
    } else if (blk < 9216) {
        // bridge weight concat
        int idx = (blk - 8192) * 256 + tid;
        int i = idx % DIN, o = idx / DIN;
        size_t base = (size_t)o * KBRIDGE + i;
        bf16 h, l;
        split_bf16(bw[idx], h, l);
        g_wh[base] = h; g_wl[base] = l;
        float scale = sc[idx];
#pragma unroll
        for (int c = 0; c < 8; c++) {
            split_bf16(sw[(size_t)idx * 8 + c] * scale, h, l);
            size_t p = base + (size_t)(c + 1) * DIN;
            g_wh[p] = h; g_wl[p] = l;
        }
    } else if (blk < 9728) {
        // conv weights (reorder + split)
        int which = (blk - 9216) >> 8;    // 0 -> conv1, 1 -> conv2
        int idx = ((blk - 9216) & 255) * 256 + tid;
        const float* w = which ? c2w : c1w;
        bf16* wh = which ? g_wc2h : g_wc1h;
        bf16* wl = which ? g_wc2l : g_wc1l;
        int i = idx % HH, o = idx / HH;
#pragma unroll
        for (int j = 0; j < 3; j++) {
            bf16 h, l;
            split_bf16(w[((size_t)o * HH + i) * 3 + j], h, l);
            size_t p = (size_t)o * KCONV + j * HH + i;
            wh[p] = h; wl[p] = l;
        }
    } else if (blk < 10240) {
        // GAT weights, both layers (transpose + split)
        int idx = (blk - 9728) * 256 + tid;    // 0..131071
        int L = idx >> 16;
        int e = idx & 65535;
        int k = e % HH, n = e / HH;
        bf16 h, l;
        split_bf16(gw[(size_t)L * HH * HH + (size_t)k * HH + n], h, l);
        if (L == 0) { g_wt0h[e] = h; g_wt0l[e] = l; }
        else        { g_wt1h[e] = h; g_wt1l[e] = l; }
    } else {
        // zero slot-3 plane of stream-K partials (exactly MROWS*HH/4 float4s)
        int idx = (blk - 10240) * 256 + tid;
        reinterpret_cast<float4*>(g_part + (size_t)3 * MROWS * HH)[idx] =
            make_float4(0.f, 0.f, 0.f, 0.f);
    }
}

// ===== shared GEMM config: 512 thr, warp tile 32x64, 3-stage, 1 barrier/chunk =====
#define BKS 32
#define SROWS 80
#define AS_STG (128 * SROWS)
#define BS_STG (256 * SROWS)
#define STG_TOT (2 * AS_STG + 2 * BS_STG)
#define GEMM_SMEM (3 * STG_TOT)

// ---------------- generic split-K GEMM (convs + GAT) ----------------
template <int SHIFT>
__global__ __launch_bounds__(512, 1) void gemm_mma(
    const bf16* __restrict__ Ah, const bf16* __restrict__ Al,
    const bf16* __restrict__ Bh, const bf16* __restrict__ Bl,
    float* __restrict__ Cpart, int K, int kLen) {
    extern __shared__ char smem[];
    uint32_t s0 = smem_u32(smem);

    int tid = threadIdx.x, lane = tid & 31, wid = tid >> 5;
    int wm = wid & 3, wn = wid >> 2;
    int bm = blockIdx.x * 128;
    int kOff = blockIdx.y * kLen;
    float* Cf = Cpart + (size_t)blockIdx.y * gridDim.x * 128 * 256;
    const int nc = kLen / BKS;

    int aRow = wm * 32 + (lane & 15);
    int aCol = (lane >> 4) * 8;
    int bRow = wn * 64 + (lane & 7) + ((lane >> 4) << 3);
    int bCol = ((lane >> 3) & 1) * 8;

    float acc[2][8][4];
#pragma unroll
    for (int i = 0; i < 2; i++)
#pragma unroll
        for (int j = 0; j < 8; j++)
#pragma unroll
            for (int q = 0; q < 4; q++) acc[i][j][q] = 0.f;

    auto issue = [&](int st, int k0) {
        uint32_t sb = s0 + (uint32_t)(st * STG_TOT);
        {
            int r = tid >> 2, c = tid & 3;
            uint32_t dh = sb + (uint32_t)(r * SROWS + c * 16);
            uint32_t dl = dh + AS_STG;
            if (SHIFT) {
                int k = kOff + k0 + c * 8;
                int j = k >> 8, cc = k & 255;
                int grow = bm + r;
                int tj = (grow & 511) + j - 1;
                if (tj >= 0 && tj < 512) {
                    size_t go = (size_t)(grow + j - 1) * 256 + cc;
                    CP_ASYNC16(dh, Ah + go);
                    CP_ASYNC16(dl, Al + go);
                } else {
                    STS128Z(dh);
                    STS128Z(dl);
                }
            } else {
                size_t go = (size_t)(bm + r) * K + kOff + k0 + c * 8;
                CP_ASYNC16(dh, Ah + go);
                CP_ASYNC16(dl, Al + go);
            }
        }
#pragma unroll
        for (int i = 0; i < 2; i++) {
            int q = i * 512 + tid;
            int r = q >> 2, c = q & 3;
            uint32_t d = sb + (uint32_t)(2 * AS_STG + r * SROWS + c * 16);
            size_t go = (size_t)r * K + kOff + k0 + c * 8;
            CP_ASYNC16(d, Bh + go);
            CP_ASYNC16(d + BS_STG, Bl + go);
        }
    };

    issue(0, 0);
    CP_COMMIT();
    if (nc > 1) { issue(1, BKS); CP_COMMIT(); }

    int st = 0;
    for (int kc = 0; kc < nc; kc++) {
        if (kc + 1 < nc) { CP_WAIT(1); } else { CP_WAIT(0); }
        __syncthreads();
        if (kc + 2 < nc) {
            int nst = st + 2; if (nst >= 3) nst -= 3;
            issue(nst, (kc + 2) * BKS);
            CP_COMMIT();
        }
        uint32_t sb = s0 + (uint32_t)(st * STG_TOT);
        uint32_t sAh = sb, sAl = sb + AS_STG;
        uint32_t sBh = sb + 2 * AS_STG, sBl = sBh + BS_STG;
#pragma unroll
        for (int kk = 0; kk < 2; kk++) {
            uint32_t ah[2][4], al[2][4];
#pragma unroll
            for (int mt = 0; mt < 2; mt++) {
                uint32_t ao = (uint32_t)((aRow + mt * 16) * SROWS + (aCol + kk * 16) * 2);
                LDSM_X4(ah[mt][0], ah[mt][1], ah[mt][2], ah[mt][3], sAh + ao);
                LDSM_X4(al[mt][0], al[mt][1], al[mt][2], al[mt][3], sAl + ao);
            }
#pragma unroll
            for (int nt2 = 0; nt2 < 4; nt2++) {
                uint32_t bo = (uint32_t)((bRow + nt2 * 16) * SROWS + (bCol + kk * 16) * 2);
                uint32_t bh[4], bl[4];
                LDSM_X4(bh[0], bh[1], bh[2], bh[3], sBh + bo);
                LDSM_X4(bl[0], bl[1], bl[2], bl[3], sBl + bo);
                int n0 = nt2 * 2, n1 = n0 + 1;
                MMA_BF16(acc[0][n0], ah[0][0], ah[0][1], ah[0][2], ah[0][3], bh[0], bh[1]);
                MMA_BF16(acc[0][n1], ah[0][0], ah[0][1], ah[0][2], ah[0][3], bh[2], bh[3]);
                MMA_BF16(acc[1][n0], ah[1][0], ah[1][1], ah[1][2], ah[1][3], bh[0], bh[1]);
                MMA_BF16(acc[1][n1], ah[1][0], ah[1][1], ah[1][2], ah[1][3], bh[2], bh[3]);
                MMA_BF16(acc[0][n0], ah[0][0], ah[0][1], ah[0][2], ah[0][3], bl[0], bl[1]);
                MMA_BF16(acc[0][n1], ah[0][0], ah[0][1], ah[0][2], ah[0][3], bl[2], bl[3]);
                MMA_BF16(acc[1][n0], ah[1][0], ah[1][1], ah[1][2], ah[1][3], bl[0], bl[1]);
                MMA_BF16(acc[1][n1], ah[1][0], ah[1][1], ah[1][2], ah[1][3], bl[2], bl[3]);
                MMA_BF16(acc[0][n0], al[0][0], al[0][1], al[0][2], al[0][3], bh[0], bh[1]);
                MMA_BF16(acc[0][n1], al[0][0], al[0][1], al[0][2], al[0][3], bh[2], bh[3]);
                MMA_BF16(acc[1][n0], al[1][0], al[1][1], al[1][2], al[1][3], bh[0], bh[1]);
                MMA_BF16(acc[1][n1], al[1][0], al[1][1], al[1][2], al[1][3], bh[2], bh[3]);
            }
        }
        if (++st == 3) st = 0;
    }

    int rbase = bm + wm * 32 + (lane >> 2);
    int cbase = wn * 64 + (lane & 3) * 2;
#pragma unroll
    for (int mt = 0; mt < 2; mt++) {
#pragma unroll
        for (int nt = 0; nt < 8; nt++) {
            int r = rbase + mt * 16;
            int c = cbase + nt * 8;
            *reinterpret_cast<float2*>(Cf + (size_t)r * 256 + c) =
                make_float2(acc[mt][nt][0], acc[mt][nt][1]);
            *reinterpret_cast<float2*>(Cf + (size_t)(r + 8) * 256 + c) =
                make_float2(acc[mt][nt][2], acc[mt][nt][3]);
        }
    }
}

// ---------------- stream-K bridge GEMM ----------------
// 64 m-tiles x 288 chunks = 18432 units over 148 CTAs (80x125 + 68x124).
#define SK_G 148
#define SK_NC 288
#define SK_MT 64
__device__ __forceinline__ int sk_start(int c) {
    return c < 80 ? 125 * c : 10000 + 124 * (c - 80);
}
__device__ __forceinline__ int sk_cta_of(int u) {
    return u < 10000 ? u / 125 : 80 + (u - 10000) / 124;
}

__global__ __launch_bounds__(512, 1) void gemm_bridge_sk(
    const bf16* __restrict__ Ah, const bf16* __restrict__ Al,
    const bf16* __restrict__ Bh, const bf16* __restrict__ Bl) {
    extern __shared__ char smem[];
    uint32_t s0 = smem_u32(smem);

    int tid = threadIdx.x, lane = tid & 31, wid = tid >> 5;
    int wm = wid & 3, wn = wid >> 2;
    int ctaid = blockIdx.x;
    int s = sk_start(ctaid);
    int e = sk_start(ctaid + 1);

    int aRow = wm * 32 + (lane & 15);
    int aCol = (lane >> 4) * 8;
    int bRow = wn * 64 + (lane & 7) + ((lane >> 4) << 3);
    int bCol = ((lane >> 3) & 1) * 8;

    int u = s;
    while (u < e) {
        int m = u / SK_NC;
        int cend = min(e, (m + 1) * SK_NC);
        int nc = cend - u;
        int kOff = (u - m * SK_NC) * BKS;
        int bm = m * 128;
        int slot = ctaid - sk_cta_of(m * SK_NC);
        float* Cf = g_part + ((size_t)slot * SK_MT + m) * 128 * 256;

        float acc[2][8][4];
#pragma unroll
        for (int i = 0; i < 2; i++)
#pragma unroll
            for (int j = 0; j < 8; j++)
#pragma unroll
                for (int q = 0; q < 4; q++) acc[i][j][q] = 0.f;

        auto issue = [&](int st, int k0) {
            uint32_t sb = s0 + (uint32_t)(st * STG_TOT);
            {
                int r = tid >> 2, c = tid & 3;
                uint32_t dh = sb + (uint32_t)(r * SROWS + c * 16);
                size_t go = (size_t)(bm + r) * KBRIDGE + kOff + k0 + c * 8;
                CP_ASYNC16(dh, Ah + go);
                CP_ASYNC16(dh + AS_STG, Al + go);
            }
#pragma unroll
            for (int i = 0; i < 2; i++) {
                int q = i * 512 + tid;
                int r = q >> 2, c = q & 3;
                uint32_t d = sb + (uint32_t)(2 * AS_STG + r * SROWS + c * 16);
                size_t go = (size_t)r * KBRIDGE + kOff + k0 + c * 8;
                CP_ASYNC16(d, Bh + go);
                CP_ASYNC16(d + BS_STG, Bl + go);
            }
        };

        issue(0, 0);
        CP_COMMIT();
        if (nc > 1) { issue(1, BKS); CP_COMMIT(); }

        int st = 0;
        for (int kc = 0; kc < nc; kc++) {
            if (kc + 1 < nc) { CP_WAIT(1); } else { CP_WAIT(0); }
            __syncthreads();
            if (kc + 2 < nc) {
                int nst = st + 2; if (nst >= 3) nst -= 3;
                issue(nst, (kc + 2) * BKS);
                CP_COMMIT();
            }
            uint32_t sb = s0 + (uint32_t)(st * STG_TOT);
            uint32_t sAh = sb, sAl = sb + AS_STG;
            uint32_t sBh = sb + 2 * AS_STG, sBl = sBh + BS_STG;
#pragma unroll
            for (int kk = 0; kk < 2; kk++) {
                uint32_t ah[2][4], al[2][4];
#pragma unroll
                for (int mt = 0; mt < 2; mt++) {
                    uint32_t ao = (uint32_t)((aRow + mt * 16) * SROWS + (aCol + kk * 16) * 2);
                    LDSM_X4(ah[mt][0], ah[mt][1], ah[mt][2], ah[mt][3], sAh + ao);
                    LDSM_X4(al[mt][0], al[mt][1], al[mt][2], al[mt][3], sAl + ao);
                }
#pragma unroll
                for (int nt2 = 0; nt2 < 4; nt2++) {
                    uint32_t bo = (uint32_t)((bRow + nt2 * 16) * SROWS + (bCol + kk * 16) * 2);
                    uint32_t bh[4], bl[4];
                    LDSM_X4(bh[0], bh[1], bh[2], bh[3], sBh + bo);
                    LDSM_X4(bl[0], bl[1], bl[2], bl[3], sBl + bo);
                    int n0 = nt2 * 2, n1 = n0 + 1;
                    MMA_BF16(acc[0][n0], ah[0][0], ah[0][1], ah[0][2], ah[0][3], bh[0], bh[1]);
                    MMA_BF16(acc[0][n1], ah[0][0], ah[0][1], ah[0][2], ah[0][3], bh[2], bh[3]);
                    MMA_BF16(acc[1][n0], ah[1][0], ah[1][1], ah[1][2], ah[1][3], bh[0], bh[1]);
                    MMA_BF16(acc[1][n1], ah[1][0], ah[1][1], ah[1][2], ah[1][3], bh[2], bh[3]);
                    MMA_BF16(acc[0][n0], ah[0][0], ah[0][1], ah[0][2], ah[0][3], bl[0], bl[1]);
                    MMA_BF16(acc[0][n1], ah[0][0], ah[0][1], ah[0][2], ah[0][3], bl[2], bl[3]);
                    MMA_BF16(acc[1][n0], ah[1][0], ah[1][1], ah[1][2], ah[1][3], bl[0], bl[1]);
                    MMA_BF16(acc[1][n1], ah[1][0], ah[1][1], ah[1][2], ah[1][3], bl[2], bl[3]);
                    MMA_BF16(acc[0][n0], al[0][0], al[0][1], al[0][2], al[0][3], bh[0], bh[1]);
                    MMA_BF16(acc[0][n1], al[0][0], al[0][1], al[0][2], al[0][3], bh[2], bh[3]);
                    MMA_BF16(acc[1][n0], al[1][0], al[1][1], al[1][2], al[1][3], bh[0], bh[1]);
                    MMA_BF16(acc[1][n1], al[1][0], al[1][1], al[1][2], al[1][3], bh[2], bh[3]);
                }
            }
            if (++st == 3) st = 0;
        }
        __syncthreads();

        // epilogue: LOCAL rows (Cf already includes the tile offset)
        int rbase = wm * 32 + (lane >> 2);
        int cbase = wn * 64 + (lane & 3) * 2;
#pragma unroll
        for (int mt = 0; mt < 2; mt++) {
#pragma unroll
            for (int nt = 0; nt < 8; nt++) {
                int r = rbase + mt * 16;
                int c = cbase + nt * 8;
                *reinterpret_cast<float2*>(Cf + (size_t)r * 256 + c) =
                    make_float2(acc[mt][nt][0], acc[mt][nt][1]);
                *reinterpret_cast<float2*>(Cf + (size_t)(r + 8) * 256 + c) =
                    make_float2(acc[mt][nt][2], acc[mt][nt][3]);
            }
        }
        u = cend;
    }
}

// ---------------- split-K combine + epilogue ----------------
template <int EPI, int SK>
__global__ void combine_k(const float* __restrict__ part, size_t slice,
                          float* __restrict__ Cf, bf16* __restrict__ Ch, bf16* __restrict__ Cl,
                          const float* __restrict__ bias, int total4) {
    int idx = blockIdx.x * blockDim.x + threadIdx.x;
    if (idx >= total4) return;
    const float4* p4 = reinterpret_cast<const float4*>(part);
    size_t s4 = slice >> 2;
    float4 a = p4[idx];
#pragma unroll
    for (int s = 1; s < SK; s++) {
        float4 b = p4[idx + (size_t)s * s4];
        a.x += b.x; a.y += b.y; a.z += b.z; a.w += b.w;
    }
    float v[4] = {a.x, a.y, a.z, a.w};
    if (EPI == 1 || EPI == 3) {
        int c = (idx * 4) & 255;
        float4 b4 = *reinterpret_cast<const float4*>(bias + c);
        v[0] = selu_f(v[0] + b4.x); v[1] = selu_f(v[1] + b4.y);
        v[2] = selu_f(v[2] + b4.z); v[3] = selu_f(v[3] + b4.w);
    }
    if (EPI >= 2) {
        split_store4(v, Ch + (size_t)idx * 4, Cl + (size_t)idx * 4);
    } else {
        *reinterpret_cast<float4*>(Cf + (size_t)idx * 4) = make_float4(v[0], v[1], v[2], v[3]);
    }
}

// ---------------- fused GAT split-K combine + source/dest reductions ----------------
__global__ void gat_combine_sd(const float* __restrict__ part,
                               const float* __restrict__ asrc, const float* __restrict__ adst) {
    int row = blockIdx.x;
    int t = threadIdx.x;
    size_t off = (size_t)row * HH + t;
    float v = 0.f;
#pragma unroll
    for (int s = 0; s < 8; s++) v += part[(size_t)s * NROWS * HH + off];
    g_hw[off] = v;
    __shared__ float r1[HH], r2[HH];
    r1[t] = v * asrc[t];
    r2[t] = v * adst[t];
    __syncthreads();
    for (int st = 128; st > 0; st >>= 1) {
        if (t < st) { r1[t] += r1[t + st]; r2[t] += r2[t + st]; }
        __syncthreads();
    }
    if (t == 0) { g_s[row] = r1[0]; g_d[row] = r2[0]; }
}

// ---------------- pool + pos (+ adj zero, + split) ----------------
__global__ void pool_pos(const float* __restrict__ y2, const float* __restrict__ pos) {
    int idx = blockIdx.x * blockDim.x + threadIdx.x;
    if (idx < BB * NN) g_adj[idx] = 0ull;
    if (idx >= BB * NN * HH) return;
    int c = idx % HH;
    int n = (idx / HH) % NN;
    int b = idx / (HH * NN);
    float s = 0.f;
#pragma unroll
    for (int t = 0; t < 8; t++) s += y2[((size_t)b * TT + n * 8 + t) * HH + c];
    float v = s * 0.125f + pos[(size_t)n * HH + c];
    size_t o = ((size_t)b * NN + n) * HH + c;
    g_hn[o] = v;
    bf16 h, l;
    split_bf16(v, h, l);
    g_hnh[o] = h; g_hnl[o] = l;
}

// ---------------- adjacency ----------------
__global__ void adj_topk() {
    int b = blockIdx.x / NN, n = blockIdx.x % NN;
    __shared__ float sc[NN];
    int m = threadIdx.x;
    const float* hb = g_hn + (size_t)b * NN * HH;
    float s = 0.f;
    for (int k = 0; k < HH; k++) s = fmaf(hb[(size_t)n * HH + k], hb[(size_t)m * HH + k], s);
    sc[m] = s;
    __syncthreads();
    if (m == 0) {
        unsigned long long mask = 1ull << n;
        int sel[TOPK];
#pragma unroll 1
        for (int it = 0; it < TOPK; it++) {
            float best = -INFINITY; int bi = 0;
            for (int j = 0; j < NN; j++)
                if (sc[j] > best) { best = sc[j]; bi = j; }
            sel[it] = bi;
            sc[bi] = -INFINITY;
            mask |= 1ull << bi;
        }
        atomicOr(&g_adj[b * NN + n], mask);
        for (int it = 0; it < TOPK; it++)
            atomicOr(&g_adj[b * NN + sel[it]], 1ull << n);
    }
}

// ---------------- GAT attention (LAST=1 fuses layernorm) ----------------
template <int LAST>
__global__ void gat_attn(const float* __restrict__ lng, const float* __restrict__ lnb) {
    int b = blockIdx.x / NN, n = blockIdx.x % NN;
    __shared__ float attn[NN];
    __shared__ float inv_s;
    __shared__ float red[HH];
    __shared__ float mu_s, is_s;
    int t = threadIdx.x;
    unsigned long long mask = g_adj[b * NN + n];
    if (t < NN) {
        float e;
        if ((mask >> t) & 1ull) {
            float z = g_s[b * NN + n] + g_d[b * NN + t];
            e = z >= 0.f ? z : 0.2f * z;
        } else {
            e = -1e9f;
        }
        attn[t] = e;
    }
    __syncthreads();
    if (t == 0) {
        float mx = -INFINITY;
        for (int j = 0; j < NN; j++) mx = fmaxf(mx, attn[j]);
        float sum = 0.f;
        for (int j = 0; j < NN; j++) { float ex = expf(attn[j] - mx); attn[j] = ex; sum += ex; }
        inv_s = 1.f / sum;
    }
    __syncthreads();
    float inv = inv_s;
    float acc = 0.f;
    for (int m = 0; m < NN; m++)
        acc = fmaf(attn[m] * inv, g_hw[((size_t)b * NN + m) * HH + t], acc);
    float o = acc > 0.f ? acc : expm1f(acc);
    size_t oo = ((size_t)b * NN + n) * HH + t;
    float nh = g_hn[oo] + o;
    if (LAST == 0) {
        g_hn[oo] = nh;
        bf16 h, l;
        split_bf16(nh, h, l);
        g_hnh[oo] = h; g_hnl[oo] = l;
    } else {
        red[t] = nh;
        __syncthreads();
        for (int st = 128; st > 0; st >>= 1) { if (t < st) red[t] += red[t + st]; __syncthreads(); }
        if (t == 0) mu_s = red[0] * (1.f / HH);
        __syncthreads();
        float mu = mu_s;
        float dv = nh - mu;
        red[t] = dv * dv;
        __syncthreads();
        for (int st = 128; st > 0; st >>= 1) { if (t < st) red[t] += red[t + st]; __syncthreads(); }
        if (t == 0) is_s = rsqrtf(red[0] * (1.f / HH) + 1e-5f);
        __syncthreads();
        g_ln[oo] = dv * is_s * lng[t] + lnb[t];
    }
}

// ---------------- fused emb pooling + classifier KAN ----------------
__global__ void emb_cls(const float* __restrict__ cbw, const float* __restrict__ csw,
                        const float* __restrict__ csc, float* __restrict__ out) {
    int b = blockIdx.x;
    int t = threadIdx.x;
    __shared__ float emb[2 * HH];
    __shared__ float r0[256], r1[256];
    {
        float sm = 0.f, mx = -INFINITY;
        const float* lb = g_ln + (size_t)b * NN * HH + t;
        for (int n = 0; n < NN; n++) {
            float v = lb[(size_t)n * HH];
            sm += v;
            mx = fmaxf(mx, v);
        }
        float mean = sm * (1.f / NN);
        emb[t] = mean;
        emb[HH + t] = mx;
        out[BB * NCLS + (size_t)b * (2 * HH) + t] = mean;
        out[BB * NCLS + (size_t)b * (2 * HH) + HH + t] = mx;
    }
    __syncthreads();
    float a0 = 0.f, a1 = 0.f;
    for (int i = t; i < 2 * HH; i += 256) {
        float x = emb[i];
        float sil = silu_f(x);
        float bs[8];
        bsplines8(x, bs);
        float p0 = sil * cbw[i];
        float p1 = sil * cbw[2 * HH + i];
        float s0 = csc[i], s1 = csc[2 * HH + i];
#pragma unroll
        for (int c = 0; c < 8; c++) {
            p0 = fmaf(bs[c] * csw[(size_t)i * 8 + c], s0, p0);
            p1 = fmaf(bs[c] * csw[(size_t)(2 * HH + i) * 8 + c], s1, p1);
        }
        a0 += p0;
        a1 += p1;
    }
    r0[t] = a0; r1[t] = a1;
    __syncthreads();
    for (int st = 128; st > 0; st >>= 1) {
        if (t < st) { r0[t] += r0[t + st]; r1[t] += r1[t + st]; }
        __syncthreads();
    }
    if (t == 0) { out[b * NCLS + 0] = r0[0]; out[b * NCLS + 1] = r1[0]; }
}

// ---------------- host launch ----------------
extern "C" void kernel_launch(void* const* d_in, const int* in_sizes, int n_in,
                              void* d_out, int out_size) {
    const float* x    = (const float*)d_in[0];
    const float* bbw  = (const float*)d_in[1];
    const float* bsw  = (const float*)d_in[2];
    const float* bsc  = (const float*)d_in[3];
    const float* c1w  = (const float*)d_in[4];
    const float* c1b  = (const float*)d_in[5];
    const float* c2w  = (const float*)d_in[6];
    const float* c2b  = (const float*)d_in[7];
    const float* pos  = (const float*)d_in[8];
    const float* gatW = (const float*)d_in[9];
    const float* asrc = (const float*)d_in[10];
    const float* adst = (const float*)d_in[11];
    const float* lng  = (const float*)d_in[12];
    const float* lnb  = (const float*)d_in[13];
    const float* cbw  = (const float*)d_in[14];
    const float* csw  = (const float*)d_in[15];
    const float* csc  = (const float*)d_in[16];
    float* out = (float*)d_out;

    bf16 *pfh, *pfl, *pwh, *pwl, *ph1h, *ph1l, *pwc1h, *pwc1l, *pwc2h, *pwc2l;
    bf16 *py1h, *py1l, *phnh, *phnl, *pwt0h, *pwt0l, *pwt1h, *pwt1l;
    float *py2, *ppart;
    cudaGetSymbolAddress((void**)&pfh, g_fh);
    cudaGetSymbolAddress((void**)&pfl, g_fl);
    cudaGetSymbolAddress((void**)&pwh, g_wh);
    cudaGetSymbolAddress((void**)&pwl, g_wl);
    cudaGetSymbolAddress((void**)&ph1h, g_h1h);
    cudaGetSymbolAddress((void**)&ph1l, g_h1l);
    cudaGetSymbolAddress((void**)&pwc1h, g_wc1h);
    cudaGetSymbolAddress((void**)&pwc1l, g_wc1l);
    cudaGetSymbolAddress((void**)&pwc2h, g_wc2h);
    cudaGetSymbolAddress((void**)&pwc2l, g_wc2l);
    cudaGetSymbolAddress((void**)&py1h, g_y1h);
    cudaGetSymbolAddress((void**)&py1l, g_y1l);
    cudaGetSymbolAddress((void**)&phnh, g_hnh);
    cudaGetSymbolAddress((void**)&phnl, g_hnl);
    cudaGetSymbolAddress((void**)&pwt0h, g_wt0h);
    cudaGetSymbolAddress((void**)&pwt0l, g_wt0l);
    cudaGetSymbolAddress((void**)&pwt1h, g_wt1h);
    cudaGetSymbolAddress((void**)&pwt1l, g_wt1l);
    cudaGetSymbolAddress((void**)&py2, g_y2);
    cudaGetSymbolAddress((void**)&ppart, g_part);

    cudaFuncSetAttribute(gemm_bridge_sk, cudaFuncAttributeMaxDynamicSharedMemorySize, GEMM_SMEM);
    cudaFuncSetAttribute(gemm_mma<0>, cudaFuncAttributeMaxDynamicSharedMemorySize, GEMM_SMEM);
    cudaFuncSetAttribute(gemm_mma<1>, cudaFuncAttributeMaxDynamicSharedMemorySize, GEMM_SMEM);

    const int TPB = 256;
    const size_t SLICE_BIG = (size_t)MROWS * HH;
    const int T4_BIG = MROWS * HH / 4;

    // unified prep (1 launch: features + all weight splits + slot-3 zero)
    prep_all<<<PREP_GRID, TPB>>>(x, bbw, bsw, bsc, c1w, c2w, gatW);

    // bridge GEMM: stream-K over 148 CTAs + 4-slot combine -> split bf16
    gemm_bridge_sk<<<SK_G, 512, GEMM_SMEM>>>(pfh, pfl, pwh, pwl);
    combine_k<2, 4><<<(T4_BIG + TPB - 1) / TPB, TPB>>>(ppart, SLICE_BIG,
                                                       nullptr, ph1h, ph1l, nullptr, T4_BIG);

    // conv1: split-K 2 + combine -> selu+bias split bf16
    gemm_mma<1><<<dim3(MROWS / 128, 2), 512, GEMM_SMEM>>>(ph1h, ph1l, pwc1h, pwc1l,
                                                          ppart, KCONV, KCONV / 2);
    combine_k<3, 2><<<(T4_BIG + TPB - 1) / TPB, TPB>>>(ppart, SLICE_BIG,
                                                       nullptr, py1h, py1l, c1b, T4_BIG);

    // conv2: split-K 2 + combine -> selu+bias fp32
    gemm_mma<1><<<dim3(MROWS / 128, 2), 512, GEMM_SMEM>>>(py1h, py1l, pwc2h, pwc2l,
                                                          ppart, KCONV, KCONV / 2);
    combine_k<1, 2><<<(T4_BIG + TPB - 1) / TPB, TPB>>>(ppart, SLICE_BIG,
                                                       py2, nullptr, nullptr, c2b, T4_BIG);

    // pool + pos (+ adj zero + split)
    pool_pos<<<(BB * NN * HH + TPB - 1) / TPB, TPB>>>(py2, pos);

    // adjacency
    adj_topk<<<BB * NN, NN>>>();

    // GAT layer 0
    gemm_mma<0><<<dim3(NROWS / 128, 8), 512, GEMM_SMEM>>>(phnh, phnl, pwt0h, pwt0l,
                                                          ppart, HH, HH / 8);
    gat_combine_sd<<<NROWS, HH>>>(ppart, asrc, adst);
    gat_attn<0><<<NROWS, HH>>>(nullptr, nullptr);

    // GAT layer 1 (fused layernorm)
    gemm_mma<0><<<dim3(NROWS / 128, 8), 512, GEMM_SMEM>>>(phnh, phnl, pwt1h, pwt1l,
                                                          ppart, HH, HH / 8);
    gat_combine_sd<<<NROWS, HH>>>(ppart, asrc + HH, adst + HH);
    gat_attn<1><<<NROWS, HH>>>(lng, lnb);

    // fused emb pooling + classifier
    emb_cls<<<BB, 256>>>(cbw, csw, csc, out);
}